// round 6
// baseline (speedup 1.0000x reference)
#include <cuda_runtime.h>
#include <cuda_fp16.h>
#include <math.h>
#include <stdint.h>

#define Bb   2
#define Hh   192
#define Wd   192
#define NH_  8
#define HD_  48
#define NW_  24
#define NTOK (Bb*Hh*Wd)   // 73728

// ---------------- scratch (device globals; no runtime alloc) ----------------
__device__ __half g_Av[(size_t)NTOK * 768];    // values split [hi|lo]
__device__ __half g_Ac[(size_t)NTOK * 256];    // coords split
__device__ __half g_Yb[(size_t)NTOK * 768];    // attn out split
__device__ __half g_Bv[1152 * 768];            // W' permuted vqk|vv [N, hi|hi]
__device__ __half g_Bc[768 * 256];             // W' permuted cqk
__device__ __half g_Bo[384 * 768];             // W' ov
__device__ float g_biasv[1152];                // permuted bias (values)
__device__ float g_biasc[768];                 // permuted bias (coords)
__device__ float g_gvp[1152];                  // permuted gamma (values; e<32 only used)
__device__ float g_gcp[768];                   // permuted gamma (coords)
__device__ float g_pv[(size_t)NTOK * 1152];    // proj out: [Q|K|V] head-major, +bias
__device__ float g_pc[(size_t)NTOK * 768];     // proj out: [Qc|Kc] head-major, +bias
__device__ float g_ssv[NTOK];                  // sum sq of vqk-origin channels
__device__ float g_ssc[NTOK];                  // sum sq of cqk channels

// ------------------------------ PTX helpers ---------------------------------
__device__ __forceinline__ uint32_t s2u(const void* p) {
    uint32_t a;
    asm("{ .reg .u64 t; cvta.to.shared.u64 t, %1; cvt.u32.u64 %0, t; }" : "=r"(a) : "l"(p));
    return a;
}
__device__ __forceinline__ void cp16(uint32_t dst, const void* src) {
    asm volatile("cp.async.cg.shared.global [%0], [%1], 16;" :: "r"(dst), "l"(src));
}
#define CP_COMMIT() asm volatile("cp.async.commit_group;" ::: "memory")
#define CP_WAIT1()  asm volatile("cp.async.wait_group 1;" ::: "memory")
#define CP_WAIT0()  asm volatile("cp.async.wait_group 0;" ::: "memory")

#define LDSM4(R0,R1,R2,R3,ADDR) \
    asm volatile("ldmatrix.sync.aligned.m8n8.x4.shared.b16 {%0,%1,%2,%3}, [%4];" \
                 : "=r"(R0), "=r"(R1), "=r"(R2), "=r"(R3) : "r"(ADDR))

#define MMA16816(D,A0,A1,A2,A3,B0,B1) \
    asm volatile("mma.sync.aligned.m16n8k16.row.col.f32.f16.f16.f32 " \
                 "{%0,%1,%2,%3},{%4,%5,%6,%7},{%8,%9},{%0,%1,%2,%3};" \
                 : "+f"(D[0]), "+f"(D[1]), "+f"(D[2]), "+f"(D[3]) \
                 : "r"(A0), "r"(A1), "r"(A2), "r"(A3), "r"(B0), "r"(B1))

// ------------------------ fused pack kernel (1 launch) -----------------------
#define T0 ((size_t)NTOK * 384)
#define T1 (T0 + (size_t)NTOK * 128)
#define T2 (T1 + 1152 * 384)
#define T3 (T2 + 768 * 128)
#define T4 (T3 + 384 * 384)
__global__ void pack_all(const float* __restrict__ values, const float* __restrict__ coords,
                         const float* __restrict__ Wqk, const float* __restrict__ Wvv,
                         const float* __restrict__ Wcqk, const float* __restrict__ Wov)
{
    size_t i = (size_t)blockIdx.x * 256 + threadIdx.x;
    if (i < T0) {                       // A_v split: exact activation
        size_t t = i / 384; int k = (int)(i - t * 384);
        float x = values[i];
        __half hi = __float2half_rn(x);
        __half lo = __float2half_rn(x - __half2float(hi));
        __half* row = g_Av + t * 768;
        row[k] = hi; row[384 + k] = lo;
    } else if (i < T1) {                // A_c split
        size_t j = i - T0;
        size_t t = j / 128; int k = (int)(j - t * 128);
        float x = coords[j];
        __half hi = __float2half_rn(x);
        __half lo = __float2half_rn(x - __half2float(hi));
        __half* row = g_Ac + t * 256;
        row[k] = hi; row[128 + k] = lo;
    } else if (i < T2) {                // B_v: permuted de-interleave [Q|K|V] head-major
        int j = (int)(i - T1);
        int n = j / 384, k = j - (j / 384) * 384;
        const int block = n / 384 == 0 ? 0 : 0;   // placeholder (n<1152)
        const int blk = n / 384;
        const int hm = (n % 384) / 48, e = n % 48;
        const int c = 3 * (e * 8 + hm) + blk;
        float w = (c < 768) ? Wqk[(size_t)k * 768 + c] : Wvv[(size_t)k * 384 + (c - 768)];
        __half hi = __float2half_rn(w);
        __half* row = g_Bv + (size_t)n * 768;
        row[k] = hi; row[384 + k] = hi;
        (void)block;
    } else if (i < T3) {                // B_c: permuted [Qc|Kc] head-major
        int j = (int)(i - T2);
        int n = j / 128, k = j - (j / 128) * 128;
        const int blk = n / 384;
        const int hm = (n % 384) / 48, e = n % 48;
        const int c = 2 * (e * 8 + hm) + blk;
        float w = Wcqk[(size_t)k * 768 + c];
        __half hi = __float2half_rn(w);
        __half* row = g_Bc + (size_t)n * 256;
        row[k] = hi; row[128 + k] = hi;
    } else if (i < T4) {                // B_o (unchanged layout)
        int j = (int)(i - T3);
        int n = j / 384, k = j - (j / 384) * 384;
        float w = Wov[(size_t)k * 384 + n];
        __half hi = __float2half_rn(w);
        __half* row = g_Bo + (size_t)n * 768;
        row[k] = hi; row[384 + k] = hi;
    }
}
// permuted bias + gamma tables, and ss zero-init
__global__ void metaperm(const float* __restrict__ bqk, const float* __restrict__ bvv,
                         const float* __restrict__ gvqk,
                         const float* __restrict__ bcqk, const float* __restrict__ gcqk)
{
    int i = blockIdx.x * 256 + threadIdx.x;
    if (i < 1152) {
        const int blk = i / 384, hm = (i % 384) / 48, e = i % 48;
        const int c = 3 * (e * 8 + hm) + blk;
        g_biasv[i] = (c < 768) ? bqk[c] : bvv[c - 768];
        g_gvp[i]   = (c < 768) ? gvqk[c] : 1.0f;
    } else if (i < 1920) {
        const int n = i - 1152;
        const int blk = n / 384, hm = (n % 384) / 48, e = n % 48;
        const int c = 2 * (e * 8 + hm) + blk;
        g_biasc[n] = bcqk[c];
        g_gcp[n]   = gcqk[c];
    }
}
__global__ void zero_ss() {
    int i = blockIdx.x * 256 + threadIdx.x;
    if (i < NTOK) { g_ssv[i] = 0.f; g_ssc[i] = 0.f; }
}

// --------- HMMA GEMM: C = A'[M,K'] @ B'[N,K']^T + bias; optional ss ---------
// smode: 0 none, 1 mask (col%48)<32 -> ss, 2 all cols -> ss
__global__ __launch_bounds__(256, 2) void gemm_mma(
    const __half* __restrict__ A, const __half* __restrict__ B,
    const float* __restrict__ bias, float* __restrict__ C, int Kp, int ldc,
    float* __restrict__ ss, int smode)
{
    extern __shared__ __align__(1024) char smem[];
    const uint32_t sb = s2u(smem);
    const int tid = threadIdx.x, lane = tid & 31, wid = tid >> 5;
    const int mB = blockIdx.y * 128, n0 = blockIdx.x * 128;
    const int wm = (wid & 3) << 5;
    const int wn = (wid >> 2) << 6;

    const int lrow = tid >> 3, lu = tid & 7;
    const size_t ldk = (size_t)Kp * 2;
    const char* Asrc = (const char*)A + (size_t)(mB + lrow) * ldk + lu * 16;
    const char* Bsrc = (const char*)B + (size_t)(n0 + lrow) * ldk + lu * 16;
    uint32_t dsto[4];
#pragma unroll
    for (int r = 0; r < 4; r++) {
        const int row = lrow + r * 32;
        dsto[r] = row * 128 + ((lu ^ (row & 7)) << 4);
    }

    const int q = lane >> 3, tr = lane & 7;
    const int qA = q >> 1, qB = q & 1;
    uint32_t rowoffA[2], xrA[2];
#pragma unroll
    for (int fm = 0; fm < 2; fm++) {
        const int row = wm + fm * 16 + tr + ((q & 1) << 3);
        rowoffA[fm] = row * 128; xrA[fm] = row & 7;
    }
    uint32_t rowoffB[4], xrB[4];
#pragma unroll
    for (int fn = 0; fn < 4; fn++) {
        const int row = wn + fn * 16 + tr + ((q >> 1) << 3);
        rowoffB[fn] = row * 128; xrB[fn] = row & 7;
    }

    float acc[2][8][4] = {};

    const int NC = Kp >> 6;
#pragma unroll
    for (int r = 0; r < 4; r++) {
        cp16(sb + dsto[r],          Asrc + (size_t)r * 32 * ldk);
        cp16(sb + 32768u + dsto[r], Bsrc + (size_t)r * 32 * ldk);
    }
    CP_COMMIT();

    for (int c = 0; c < NC; c++) {
        const int buf = c & 1;
        if (c + 1 < NC) {
            const uint32_t ab = sb + (buf ^ 1) * 16384u;
            const uint32_t bb = sb + 32768u + (buf ^ 1) * 16384u;
            const char* An = Asrc + (size_t)(c + 1) * 128;
            const char* Bn = Bsrc + (size_t)(c + 1) * 128;
#pragma unroll
            for (int r = 0; r < 4; r++) {
                cp16(ab + dsto[r], An + (size_t)r * 32 * ldk);
                cp16(bb + dsto[r], Bn + (size_t)r * 32 * ldk);
            }
            CP_COMMIT();
            CP_WAIT1();
        } else {
            CP_WAIT0();
        }
        __syncthreads();

        const uint32_t Ab = sb + buf * 16384u;
        const uint32_t Bs = sb + 32768u + buf * 16384u;
#pragma unroll
        for (int ks = 0; ks < 4; ks++) {
            uint32_t a[2][4], bf[4][4];
#pragma unroll
            for (int fm = 0; fm < 2; fm++) {
                const uint32_t ad = Ab + rowoffA[fm] + ((((uint32_t)(ks * 2 + qA)) ^ xrA[fm]) << 4);
                LDSM4(a[fm][0], a[fm][1], a[fm][2], a[fm][3], ad);
            }
#pragma unroll
            for (int fn = 0; fn < 4; fn++) {
                const uint32_t bd = Bs + rowoffB[fn] + ((((uint32_t)(ks * 2 + qB)) ^ xrB[fn]) << 4);
                LDSM4(bf[fn][0], bf[fn][1], bf[fn][2], bf[fn][3], bd);
            }
#pragma unroll
            for (int fm = 0; fm < 2; fm++)
#pragma unroll
                for (int fn = 0; fn < 4; fn++) {
                    MMA16816(acc[fm][2 * fn],     a[fm][0], a[fm][1], a[fm][2], a[fm][3],
                             bf[fn][0], bf[fn][1]);
                    MMA16816(acc[fm][2 * fn + 1], a[fm][0], a[fm][1], a[fm][2], a[fm][3],
                             bf[fn][2], bf[fn][3]);
                }
        }
        __syncthreads();
    }

    const int er = lane >> 2, ec = (lane & 3) << 1;
    float ssa[2][2] = {{0.f, 0.f}, {0.f, 0.f}};
#pragma unroll
    for (int fm = 0; fm < 2; fm++) {
#pragma unroll
        for (int fn = 0; fn < 8; fn++) {
            const int gm = mB + wm + fm * 16 + er;
            const int gn = n0 + wn + fn * 8 + ec;
            const float2 bv = *(const float2*)(bias + gn);
            float2 o0, o1;
            o0.x = acc[fm][fn][0] + bv.x; o0.y = acc[fm][fn][1] + bv.y;
            o1.x = acc[fm][fn][2] + bv.x; o1.y = acc[fm][fn][3] + bv.y;
            *(float2*)(C + (size_t)gm * ldc + gn) = o0;
            *(float2*)(C + (size_t)(gm + 8) * ldc + gn) = o1;
            if (smode) {
                const bool m0 = (smode == 2) || ((gn % 48) < 32);
                const bool m1 = (smode == 2) || (((gn + 1) % 48) < 32);
                ssa[fm][0] += (m0 ? o0.x * o0.x : 0.f) + (m1 ? o0.y * o0.y : 0.f);
                ssa[fm][1] += (m0 ? o1.x * o1.x : 0.f) + (m1 ? o1.y * o1.y : 0.f);
            }
        }
    }
    if (smode) {
#pragma unroll
        for (int fm = 0; fm < 2; fm++)
#pragma unroll
            for (int h = 0; h < 2; h++) {
                float v = ssa[fm][h];
                v += __shfl_xor_sync(0xffffffffu, v, 1);
                v += __shfl_xor_sync(0xffffffffu, v, 2);
                if ((lane & 3) == 0)
                    atomicAdd(ss + mB + wm + fm * 16 + er + h * 8, v);
            }
    }
}

// ---------------------------- windowed attention ----------------------------
// gathers directly from g_pv/g_pc (roll + window + norm + fp16 split inline)
// smem: Q2 64x200 half @0 (25600) | K2 @25600 | Vs 64x48 f32 @51200 (12288)
//       Ds 64x65 f32 @63488 (16640) | Ps 225 f32 @80128 (900)
//       ts int[64] @81028 | rv f32[64] @81284 | rc f32[64] @81540  total 81796
__global__ __launch_bounds__(256) void attn_k(const float* __restrict__ pos_emb,
                                              const float* __restrict__ lamp)
{
    extern __shared__ __align__(128) char smx[];
    __half* Q2 = (__half*)smx;
    __half* K2 = (__half*)(smx + 25600);
    float* Vs  = (float*)(smx + 51200);
    float* Ds  = (float*)(smx + 63488);
    float* Ps  = (float*)(smx + 80128);
    int*   ts  = (int*)(smx + 81028);
    float* rv  = (float*)(smx + 81284);
    float* rc  = (float*)(smx + 81540);

    int blk = blockIdx.x;
    const int wx = blk % NW_; blk /= NW_;
    const int wy = blk % NW_; blk /= NW_;
    const int head = blk % NH_;
    const int b = blk / NH_;
    const int tid = threadIdx.x;

    if (tid < 64) {
        const int ry = tid >> 3, rx = tid & 7;
        const int y = (wy * 8 + ry + 4) % Hh;
        const int x = (wx * 8 + rx + 4) % Wd;
        const int t = b * (Hh * Wd) + y * Wd + x;
        ts[tid] = t;
        rv[tid] = rsqrtf(g_ssv[t] * (1.f / 768.f) + 1e-6f);
        rc[tid] = rsqrtf(g_ssc[t] * (1.f / 768.f) + 1e-6f);
    }
    for (int i = tid; i < 225; i += 256) Ps[i] = pos_emb[i];
    __syncthreads();

    const float lam = lamp[0];
    const int hb = head * 48;
    // gather + normalize + fp16 hi/lo split for Q,K
    for (int i = tid; i < 64 * 96; i += 256) {
        const int tok = i / 96, ch = i - tok * 96;
        const int t = ts[tok];
        float qraw, kraw, fq, fk;
        if (ch < 48) {
            const float* pvr = g_pv + (size_t)t * 1152;
            qraw = pvr[hb + ch];
            kraw = pvr[384 + hb + ch];
            if (ch < 32) {
                const float r1 = rv[tok];
                fq = r1 * g_gvp[hb + ch];
                fk = r1 * g_gvp[384 + hb + ch];
            } else { fq = 1.f; fk = 1.f; }
        } else {
            const int c2 = ch - 48;
            const float* pcr = g_pc + (size_t)t * 768;
            qraw = pcr[hb + c2];
            kraw = pcr[384 + hb + c2];
            const float r2 = rc[tok];
            fq = r2 * g_gcp[hb + c2] * lam;
            fk = r2 * g_gcp[384 + hb + c2];
        }
        const float qv_ = qraw * fq, kv_ = kraw * fk;
        const __half qh = __float2half_rn(qv_);
        const __half kh = __float2half_rn(kv_);
        char* qrow = (char*)Q2 + tok * 400;
        char* krow = (char*)K2 + tok * 400;
        *(__half*)(qrow + ch * 2)       = qh;
        *(__half*)(qrow + 192 + ch * 2) = __float2half_rn(qv_ - __half2float(qh));
        *(__half*)(krow + ch * 2)       = kh;
        *(__half*)(krow + 192 + ch * 2) = __float2half_rn(kv_ - __half2float(kh));
    }
    // gather + normalize V (fp32)
    for (int i = tid; i < 64 * 48; i += 256) {
        const int tok = i / 48, ch = i - tok * 48;
        const int t = ts[tok];
        const float raw = g_pv[(size_t)t * 1152 + 768 + hb + ch];
        const float f = (ch < 32) ? rv[tok] * g_gvp[768 + hb + ch] : 1.f;
        Vs[tok * 48 + ch] = raw * f;
    }
    __syncthreads();

    // ---- QK^T via HMMA, exact 3-pass fp16 split ----
    const int lane = tid & 31, w = tid >> 5;
    const int wq = w & 3, wk = w >> 2;
    const int q = lane >> 3, tr = lane & 7;
    const uint32_t sQ = s2u(Q2), sK = s2u(K2);
    const uint32_t aBase = sQ + (uint32_t)(16 * wq + tr + ((q & 1) << 3)) * 400 + ((q >> 1) << 4);
    uint32_t bBase[2];
    bBase[0] = sK + (uint32_t)(32 * wk + tr + ((q >> 1) << 3)) * 400 + ((q & 1) << 4);
    bBase[1] = bBase[0] + 16 * 400;

    float acc[4][4] = {};
#pragma unroll
    for (int s = 0; s < 18; s++) {
        const int ca = (s < 12) ? s : s - 12;
        const int cb = (s < 6) ? s : s - 6;
        uint32_t a0, a1, a2, a3;
        LDSM4(a0, a1, a2, a3, aBase + ca * 32);
#pragma unroll
        for (int fn = 0; fn < 2; fn++) {
            uint32_t b0, b1, b2, b3;
            LDSM4(b0, b1, b2, b3, bBase[fn] + cb * 32);
            MMA16816(acc[2 * fn],     a0, a1, a2, a3, b0, b1);
            MMA16816(acc[2 * fn + 1], a0, a1, a2, a3, b2, b3);
        }
    }

    const float scale = 0.14433756729740643f;   // 1/sqrt(48)
    const bool lastR = (wy == NW_ - 1), lastC = (wx == NW_ - 1);
#pragma unroll
    for (int f = 0; f < 4; f++) {
#pragma unroll
        for (int r = 0; r < 4; r++) {
            const int i = 16 * wq + (lane >> 2) + ((r >> 1) << 3);
            const int j = 32 * wk + 8 * f + ((lane & 3) << 1) + (r & 1);
            float v = acc[f][r] * scale
                    + Ps[((j >> 3) - (i >> 3) + 7) * 15 + ((j & 7) - (i & 7) + 7)];
            if (lastR && (((i >= 32) ? 1 : 0) ^ ((j >= 32) ? 1 : 0)))           v = -INFINITY;
            if (lastC && ((((i & 7) >= 4) ? 1 : 0) ^ (((j & 7) >= 4) ? 1 : 0))) v = -INFINITY;
            Ds[i * 65 + j] = v;
        }
    }
    __syncthreads();

    // ---- softmax ----
    const int r = tid >> 2, qd = tid & 3;
    float m = -INFINITY;
#pragma unroll
    for (int j = 0; j < 16; j++) m = fmaxf(m, Ds[r * 65 + qd * 16 + j]);
    m = fmaxf(m, __shfl_xor_sync(0xffffffffu, m, 1));
    m = fmaxf(m, __shfl_xor_sync(0xffffffffu, m, 2));
    float s = 0.f;
#pragma unroll
    for (int j = 0; j < 16; j++) {
        float eV = __expf(Ds[r * 65 + qd * 16 + j] - m);
        Ds[r * 65 + qd * 16 + j] = eV;
        s += eV;
    }
    s += __shfl_xor_sync(0xffffffffu, s, 1);
    s += __shfl_xor_sync(0xffffffffu, s, 2);
    const float inv = 1.f / s;
    __syncthreads();

    // ---- AV (fp32 FFMA) ----
    float o[12] = {};
    for (int j = 0; j < 64; j++) {
        const float a = Ds[r * 65 + j] * inv;
        const float* vp = &Vs[j * 48 + qd * 12];
#pragma unroll
        for (int u = 0; u < 3; u++) {
            float4 v4 = *(const float4*)&vp[u * 4];
            o[u * 4 + 0] += a * v4.x; o[u * 4 + 1] += a * v4.y;
            o[u * 4 + 2] += a * v4.z; o[u * 4 + 3] += a * v4.w;
        }
    }
    const int Y = wy * 8 + (r >> 3), X = wx * 8 + (r & 7);
    const size_t t = ((size_t)b * Hh + Y) * Wd + X;
    __half* op = g_Yb + t * 768 + head * HD_ + qd * 12;
#pragma unroll
    for (int u = 0; u < 12; u++) {
        __half hi = __float2half_rn(o[u]);
        __half lo = __float2half_rn(o[u] - __half2float(hi));
        op[u] = hi; op[384 + u] = lo;
    }
}

// ------------------------------- launcher -----------------------------------
extern "C" void kernel_launch(void* const* d_in, const int* in_sizes, int n_in,
                              void* d_out, int out_size)
{
    const float* values = (const float*)d_in[0];
    const float* coords = (const float*)d_in[1];
    const float* W_vqk  = (const float*)d_in[2];
    const float* b_vqk  = (const float*)d_in[3];
    const float* gm_vqk = (const float*)d_in[4];
    const float* W_vv   = (const float*)d_in[5];
    const float* b_vv   = (const float*)d_in[6];
    const float* W_cqk  = (const float*)d_in[7];
    const float* b_cqk  = (const float*)d_in[8];
    const float* gm_cqk = (const float*)d_in[9];
    const float* lam    = (const float*)d_in[10];
    const float* pos    = (const float*)d_in[11];
    const float* W_ov   = (const float*)d_in[12];
    const float* b_ov   = (const float*)d_in[13];
    float* out = (float*)d_out;

    __half *Av, *Ac, *Yb, *Bv, *Bc, *Bo;
    float *pv, *pc, *biasv, *biasc, *ssv, *ssc;
    cudaGetSymbolAddress((void**)&Av, g_Av);
    cudaGetSymbolAddress((void**)&Ac, g_Ac);
    cudaGetSymbolAddress((void**)&Yb, g_Yb);
    cudaGetSymbolAddress((void**)&Bv, g_Bv);
    cudaGetSymbolAddress((void**)&Bc, g_Bc);
    cudaGetSymbolAddress((void**)&Bo, g_Bo);
    cudaGetSymbolAddress((void**)&pv, g_pv);
    cudaGetSymbolAddress((void**)&pc, g_pc);
    cudaGetSymbolAddress((void**)&biasv, g_biasv);
    cudaGetSymbolAddress((void**)&biasc, g_biasc);
    cudaGetSymbolAddress((void**)&ssv, g_ssv);
    cudaGetSymbolAddress((void**)&ssc, g_ssc);

    pack_all<<<(int)((T4 + 255) / 256), 256>>>(values, coords, W_vqk, W_vv, W_cqk, W_ov);
    metaperm<<<8, 256>>>(b_vqk, b_vv, gm_vqk, b_cqk, gm_cqk);
    zero_ss<<<(NTOK + 255) / 256, 256>>>();

    const int gsm = 65536;
    cudaFuncSetAttribute(gemm_mma, cudaFuncAttributeMaxDynamicSharedMemorySize, gsm);

    gemm_mma<<<dim3(768 / 128,  NTOK / 128), 256, gsm>>>(Ac, Bc, biasc, pc, 256,  768, ssc, 2);
    gemm_mma<<<dim3(1152 / 128, NTOK / 128), 256, gsm>>>(Av, Bv, biasv, pv, 768, 1152, ssv, 1);

    const int asm_ = 81796;
    cudaFuncSetAttribute(attn_k, cudaFuncAttributeMaxDynamicSharedMemorySize, asm_);
    attn_k<<<Bb * NH_ * NW_ * NW_, 256, asm_>>>(pos, lam);

    gemm_mma<<<dim3(384 / 128, NTOK / 128), 256, gsm>>>(Yb, Bo, b_ov, out, 768, 384, nullptr, 0);
}

// round 7
// speedup vs baseline: 1.5459x; 1.5459x over previous
#include <cuda_runtime.h>
#include <cuda_fp16.h>
#include <math.h>
#include <stdint.h>

#define Bb   2
#define Hh   192
#define Wd   192
#define NH_  8
#define HD_  48
#define NW_  24
#define NTOK (Bb*Hh*Wd)   // 73728

// ---------------- scratch (device globals; no runtime alloc) ----------------
__device__ __half g_Av[(size_t)NTOK * 768];    // values split [hi|lo]
__device__ __half g_Ac[(size_t)NTOK * 256];    // coords split
__device__ __half g_Yb[(size_t)NTOK * 768];    // attn out split
__device__ __half g_Bv[1152 * 768];            // W' permuted vqk|vv [N, hi|hi]
__device__ __half g_Bc[768 * 256];             // W' permuted cqk
__device__ __half g_Bo[384 * 768];             // W' ov
__device__ float g_biasv[1152];
__device__ float g_biasc[768];
__device__ float g_gvp[1152];
__device__ float g_gcp[768];
__device__ float g_pv[(size_t)NTOK * 1152];    // proj out: [Q|K|V] head-major, +bias
__device__ float g_pc[(size_t)NTOK * 768];     // proj out: [Qc|Kc] head-major, +bias
__device__ float g_ssv[NTOK];
__device__ float g_ssc[NTOK];

// ------------------------------ PTX helpers ---------------------------------
__device__ __forceinline__ uint32_t s2u(const void* p) {
    uint32_t a;
    asm("{ .reg .u64 t; cvta.to.shared.u64 t, %1; cvt.u32.u64 %0, t; }" : "=r"(a) : "l"(p));
    return a;
}
__device__ __forceinline__ void cp16(uint32_t dst, const void* src) {
    asm volatile("cp.async.cg.shared.global [%0], [%1], 16;" :: "r"(dst), "l"(src));
}
#define CP_COMMIT() asm volatile("cp.async.commit_group;" ::: "memory")
#define CP_WAIT1()  asm volatile("cp.async.wait_group 1;" ::: "memory")
#define CP_WAIT0()  asm volatile("cp.async.wait_group 0;" ::: "memory")

#define LDSM4(R0,R1,R2,R3,ADDR) \
    asm volatile("ldmatrix.sync.aligned.m8n8.x4.shared.b16 {%0,%1,%2,%3}, [%4];" \
                 : "=r"(R0), "=r"(R1), "=r"(R2), "=r"(R3) : "r"(ADDR))
#define LDSM2(R0,R1,ADDR) \
    asm volatile("ldmatrix.sync.aligned.m8n8.x2.shared.b16 {%0,%1}, [%2];" \
                 : "=r"(R0), "=r"(R1) : "r"(ADDR))

#define MMA16816(D,A0,A1,A2,A3,B0,B1) \
    asm volatile("mma.sync.aligned.m16n8k16.row.col.f32.f16.f16.f32 " \
                 "{%0,%1,%2,%3},{%4,%5,%6,%7},{%8,%9},{%0,%1,%2,%3};" \
                 : "+f"(D[0]), "+f"(D[1]), "+f"(D[2]), "+f"(D[3]) \
                 : "r"(A0), "r"(A1), "r"(A2), "r"(A3), "r"(B0), "r"(B1))

__device__ __forceinline__ uint32_t packh(__half a, __half b) {
    return (uint32_t)__half_as_ushort(a) | ((uint32_t)__half_as_ushort(b) << 16);
}

// ---------------- fused pack + metaperm + ss-zero (1 launch) -----------------
#define T0 ((size_t)NTOK * 384)
#define T1 (T0 + (size_t)NTOK * 128)
#define T2 (T1 + 1152 * 384)
#define T3 (T2 + 768 * 128)
#define T4 (T3 + 384 * 384)
#define T5 (T4 + NTOK)
#define T6 (T5 + 1920)
__global__ void pack_all(const float* __restrict__ values, const float* __restrict__ coords,
                         const float* __restrict__ Wqk, const float* __restrict__ Wvv,
                         const float* __restrict__ Wcqk, const float* __restrict__ Wov,
                         const float* __restrict__ bqk, const float* __restrict__ bvv,
                         const float* __restrict__ gvqk,
                         const float* __restrict__ bcqk, const float* __restrict__ gcqk)
{
    size_t i = (size_t)blockIdx.x * 256 + threadIdx.x;
    if (i < T0) {
        size_t t = i / 384; int k = (int)(i - t * 384);
        float x = values[i];
        __half hi = __float2half_rn(x);
        __half lo = __float2half_rn(x - __half2float(hi));
        __half* row = g_Av + t * 768;
        row[k] = hi; row[384 + k] = lo;
    } else if (i < T1) {
        size_t j = i - T0;
        size_t t = j / 128; int k = (int)(j - t * 128);
        float x = coords[j];
        __half hi = __float2half_rn(x);
        __half lo = __float2half_rn(x - __half2float(hi));
        __half* row = g_Ac + t * 256;
        row[k] = hi; row[128 + k] = lo;
    } else if (i < T2) {                // B_v permuted de-interleave [Q|K|V] head-major
        int j = (int)(i - T1);
        int n = j / 384, k = j - (j / 384) * 384;
        const int blk = n / 384;
        const int hm = (n % 384) / 48, e = n % 48;
        const int c = 3 * (e * 8 + hm) + blk;
        float w = (c < 768) ? Wqk[(size_t)k * 768 + c] : Wvv[(size_t)k * 384 + (c - 768)];
        __half hi = __float2half_rn(w);
        __half* row = g_Bv + (size_t)n * 768;
        row[k] = hi; row[384 + k] = hi;
    } else if (i < T3) {                // B_c permuted [Qc|Kc]
        int j = (int)(i - T2);
        int n = j / 128, k = j - (j / 128) * 128;
        const int blk = n / 384;
        const int hm = (n % 384) / 48, e = n % 48;
        const int c = 2 * (e * 8 + hm) + blk;
        float w = Wcqk[(size_t)k * 768 + c];
        __half hi = __float2half_rn(w);
        __half* row = g_Bc + (size_t)n * 256;
        row[k] = hi; row[128 + k] = hi;
    } else if (i < T4) {                // B_o
        int j = (int)(i - T3);
        int n = j / 384, k = j - (j / 384) * 384;
        float w = Wov[(size_t)k * 384 + n];
        __half hi = __float2half_rn(w);
        __half* row = g_Bo + (size_t)n * 768;
        row[k] = hi; row[384 + k] = hi;
    } else if (i < T5) {                // ss zero
        const int t = (int)(i - T4);
        g_ssv[t] = 0.f; g_ssc[t] = 0.f;
    } else if (i < T6) {                // bias/gamma permute
        int n = (int)(i - T5);
        if (n < 1152) {
            const int blk = n / 384, hm = (n % 384) / 48, e = n % 48;
            const int c = 3 * (e * 8 + hm) + blk;
            g_biasv[n] = (c < 768) ? bqk[c] : bvv[c - 768];
            g_gvp[n]   = (c < 768) ? gvqk[c] : 1.0f;
        } else {
            const int n2 = n - 1152;
            const int blk = n2 / 384, hm = (n2 % 384) / 48, e = n2 % 48;
            const int c = 2 * (e * 8 + hm) + blk;
            g_biasc[n2] = bcqk[c];
            g_gcp[n2]   = gcqk[c];
        }
    }
}

// --------- HMMA GEMM: C = A'[M,K'] @ B'[N,K']^T + bias; optional ss ---------
__global__ __launch_bounds__(256, 2) void gemm_mma(
    const __half* __restrict__ A, const __half* __restrict__ B,
    const float* __restrict__ bias, float* __restrict__ C, int Kp, int ldc,
    float* __restrict__ ss, int smode)
{
    extern __shared__ __align__(1024) char smem[];
    const uint32_t sb = s2u(smem);
    const int tid = threadIdx.x, lane = tid & 31, wid = tid >> 5;
    const int mB = blockIdx.y * 128, n0 = blockIdx.x * 128;
    const int wm = (wid & 3) << 5;
    const int wn = (wid >> 2) << 6;

    const int lrow = tid >> 3, lu = tid & 7;
    const size_t ldk = (size_t)Kp * 2;
    const char* Asrc = (const char*)A + (size_t)(mB + lrow) * ldk + lu * 16;
    const char* Bsrc = (const char*)B + (size_t)(n0 + lrow) * ldk + lu * 16;
    uint32_t dsto[4];
#pragma unroll
    for (int r = 0; r < 4; r++) {
        const int row = lrow + r * 32;
        dsto[r] = row * 128 + ((lu ^ (row & 7)) << 4);
    }

    const int q = lane >> 3, tr = lane & 7;
    const int qA = q >> 1, qB = q & 1;
    uint32_t rowoffA[2], xrA[2];
#pragma unroll
    for (int fm = 0; fm < 2; fm++) {
        const int row = wm + fm * 16 + tr + ((q & 1) << 3);
        rowoffA[fm] = row * 128; xrA[fm] = row & 7;
    }
    uint32_t rowoffB[4], xrB[4];
#pragma unroll
    for (int fn = 0; fn < 4; fn++) {
        const int row = wn + fn * 16 + tr + ((q >> 1) << 3);
        rowoffB[fn] = row * 128; xrB[fn] = row & 7;
    }

    float acc[2][8][4] = {};

    const int NC = Kp >> 6;
#pragma unroll
    for (int r = 0; r < 4; r++) {
        cp16(sb + dsto[r],          Asrc + (size_t)r * 32 * ldk);
        cp16(sb + 32768u + dsto[r], Bsrc + (size_t)r * 32 * ldk);
    }
    CP_COMMIT();

    for (int c = 0; c < NC; c++) {
        const int buf = c & 1;
        if (c + 1 < NC) {
            const uint32_t ab = sb + (buf ^ 1) * 16384u;
            const uint32_t bb = sb + 32768u + (buf ^ 1) * 16384u;
            const char* An = Asrc + (size_t)(c + 1) * 128;
            const char* Bn = Bsrc + (size_t)(c + 1) * 128;
#pragma unroll
            for (int r = 0; r < 4; r++) {
                cp16(ab + dsto[r], An + (size_t)r * 32 * ldk);
                cp16(bb + dsto[r], Bn + (size_t)r * 32 * ldk);
            }
            CP_COMMIT();
            CP_WAIT1();
        } else {
            CP_WAIT0();
        }
        __syncthreads();

        const uint32_t Ab = sb + buf * 16384u;
        const uint32_t Bs = sb + 32768u + buf * 16384u;
#pragma unroll
        for (int ks = 0; ks < 4; ks++) {
            uint32_t a[2][4], bf[4][4];
#pragma unroll
            for (int fm = 0; fm < 2; fm++) {
                const uint32_t ad = Ab + rowoffA[fm] + ((((uint32_t)(ks * 2 + qA)) ^ xrA[fm]) << 4);
                LDSM4(a[fm][0], a[fm][1], a[fm][2], a[fm][3], ad);
            }
#pragma unroll
            for (int fn = 0; fn < 4; fn++) {
                const uint32_t bd = Bs + rowoffB[fn] + ((((uint32_t)(ks * 2 + qB)) ^ xrB[fn]) << 4);
                LDSM4(bf[fn][0], bf[fn][1], bf[fn][2], bf[fn][3], bd);
            }
#pragma unroll
            for (int fm = 0; fm < 2; fm++)
#pragma unroll
                for (int fn = 0; fn < 4; fn++) {
                    MMA16816(acc[fm][2 * fn],     a[fm][0], a[fm][1], a[fm][2], a[fm][3],
                             bf[fn][0], bf[fn][1]);
                    MMA16816(acc[fm][2 * fn + 1], a[fm][0], a[fm][1], a[fm][2], a[fm][3],
                             bf[fn][2], bf[fn][3]);
                }
        }
        __syncthreads();
    }

    const int er = lane >> 2, ec = (lane & 3) << 1;
    float ssa[2][2] = {{0.f, 0.f}, {0.f, 0.f}};
#pragma unroll
    for (int fm = 0; fm < 2; fm++) {
#pragma unroll
        for (int fn = 0; fn < 8; fn++) {
            const int gm = mB + wm + fm * 16 + er;
            const int gn = n0 + wn + fn * 8 + ec;
            const float2 bv = *(const float2*)(bias + gn);
            float2 o0, o1;
            o0.x = acc[fm][fn][0] + bv.x; o0.y = acc[fm][fn][1] + bv.y;
            o1.x = acc[fm][fn][2] + bv.x; o1.y = acc[fm][fn][3] + bv.y;
            *(float2*)(C + (size_t)gm * ldc + gn) = o0;
            *(float2*)(C + (size_t)(gm + 8) * ldc + gn) = o1;
            if (smode) {
                const bool m0 = (smode == 2) || ((gn % 48) < 32);
                const bool m1 = (smode == 2) || (((gn + 1) % 48) < 32);
                ssa[fm][0] += (m0 ? o0.x * o0.x : 0.f) + (m1 ? o0.y * o0.y : 0.f);
                ssa[fm][1] += (m0 ? o1.x * o1.x : 0.f) + (m1 ? o1.y * o1.y : 0.f);
            }
        }
    }
    if (smode) {
#pragma unroll
        for (int fm = 0; fm < 2; fm++)
#pragma unroll
            for (int h = 0; h < 2; h++) {
                float v = ssa[fm][h];
                v += __shfl_xor_sync(0xffffffffu, v, 1);
                v += __shfl_xor_sync(0xffffffffu, v, 2);
                if ((lane & 3) == 0)
                    atomicAdd(ss + mB + wm + fm * 16 + er + h * 8, v);
            }
    }
}

// ---------------------------- windowed attention ----------------------------
// smem layout (bytes):
#define Q2_OFF  0u            // 64 x 400  (96 hi + 96 lo halves + pad)
#define K2_OFF  25600u
#define VTH_OFF 51200u        // 48 x 144  (V^T hi, 64 toks + pad)
#define VTL_OFF 58112u
#define DS_OFF  65024u        // 64 x 65 f32
#define PH_OFF  81664u        // 64 x 144  (P hi)
#define PL_OFF  90880u
#define PS_OFF  100096u       // 225 f32
#define TS_OFF  100996u
#define RV_OFF  101252u
#define RC_OFF  101508u
#define ASMB    101764
__global__ __launch_bounds__(256) void attn_k(const float* __restrict__ pos_emb,
                                              const float* __restrict__ lamp)
{
    extern __shared__ __align__(128) char smx[];
    float* Ds = (float*)(smx + DS_OFF);
    float* Ps = (float*)(smx + PS_OFF);
    int*   ts = (int*)(smx + TS_OFF);
    float* rv = (float*)(smx + RV_OFF);
    float* rc = (float*)(smx + RC_OFF);

    int blk = blockIdx.x;
    const int wx = blk % NW_; blk /= NW_;
    const int wy = blk % NW_; blk /= NW_;
    const int head = blk % NH_;
    const int b = blk / NH_;
    const int tid = threadIdx.x;

    if (tid < 64) {
        const int ry = tid >> 3, rx = tid & 7;
        const int y = (wy * 8 + ry + 4) % Hh;
        const int x = (wx * 8 + rx + 4) % Wd;
        const int t = b * (Hh * Wd) + y * Wd + x;
        ts[tid] = t;
        rv[tid] = rsqrtf(g_ssv[t] * (1.f / 768.f) + 1e-6f);
        rc[tid] = rsqrtf(g_ssc[t] * (1.f / 768.f) + 1e-6f);
    }
    for (int i = tid; i < 225; i += 256) Ps[i] = pos_emb[i];
    __syncthreads();

    const float lam = lamp[0];
    const int hb = head * 48;

    // ---- Q/K gather: float4 loads, hi/lo split, 8B smem stores ----
    for (int i = tid; i < 64 * 24; i += 256) {
        const int tok = i / 24, u = i - tok * 24;
        const int t = ts[tok];
        float4 qr, kr, gq, gk;
        int ch;
        if (u < 12) {
            ch = u * 4;
            const float* pvr = g_pv + (size_t)t * 1152;
            qr = *(const float4*)(pvr + hb + ch);
            kr = *(const float4*)(pvr + 384 + hb + ch);
            if (u < 8) {
                const float r1 = rv[tok];
                gq = *(const float4*)(g_gvp + hb + ch);
                gk = *(const float4*)(g_gvp + 384 + hb + ch);
                gq.x *= r1; gq.y *= r1; gq.z *= r1; gq.w *= r1;
                gk.x *= r1; gk.y *= r1; gk.z *= r1; gk.w *= r1;
            } else {
                gq = make_float4(1.f, 1.f, 1.f, 1.f);
                gk = gq;
            }
        } else {
            const int c2 = (u - 12) * 4;
            ch = 48 + c2;
            const float* pcr = g_pc + (size_t)t * 768;
            qr = *(const float4*)(pcr + hb + c2);
            kr = *(const float4*)(pcr + 384 + hb + c2);
            const float r2 = rc[tok];
            const float r2l = r2 * lam;
            gq = *(const float4*)(g_gcp + hb + c2);
            gk = *(const float4*)(g_gcp + 384 + hb + c2);
            gq.x *= r2l; gq.y *= r2l; gq.z *= r2l; gq.w *= r2l;
            gk.x *= r2;  gk.y *= r2;  gk.z *= r2;  gk.w *= r2;
        }
        const float q0 = qr.x * gq.x, q1 = qr.y * gq.y, q2 = qr.z * gq.z, q3 = qr.w * gq.w;
        const float k0 = kr.x * gk.x, k1 = kr.y * gk.y, k2 = kr.z * gk.z, k3 = kr.w * gk.w;
        __half qh0 = __float2half_rn(q0), qh1 = __float2half_rn(q1),
               qh2 = __float2half_rn(q2), qh3 = __float2half_rn(q3);
        __half kh0 = __float2half_rn(k0), kh1 = __float2half_rn(k1),
               kh2 = __float2half_rn(k2), kh3 = __float2half_rn(k3);
        uint2 qh = make_uint2(packh(qh0, qh1), packh(qh2, qh3));
        uint2 kh = make_uint2(packh(kh0, kh1), packh(kh2, kh3));
        uint2 ql = make_uint2(
            packh(__float2half_rn(q0 - __half2float(qh0)), __float2half_rn(q1 - __half2float(qh1))),
            packh(__float2half_rn(q2 - __half2float(qh2)), __float2half_rn(q3 - __half2float(qh3))));
        uint2 kl = make_uint2(
            packh(__float2half_rn(k0 - __half2float(kh0)), __float2half_rn(k1 - __half2float(kh1))),
            packh(__float2half_rn(k2 - __half2float(kh2)), __float2half_rn(k3 - __half2float(kh3))));
        char* qrow = smx + Q2_OFF + tok * 400;
        char* krow = smx + K2_OFF + tok * 400;
        *(uint2*)(qrow + ch * 2)       = qh;
        *(uint2*)(qrow + 192 + ch * 2) = ql;
        *(uint2*)(krow + ch * 2)       = kh;
        *(uint2*)(krow + 192 + ch * 2) = kl;
    }
    // ---- V gather: transposed e-major hi/lo ----
    {
        __half* vh = (__half*)(smx + VTH_OFF);
        __half* vl = (__half*)(smx + VTL_OFF);
        for (int i = tid; i < 64 * 12; i += 256) {
            const int tok = i / 12, u = i - tok * 12;
            const int t = ts[tok];
            const int ch = u * 4;
            float4 raw = *(const float4*)(g_pv + (size_t)t * 1152 + 768 + hb + ch);
            float4 g;
            if (u < 8) {
                const float r1 = rv[tok];
                g = *(const float4*)(g_gvp + 768 + hb + ch);
                g.x *= r1; g.y *= r1; g.z *= r1; g.w *= r1;
            } else g = make_float4(1.f, 1.f, 1.f, 1.f);
            const float v0 = raw.x * g.x, v1 = raw.y * g.y, v2 = raw.z * g.z, v3 = raw.w * g.w;
            const __half h0 = __float2half_rn(v0), h1 = __float2half_rn(v1),
                         h2 = __float2half_rn(v2), h3 = __float2half_rn(v3);
            vh[(ch + 0) * 72 + tok] = h0;
            vh[(ch + 1) * 72 + tok] = h1;
            vh[(ch + 2) * 72 + tok] = h2;
            vh[(ch + 3) * 72 + tok] = h3;
            vl[(ch + 0) * 72 + tok] = __float2half_rn(v0 - __half2float(h0));
            vl[(ch + 1) * 72 + tok] = __float2half_rn(v1 - __half2float(h1));
            vl[(ch + 2) * 72 + tok] = __float2half_rn(v2 - __half2float(h2));
            vl[(ch + 3) * 72 + tok] = __float2half_rn(v3 - __half2float(h3));
        }
    }
    __syncthreads();

    // ---- QK^T via HMMA, exact 3-pass fp16 split ----
    const int lane = tid & 31, w = tid >> 5;
    const int wq = w & 3, wk = w >> 2;
    const int q = lane >> 3, tr = lane & 7;
    const uint32_t sQ = s2u(smx + Q2_OFF), sK = s2u(smx + K2_OFF);
    const uint32_t aBase = sQ + (uint32_t)(16 * wq + tr + ((q & 1) << 3)) * 400 + ((q >> 1) << 4);
    uint32_t bBase[2];
    bBase[0] = sK + (uint32_t)(32 * wk + tr + ((q >> 1) << 3)) * 400 + ((q & 1) << 4);
    bBase[1] = bBase[0] + 16 * 400;

    float acc[4][4] = {};
#pragma unroll
    for (int s = 0; s < 18; s++) {
        const int ca = (s < 12) ? s : s - 12;
        const int cb = (s < 6) ? s : s - 6;
        uint32_t a0, a1, a2, a3;
        LDSM4(a0, a1, a2, a3, aBase + ca * 32);
#pragma unroll
        for (int fn = 0; fn < 2; fn++) {
            uint32_t b0, b1, b2, b3;
            LDSM4(b0, b1, b2, b3, bBase[fn] + cb * 32);
            MMA16816(acc[2 * fn],     a0, a1, a2, a3, b0, b1);
            MMA16816(acc[2 * fn + 1], a0, a1, a2, a3, b2, b3);
        }
    }

    const float scale = 0.14433756729740643f;   // 1/sqrt(48)
    const bool lastR = (wy == NW_ - 1), lastC = (wx == NW_ - 1);
#pragma unroll
    for (int f = 0; f < 4; f++) {
#pragma unroll
        for (int r = 0; r < 4; r++) {
            const int i = 16 * wq + (lane >> 2) + ((r >> 1) << 3);
            const int j = 32 * wk + 8 * f + ((lane & 3) << 1) + (r & 1);
            float v = acc[f][r] * scale
                    + Ps[((j >> 3) - (i >> 3) + 7) * 15 + ((j & 7) - (i & 7) + 7)];
            if (lastR && (((i >= 32) ? 1 : 0) ^ ((j >= 32) ? 1 : 0)))           v = -INFINITY;
            if (lastC && ((((i & 7) >= 4) ? 1 : 0) ^ (((j & 7) >= 4) ? 1 : 0))) v = -INFINITY;
            Ds[i * 65 + j] = v;
        }
    }
    __syncthreads();

    // ---- softmax -> P hi/lo fp16 ----
    {
        const int r = tid >> 2, qd = tid & 3;
        float m = -INFINITY;
#pragma unroll
        for (int j = 0; j < 16; j++) m = fmaxf(m, Ds[r * 65 + qd * 16 + j]);
        m = fmaxf(m, __shfl_xor_sync(0xffffffffu, m, 1));
        m = fmaxf(m, __shfl_xor_sync(0xffffffffu, m, 2));
        float ev[16];
        float s = 0.f;
#pragma unroll
        for (int j = 0; j < 16; j++) {
            ev[j] = __expf(Ds[r * 65 + qd * 16 + j] - m);
            s += ev[j];
        }
        s += __shfl_xor_sync(0xffffffffu, s, 1);
        s += __shfl_xor_sync(0xffffffffu, s, 2);
        const float inv = 1.f / s;
        char* PhB = smx + PH_OFF + r * 144 + qd * 32;
        char* PlB = smx + PL_OFF + r * 144 + qd * 32;
#pragma unroll
        for (int j = 0; j < 16; j += 2) {
            const float p0 = ev[j] * inv, p1 = ev[j + 1] * inv;
            const __half h0 = __float2half_rn(p0), h1 = __float2half_rn(p1);
            *(uint32_t*)(PhB + j * 2) = packh(h0, h1);
            *(uint32_t*)(PlB + j * 2) = packh(__float2half_rn(p0 - __half2float(h0)),
                                              __float2half_rn(p1 - __half2float(h1)));
        }
    }
    __syncthreads();

    // ---- AV via HMMA: PhVh + PlVh + PhVl ----
    const int wq2 = w & 3, wn2 = w >> 2;   // m16 slice, n24 slice
    const uint32_t sPh = s2u(smx + PH_OFF), sPl = s2u(smx + PL_OFF);
    const uint32_t sVh = s2u(smx + VTH_OFF), sVl = s2u(smx + VTL_OFF);
    const uint32_t aOff = (uint32_t)(16 * wq2 + tr + ((q & 1) << 3)) * 144 + ((q >> 1) << 4);
    const uint32_t b4Off = (uint32_t)(24 * wn2 + tr + ((q >> 1) << 3)) * 144 + ((q & 1) << 4);
    const int tr2 = lane & 7, q01 = (lane >> 3) & 1;
    const uint32_t b2Off = (uint32_t)(24 * wn2 + 16 + tr2) * 144 + (q01 << 4);

    float acc3[3][4] = {};
#pragma unroll
    for (int p = 0; p < 3; p++) {
        const uint32_t aB = (p == 1 ? sPl : sPh);
        const uint32_t bB = (p == 2 ? sVl : sVh);
#pragma unroll
        for (int ks = 0; ks < 4; ks++) {
            uint32_t a0, a1, a2, a3, b0, b1, b2, b3, b4, b5;
            LDSM4(a0, a1, a2, a3, aB + aOff + ks * 32);
            LDSM4(b0, b1, b2, b3, bB + b4Off + ks * 32);
            LDSM2(b4, b5, bB + b2Off + ks * 32);
            MMA16816(acc3[0], a0, a1, a2, a3, b0, b1);
            MMA16816(acc3[1], a0, a1, a2, a3, b2, b3);
            MMA16816(acc3[2], a0, a1, a2, a3, b4, b5);
        }
    }

    // ---- output: hi/lo fp16 split straight to g_Yb ----
    const int er2 = lane >> 2, ec2 = (lane & 3) << 1;
#pragma unroll
    for (int h = 0; h < 2; h++) {
        const int i = 16 * wq2 + er2 + h * 8;
        const int Y = wy * 8 + (i >> 3), X = wx * 8 + (i & 7);
        const size_t t = ((size_t)b * Hh + Y) * Wd + X;
        __half* op = g_Yb + t * 768 + hb;
#pragma unroll
        for (int f = 0; f < 3; f++) {
            const int e = 24 * wn2 + 8 * f + ec2;
            const float v0 = acc3[f][h * 2], v1 = acc3[f][h * 2 + 1];
            const __half h0 = __float2half_rn(v0), h1 = __float2half_rn(v1);
            *(__half2*)(op + e) = __halves2half2(h0, h1);
            *(__half2*)(op + 384 + e) = __halves2half2(
                __float2half_rn(v0 - __half2float(h0)),
                __float2half_rn(v1 - __half2float(h1)));
        }
    }
}

// ------------------------------- launcher -----------------------------------
extern "C" void kernel_launch(void* const* d_in, const int* in_sizes, int n_in,
                              void* d_out, int out_size)
{
    const float* values = (const float*)d_in[0];
    const float* coords = (const float*)d_in[1];
    const float* W_vqk  = (const float*)d_in[2];
    const float* b_vqk  = (const float*)d_in[3];
    const float* gm_vqk = (const float*)d_in[4];
    const float* W_vv   = (const float*)d_in[5];
    const float* b_vv   = (const float*)d_in[6];
    const float* W_cqk  = (const float*)d_in[7];
    const float* b_cqk  = (const float*)d_in[8];
    const float* gm_cqk = (const float*)d_in[9];
    const float* lam    = (const float*)d_in[10];
    const float* pos    = (const float*)d_in[11];
    const float* W_ov   = (const float*)d_in[12];
    const float* b_ov   = (const float*)d_in[13];
    float* out = (float*)d_out;

    __half *Av, *Ac, *Yb, *Bv, *Bc, *Bo;
    float *pv, *pc, *biasv, *biasc, *ssv, *ssc;
    cudaGetSymbolAddress((void**)&Av, g_Av);
    cudaGetSymbolAddress((void**)&Ac, g_Ac);
    cudaGetSymbolAddress((void**)&Yb, g_Yb);
    cudaGetSymbolAddress((void**)&Bv, g_Bv);
    cudaGetSymbolAddress((void**)&Bc, g_Bc);
    cudaGetSymbolAddress((void**)&Bo, g_Bo);
    cudaGetSymbolAddress((void**)&pv, g_pv);
    cudaGetSymbolAddress((void**)&pc, g_pc);
    cudaGetSymbolAddress((void**)&biasv, g_biasv);
    cudaGetSymbolAddress((void**)&biasc, g_biasc);
    cudaGetSymbolAddress((void**)&ssv, g_ssv);
    cudaGetSymbolAddress((void**)&ssc, g_ssc);

    // 1) fused pack + ss-zero + meta permute
    pack_all<<<(int)((T6 + 255) / 256), 256>>>(values, coords, W_vqk, W_vv, W_cqk, W_ov,
                                               b_vqk, b_vv, gm_vqk, b_cqk, gm_cqk);

    const int gsm = 65536;
    cudaFuncSetAttribute(gemm_mma, cudaFuncAttributeMaxDynamicSharedMemorySize, gsm);

    // 2) coords projection, 3) values projection
    gemm_mma<<<dim3(768 / 128,  NTOK / 128), 256, gsm>>>(Ac, Bc, biasc, pc, 256,  768, ssc, 2);
    gemm_mma<<<dim3(1152 / 128, NTOK / 128), 256, gsm>>>(Av, Bv, biasv, pv, 768, 1152, ssv, 1);

    // 4) attention (profiled slot)
    cudaFuncSetAttribute(attn_k, cudaFuncAttributeMaxDynamicSharedMemorySize, ASMB);
    attn_k<<<Bb * NH_ * NW_ * NW_, 256, ASMB>>>(pos, lam);

    // 5) output projection
    gemm_mma<<<dim3(384 / 128, NTOK / 128), 256, gsm>>>(Yb, Bo, b_ov, out, 768, 384, nullptr, 0);
}

// round 8
// speedup vs baseline: 1.5908x; 1.0290x over previous
#include <cuda_runtime.h>
#include <cuda_fp16.h>
#include <math.h>
#include <stdint.h>

#define Bb   2
#define Hh   192
#define Wd   192
#define NH_  8
#define HD_  48
#define NW_  24
#define NTOK (Bb*Hh*Wd)   // 73728

// ---------------- scratch (device globals; no runtime alloc) ----------------
__device__ __half g_Av[(size_t)NTOK * 768];    // values split [hi|lo]
__device__ __half g_Ac[(size_t)NTOK * 256];    // coords split
__device__ __half g_Yb[(size_t)NTOK * 768];    // attn out split
__device__ __half g_Bv[1152 * 768];            // W' permuted vqk|vv [N, hi|hi]
__device__ __half g_Bc[768 * 256];             // W' permuted cqk
__device__ __half g_Bo[384 * 768];             // W' ov
__device__ float g_biasv[1152];
__device__ float g_biasc[768];
__device__ float g_gvp[1152];
__device__ float g_gcp[768];
__device__ float g_pv[(size_t)NTOK * 1152];    // proj out: [Q|K|V] head-major, +bias
__device__ float g_pc[(size_t)NTOK * 768];     // proj out: [Qc|Kc] head-major, +bias
__device__ float g_ssv[NTOK];
__device__ float g_ssc[NTOK];

// ------------------------------ PTX helpers ---------------------------------
__device__ __forceinline__ uint32_t s2u(const void* p) {
    uint32_t a;
    asm("{ .reg .u64 t; cvta.to.shared.u64 t, %1; cvt.u32.u64 %0, t; }" : "=r"(a) : "l"(p));
    return a;
}
__device__ __forceinline__ void cp16(uint32_t dst, const void* src) {
    asm volatile("cp.async.cg.shared.global [%0], [%1], 16;" :: "r"(dst), "l"(src));
}
#define CP_COMMIT() asm volatile("cp.async.commit_group;" ::: "memory")
#define CP_WAIT1()  asm volatile("cp.async.wait_group 1;" ::: "memory")
#define CP_WAIT0()  asm volatile("cp.async.wait_group 0;" ::: "memory")

#define LDSM4(R0,R1,R2,R3,ADDR) \
    asm volatile("ldmatrix.sync.aligned.m8n8.x4.shared.b16 {%0,%1,%2,%3}, [%4];" \
                 : "=r"(R0), "=r"(R1), "=r"(R2), "=r"(R3) : "r"(ADDR))
#define LDSM2(R0,R1,ADDR) \
    asm volatile("ldmatrix.sync.aligned.m8n8.x2.shared.b16 {%0,%1}, [%2];" \
                 : "=r"(R0), "=r"(R1) : "r"(ADDR))

#define MMA16816(D,A0,A1,A2,A3,B0,B1) \
    asm volatile("mma.sync.aligned.m16n8k16.row.col.f32.f16.f16.f32 " \
                 "{%0,%1,%2,%3},{%4,%5,%6,%7},{%8,%9},{%0,%1,%2,%3};" \
                 : "+f"(D[0]), "+f"(D[1]), "+f"(D[2]), "+f"(D[3]) \
                 : "r"(A0), "r"(A1), "r"(A2), "r"(A3), "r"(B0), "r"(B1))

__device__ __forceinline__ uint32_t packh(__half a, __half b) {
    return (uint32_t)__half_as_ushort(a) | ((uint32_t)__half_as_ushort(b) << 16);
}

// ---------------- fused pack + metaperm + ss-zero (1 launch) -----------------
#define T0 ((size_t)NTOK * 384)
#define T1 (T0 + (size_t)NTOK * 128)
#define T2 (T1 + 1152 * 384)
#define T3 (T2 + 768 * 128)
#define T4 (T3 + 384 * 384)
#define T5 (T4 + NTOK)
#define T6 (T5 + 1920)
__global__ void pack_all(const float* __restrict__ values, const float* __restrict__ coords,
                         const float* __restrict__ Wqk, const float* __restrict__ Wvv,
                         const float* __restrict__ Wcqk, const float* __restrict__ Wov,
                         const float* __restrict__ bqk, const float* __restrict__ bvv,
                         const float* __restrict__ gvqk,
                         const float* __restrict__ bcqk, const float* __restrict__ gcqk)
{
    size_t i = (size_t)blockIdx.x * 256 + threadIdx.x;
    if (i < T0) {
        size_t t = i / 384; int k = (int)(i - t * 384);
        float x = values[i];
        __half hi = __float2half_rn(x);
        __half lo = __float2half_rn(x - __half2float(hi));
        __half* row = g_Av + t * 768;
        row[k] = hi; row[384 + k] = lo;
    } else if (i < T1) {
        size_t j = i - T0;
        size_t t = j / 128; int k = (int)(j - t * 128);
        float x = coords[j];
        __half hi = __float2half_rn(x);
        __half lo = __float2half_rn(x - __half2float(hi));
        __half* row = g_Ac + t * 256;
        row[k] = hi; row[128 + k] = lo;
    } else if (i < T2) {                // B_v permuted de-interleave [Q|K|V] head-major
        int j = (int)(i - T1);
        int n = j / 384, k = j - (j / 384) * 384;
        const int blk = n / 384;
        const int hm = (n % 384) / 48, e = n % 48;
        const int c = 3 * (e * 8 + hm) + blk;
        float w = (c < 768) ? Wqk[(size_t)k * 768 + c] : Wvv[(size_t)k * 384 + (c - 768)];
        __half hi = __float2half_rn(w);
        __half* row = g_Bv + (size_t)n * 768;
        row[k] = hi; row[384 + k] = hi;
    } else if (i < T3) {                // B_c permuted [Qc|Kc]
        int j = (int)(i - T2);
        int n = j / 128, k = j - (j / 128) * 128;
        const int blk = n / 384;
        const int hm = (n % 384) / 48, e = n % 48;
        const int c = 2 * (e * 8 + hm) + blk;
        float w = Wcqk[(size_t)k * 768 + c];
        __half hi = __float2half_rn(w);
        __half* row = g_Bc + (size_t)n * 256;
        row[k] = hi; row[128 + k] = hi;
    } else if (i < T4) {                // B_o
        int j = (int)(i - T3);
        int n = j / 384, k = j - (j / 384) * 384;
        float w = Wov[(size_t)k * 384 + n];
        __half hi = __float2half_rn(w);
        __half* row = g_Bo + (size_t)n * 768;
        row[k] = hi; row[384 + k] = hi;
    } else if (i < T5) {                // ss zero
        const int t = (int)(i - T4);
        g_ssv[t] = 0.f; g_ssc[t] = 0.f;
    } else if (i < T6) {                // bias/gamma permute
        int n = (int)(i - T5);
        if (n < 1152) {
            const int blk = n / 384, hm = (n % 384) / 48, e = n % 48;
            const int c = 3 * (e * 8 + hm) + blk;
            g_biasv[n] = (c < 768) ? bqk[c] : bvv[c - 768];
            g_gvp[n]   = (c < 768) ? gvqk[c] : 1.0f;
        } else {
            const int n2 = n - 1152;
            const int blk = n2 / 384, hm = (n2 % 384) / 48, e = n2 % 48;
            const int c = 2 * (e * 8 + hm) + blk;
            g_biasc[n2] = bcqk[c];
            g_gcp[n2]   = gcqk[c];
        }
    }
}

// --------- HMMA GEMM: C = A'[M,K'] @ B'[N,K']^T + bias; optional ss ---------
__global__ __launch_bounds__(256, 2) void gemm_mma(
    const __half* __restrict__ A, const __half* __restrict__ B,
    const float* __restrict__ bias, float* __restrict__ C, int Kp, int ldc,
    float* __restrict__ ss, int smode)
{
    extern __shared__ __align__(1024) char smem[];
    const uint32_t sb = s2u(smem);
    const int tid = threadIdx.x, lane = tid & 31, wid = tid >> 5;
    const int mB = blockIdx.y * 128, n0 = blockIdx.x * 128;
    const int wm = (wid & 3) << 5;
    const int wn = (wid >> 2) << 6;

    const int lrow = tid >> 3, lu = tid & 7;
    const size_t ldk = (size_t)Kp * 2;
    const char* Asrc = (const char*)A + (size_t)(mB + lrow) * ldk + lu * 16;
    const char* Bsrc = (const char*)B + (size_t)(n0 + lrow) * ldk + lu * 16;
    uint32_t dsto[4];
#pragma unroll
    for (int r = 0; r < 4; r++) {
        const int row = lrow + r * 32;
        dsto[r] = row * 128 + ((lu ^ (row & 7)) << 4);
    }

    const int q = lane >> 3, tr = lane & 7;
    const int qA = q >> 1, qB = q & 1;
    uint32_t rowoffA[2], xrA[2];
#pragma unroll
    for (int fm = 0; fm < 2; fm++) {
        const int row = wm + fm * 16 + tr + ((q & 1) << 3);
        rowoffA[fm] = row * 128; xrA[fm] = row & 7;
    }
    uint32_t rowoffB[4], xrB[4];
#pragma unroll
    for (int fn = 0; fn < 4; fn++) {
        const int row = wn + fn * 16 + tr + ((q >> 1) << 3);
        rowoffB[fn] = row * 128; xrB[fn] = row & 7;
    }

    float acc[2][8][4] = {};

    const int NC = Kp >> 6;
#pragma unroll
    for (int r = 0; r < 4; r++) {
        cp16(sb + dsto[r],          Asrc + (size_t)r * 32 * ldk);
        cp16(sb + 32768u + dsto[r], Bsrc + (size_t)r * 32 * ldk);
    }
    CP_COMMIT();

    for (int c = 0; c < NC; c++) {
        const int buf = c & 1;
        if (c + 1 < NC) {
            const uint32_t ab = sb + (buf ^ 1) * 16384u;
            const uint32_t bb = sb + 32768u + (buf ^ 1) * 16384u;
            const char* An = Asrc + (size_t)(c + 1) * 128;
            const char* Bn = Bsrc + (size_t)(c + 1) * 128;
#pragma unroll
            for (int r = 0; r < 4; r++) {
                cp16(ab + dsto[r], An + (size_t)r * 32 * ldk);
                cp16(bb + dsto[r], Bn + (size_t)r * 32 * ldk);
            }
            CP_COMMIT();
            CP_WAIT1();
        } else {
            CP_WAIT0();
        }
        __syncthreads();

        const uint32_t Ab = sb + buf * 16384u;
        const uint32_t Bs = sb + 32768u + buf * 16384u;
#pragma unroll
        for (int ks = 0; ks < 4; ks++) {
            uint32_t a[2][4], bf[4][4];
#pragma unroll
            for (int fm = 0; fm < 2; fm++) {
                const uint32_t ad = Ab + rowoffA[fm] + ((((uint32_t)(ks * 2 + qA)) ^ xrA[fm]) << 4);
                LDSM4(a[fm][0], a[fm][1], a[fm][2], a[fm][3], ad);
            }
#pragma unroll
            for (int fn = 0; fn < 4; fn++) {
                const uint32_t bd = Bs + rowoffB[fn] + ((((uint32_t)(ks * 2 + qB)) ^ xrB[fn]) << 4);
                LDSM4(bf[fn][0], bf[fn][1], bf[fn][2], bf[fn][3], bd);
            }
#pragma unroll
            for (int fm = 0; fm < 2; fm++)
#pragma unroll
                for (int fn = 0; fn < 4; fn++) {
                    MMA16816(acc[fm][2 * fn],     a[fm][0], a[fm][1], a[fm][2], a[fm][3],
                             bf[fn][0], bf[fn][1]);
                    MMA16816(acc[fm][2 * fn + 1], a[fm][0], a[fm][1], a[fm][2], a[fm][3],
                             bf[fn][2], bf[fn][3]);
                }
        }
        __syncthreads();
    }

    const int er = lane >> 2, ec = (lane & 3) << 1;
    float ssa[2][2] = {{0.f, 0.f}, {0.f, 0.f}};
#pragma unroll
    for (int fm = 0; fm < 2; fm++) {
#pragma unroll
        for (int fn = 0; fn < 8; fn++) {
            const int gm = mB + wm + fm * 16 + er;
            const int gn = n0 + wn + fn * 8 + ec;
            const float2 bv = *(const float2*)(bias + gn);
            float2 o0, o1;
            o0.x = acc[fm][fn][0] + bv.x; o0.y = acc[fm][fn][1] + bv.y;
            o1.x = acc[fm][fn][2] + bv.x; o1.y = acc[fm][fn][3] + bv.y;
            *(float2*)(C + (size_t)gm * ldc + gn) = o0;
            *(float2*)(C + (size_t)(gm + 8) * ldc + gn) = o1;
            if (smode) {
                const bool m0 = (smode == 2) || ((gn % 48) < 32);
                const bool m1 = (smode == 2) || (((gn + 1) % 48) < 32);
                ssa[fm][0] += (m0 ? o0.x * o0.x : 0.f) + (m1 ? o0.y * o0.y : 0.f);
                ssa[fm][1] += (m0 ? o1.x * o1.x : 0.f) + (m1 ? o1.y * o1.y : 0.f);
            }
        }
    }
    if (smode) {
#pragma unroll
        for (int fm = 0; fm < 2; fm++)
#pragma unroll
            for (int h = 0; h < 2; h++) {
                float v = ssa[fm][h];
                v += __shfl_xor_sync(0xffffffffu, v, 1);
                v += __shfl_xor_sync(0xffffffffu, v, 2);
                if ((lane & 3) == 0)
                    atomicAdd(ss + mB + wm + fm * 16 + er + h * 8, v);
            }
    }
}

// ---------------------------- windowed attention ----------------------------
// smem layout (bytes) — Ds/Ph/Pl ALIAS the Q2/K2 region (dead after QK MMA):
#define Q2_OFF  0u            // 64 x 400  (96 hi + 96 lo halves + pad)
#define K2_OFF  25600u
#define DS_OFF  0u            // 64 x 65 f32 (16640) — aliases Q2
#define PH_OFF  16640u        // 64 x 144  (P hi, 9216)
#define PL_OFF  25856u        // 64 x 144  (P lo, 9216) — ends 35072 < 51200
#define VTH_OFF 51200u        // 48 x 144  (V^T hi)
#define VTL_OFF 58112u
#define PS_OFF  65024u        // 225 f32
#define TS_OFF  65936u
#define RV_OFF  66192u
#define RC_OFF  66448u
#define ASMB    66704
__global__ __launch_bounds__(256, 2) void attn_k(const float* __restrict__ pos_emb,
                                                 const float* __restrict__ lamp)
{
    extern __shared__ __align__(128) char smx[];
    float* Ds = (float*)(smx + DS_OFF);
    float* Ps = (float*)(smx + PS_OFF);
    int*   ts = (int*)(smx + TS_OFF);
    float* rv = (float*)(smx + RV_OFF);
    float* rc = (float*)(smx + RC_OFF);

    int blk = blockIdx.x;
    const int wx = blk % NW_; blk /= NW_;
    const int wy = blk % NW_; blk /= NW_;
    const int head = blk % NH_;
    const int b = blk / NH_;
    const int tid = threadIdx.x;

    if (tid < 64) {
        const int ry = tid >> 3, rx = tid & 7;
        const int y = (wy * 8 + ry + 4) % Hh;
        const int x = (wx * 8 + rx + 4) % Wd;
        const int t = b * (Hh * Wd) + y * Wd + x;
        ts[tid] = t;
        rv[tid] = rsqrtf(g_ssv[t] * (1.f / 768.f) + 1e-6f);
        rc[tid] = rsqrtf(g_ssc[t] * (1.f / 768.f) + 1e-6f);
    }
    for (int i = tid; i < 225; i += 256) Ps[i] = pos_emb[i];
    __syncthreads();

    const float lam = lamp[0];
    const int hb = head * 48;

    // ---- Q/K gather: float4 loads, hi/lo split, 8B smem stores ----
    for (int i = tid; i < 64 * 24; i += 256) {
        const int tok = i / 24, u = i - tok * 24;
        const int t = ts[tok];
        float4 qr, kr, gq, gk;
        int ch;
        if (u < 12) {
            ch = u * 4;
            const float* pvr = g_pv + (size_t)t * 1152;
            qr = *(const float4*)(pvr + hb + ch);
            kr = *(const float4*)(pvr + 384 + hb + ch);
            if (u < 8) {
                const float r1 = rv[tok];
                gq = *(const float4*)(g_gvp + hb + ch);
                gk = *(const float4*)(g_gvp + 384 + hb + ch);
                gq.x *= r1; gq.y *= r1; gq.z *= r1; gq.w *= r1;
                gk.x *= r1; gk.y *= r1; gk.z *= r1; gk.w *= r1;
            } else {
                gq = make_float4(1.f, 1.f, 1.f, 1.f);
                gk = gq;
            }
        } else {
            const int c2 = (u - 12) * 4;
            ch = 48 + c2;
            const float* pcr = g_pc + (size_t)t * 768;
            qr = *(const float4*)(pcr + hb + c2);
            kr = *(const float4*)(pcr + 384 + hb + c2);
            const float r2 = rc[tok];
            const float r2l = r2 * lam;
            gq = *(const float4*)(g_gcp + hb + c2);
            gk = *(const float4*)(g_gcp + 384 + hb + c2);
            gq.x *= r2l; gq.y *= r2l; gq.z *= r2l; gq.w *= r2l;
            gk.x *= r2;  gk.y *= r2;  gk.z *= r2;  gk.w *= r2;
        }
        const float q0 = qr.x * gq.x, q1 = qr.y * gq.y, q2 = qr.z * gq.z, q3 = qr.w * gq.w;
        const float k0 = kr.x * gk.x, k1 = kr.y * gk.y, k2 = kr.z * gk.z, k3 = kr.w * gk.w;
        __half qh0 = __float2half_rn(q0), qh1 = __float2half_rn(q1),
               qh2 = __float2half_rn(q2), qh3 = __float2half_rn(q3);
        __half kh0 = __float2half_rn(k0), kh1 = __float2half_rn(k1),
               kh2 = __float2half_rn(k2), kh3 = __float2half_rn(k3);
        uint2 qh = make_uint2(packh(qh0, qh1), packh(qh2, qh3));
        uint2 kh = make_uint2(packh(kh0, kh1), packh(kh2, kh3));
        uint2 ql = make_uint2(
            packh(__float2half_rn(q0 - __half2float(qh0)), __float2half_rn(q1 - __half2float(qh1))),
            packh(__float2half_rn(q2 - __half2float(qh2)), __float2half_rn(q3 - __half2float(qh3))));
        uint2 kl = make_uint2(
            packh(__float2half_rn(k0 - __half2float(kh0)), __float2half_rn(k1 - __half2float(kh1))),
            packh(__float2half_rn(k2 - __half2float(kh2)), __float2half_rn(k3 - __half2float(kh3))));
        char* qrow = smx + Q2_OFF + tok * 400;
        char* krow = smx + K2_OFF + tok * 400;
        *(uint2*)(qrow + ch * 2)       = qh;
        *(uint2*)(qrow + 192 + ch * 2) = ql;
        *(uint2*)(krow + ch * 2)       = kh;
        *(uint2*)(krow + 192 + ch * 2) = kl;
    }
    // ---- V gather: transposed e-major hi/lo ----
    {
        __half* vh = (__half*)(smx + VTH_OFF);
        __half* vl = (__half*)(smx + VTL_OFF);
        for (int i = tid; i < 64 * 12; i += 256) {
            const int tok = i / 12, u = i - tok * 12;
            const int t = ts[tok];
            const int ch = u * 4;
            float4 raw = *(const float4*)(g_pv + (size_t)t * 1152 + 768 + hb + ch);
            float4 g;
            if (u < 8) {
                const float r1 = rv[tok];
                g = *(const float4*)(g_gvp + 768 + hb + ch);
                g.x *= r1; g.y *= r1; g.z *= r1; g.w *= r1;
            } else g = make_float4(1.f, 1.f, 1.f, 1.f);
            const float v0 = raw.x * g.x, v1 = raw.y * g.y, v2 = raw.z * g.z, v3 = raw.w * g.w;
            const __half h0 = __float2half_rn(v0), h1 = __float2half_rn(v1),
                         h2 = __float2half_rn(v2), h3 = __float2half_rn(v3);
            vh[(ch + 0) * 72 + tok] = h0;
            vh[(ch + 1) * 72 + tok] = h1;
            vh[(ch + 2) * 72 + tok] = h2;
            vh[(ch + 3) * 72 + tok] = h3;
            vl[(ch + 0) * 72 + tok] = __float2half_rn(v0 - __half2float(h0));
            vl[(ch + 1) * 72 + tok] = __float2half_rn(v1 - __half2float(h1));
            vl[(ch + 2) * 72 + tok] = __float2half_rn(v2 - __half2float(h2));
            vl[(ch + 3) * 72 + tok] = __float2half_rn(v3 - __half2float(h3));
        }
    }
    __syncthreads();

    // ---- QK^T via HMMA, exact 3-pass fp16 split ----
    const int lane = tid & 31, w = tid >> 5;
    const int wq = w & 3, wk = w >> 2;
    const int q = lane >> 3, tr = lane & 7;
    const uint32_t sQ = s2u(smx + Q2_OFF), sK = s2u(smx + K2_OFF);
    const uint32_t aBase = sQ + (uint32_t)(16 * wq + tr + ((q & 1) << 3)) * 400 + ((q >> 1) << 4);
    uint32_t bBase[2];
    bBase[0] = sK + (uint32_t)(32 * wk + tr + ((q >> 1) << 3)) * 400 + ((q & 1) << 4);
    bBase[1] = bBase[0] + 16 * 400;

    float acc[4][4] = {};
#pragma unroll
    for (int s = 0; s < 18; s++) {
        const int ca = (s < 12) ? s : s - 12;
        const int cb = (s < 6) ? s : s - 6;
        uint32_t a0, a1, a2, a3;
        LDSM4(a0, a1, a2, a3, aBase + ca * 32);
#pragma unroll
        for (int fn = 0; fn < 2; fn++) {
            uint32_t b0, b1, b2, b3;
            LDSM4(b0, b1, b2, b3, bBase[fn] + cb * 32);
            MMA16816(acc[2 * fn],     a0, a1, a2, a3, b0, b1);
            MMA16816(acc[2 * fn + 1], a0, a1, a2, a3, b2, b3);
        }
    }
    __syncthreads();   // Q2/K2 now dead everywhere; safe to write aliased Ds

    const float scale = 0.14433756729740643f;   // 1/sqrt(48)
    const bool lastR = (wy == NW_ - 1), lastC = (wx == NW_ - 1);
#pragma unroll
    for (int f = 0; f < 4; f++) {
#pragma unroll
        for (int r = 0; r < 4; r++) {
            const int i = 16 * wq + (lane >> 2) + ((r >> 1) << 3);
            const int j = 32 * wk + 8 * f + ((lane & 3) << 1) + (r & 1);
            float v = acc[f][r] * scale
                    + Ps[((j >> 3) - (i >> 3) + 7) * 15 + ((j & 7) - (i & 7) + 7)];
            if (lastR && (((i >= 32) ? 1 : 0) ^ ((j >= 32) ? 1 : 0)))           v = -INFINITY;
            if (lastC && ((((i & 7) >= 4) ? 1 : 0) ^ (((j & 7) >= 4) ? 1 : 0))) v = -INFINITY;
            Ds[i * 65 + j] = v;
        }
    }
    __syncthreads();

    // ---- softmax -> P hi/lo fp16 ----
    {
        const int r = tid >> 2, qd = tid & 3;
        float m = -INFINITY;
#pragma unroll
        for (int j = 0; j < 16; j++) m = fmaxf(m, Ds[r * 65 + qd * 16 + j]);
        m = fmaxf(m, __shfl_xor_sync(0xffffffffu, m, 1));
        m = fmaxf(m, __shfl_xor_sync(0xffffffffu, m, 2));
        float ev[16];
        float s = 0.f;
#pragma unroll
        for (int j = 0; j < 16; j++) {
            ev[j] = __expf(Ds[r * 65 + qd * 16 + j] - m);
            s += ev[j];
        }
        s += __shfl_xor_sync(0xffffffffu, s, 1);
        s += __shfl_xor_sync(0xffffffffu, s, 2);
        const float inv = 1.f / s;
        char* PhB = smx + PH_OFF + r * 144 + qd * 32;
        char* PlB = smx + PL_OFF + r * 144 + qd * 32;
#pragma unroll
        for (int j = 0; j < 16; j += 2) {
            const float p0 = ev[j] * inv, p1 = ev[j + 1] * inv;
            const __half h0 = __float2half_rn(p0), h1 = __float2half_rn(p1);
            *(uint32_t*)(PhB + j * 2) = packh(h0, h1);
            *(uint32_t*)(PlB + j * 2) = packh(__float2half_rn(p0 - __half2float(h0)),
                                              __float2half_rn(p1 - __half2float(h1)));
        }
    }
    __syncthreads();

    // ---- AV via HMMA: PhVh + PlVh + PhVl ----
    const int wq2 = w & 3, wn2 = w >> 2;   // m16 slice, n24 slice
    const uint32_t sPh = s2u(smx + PH_OFF), sPl = s2u(smx + PL_OFF);
    const uint32_t sVh = s2u(smx + VTH_OFF), sVl = s2u(smx + VTL_OFF);
    const uint32_t aOff = (uint32_t)(16 * wq2 + tr + ((q & 1) << 3)) * 144 + ((q >> 1) << 4);
    const uint32_t b4Off = (uint32_t)(24 * wn2 + tr + ((q >> 1) << 3)) * 144 + ((q & 1) << 4);
    const int tr2 = lane & 7, q01 = (lane >> 3) & 1;
    const uint32_t b2Off = (uint32_t)(24 * wn2 + 16 + tr2) * 144 + (q01 << 4);

    float acc3[3][4] = {};
#pragma unroll
    for (int p = 0; p < 3; p++) {
        const uint32_t aB = (p == 1 ? sPl : sPh);
        const uint32_t bB = (p == 2 ? sVl : sVh);
#pragma unroll
        for (int ks = 0; ks < 4; ks++) {
            uint32_t a0, a1, a2, a3, b0, b1, b2, b3, b4, b5;
            LDSM4(a0, a1, a2, a3, aB + aOff + ks * 32);
            LDSM4(b0, b1, b2, b3, bB + b4Off + ks * 32);
            LDSM2(b4, b5, bB + b2Off + ks * 32);
            MMA16816(acc3[0], a0, a1, a2, a3, b0, b1);
            MMA16816(acc3[1], a0, a1, a2, a3, b2, b3);
            MMA16816(acc3[2], a0, a1, a2, a3, b4, b5);
        }
    }

    // ---- output: hi/lo fp16 split straight to g_Yb ----
    const int er2 = lane >> 2, ec2 = (lane & 3) << 1;
#pragma unroll
    for (int h = 0; h < 2; h++) {
        const int i = 16 * wq2 + er2 + h * 8;
        const int Y = wy * 8 + (i >> 3), X = wx * 8 + (i & 7);
        const size_t t = ((size_t)b * Hh + Y) * Wd + X;
        __half* op = g_Yb + t * 768 + hb;
#pragma unroll
        for (int f = 0; f < 3; f++) {
            const int e = 24 * wn2 + 8 * f + ec2;
            const float v0 = acc3[f][h * 2], v1 = acc3[f][h * 2 + 1];
            const __half h0 = __float2half_rn(v0), h1 = __float2half_rn(v1);
            *(__half2*)(op + e) = __halves2half2(h0, h1);
            *(__half2*)(op + 384 + e) = __halves2half2(
                __float2half_rn(v0 - __half2float(h0)),
                __float2half_rn(v1 - __half2float(h1)));
        }
    }
}

// ------------------------------- launcher -----------------------------------
extern "C" void kernel_launch(void* const* d_in, const int* in_sizes, int n_in,
                              void* d_out, int out_size)
{
    const float* values = (const float*)d_in[0];
    const float* coords = (const float*)d_in[1];
    const float* W_vqk  = (const float*)d_in[2];
    const float* b_vqk  = (const float*)d_in[3];
    const float* gm_vqk = (const float*)d_in[4];
    const float* W_vv   = (const float*)d_in[5];
    const float* b_vv   = (const float*)d_in[6];
    const float* W_cqk  = (const float*)d_in[7];
    const float* b_cqk  = (const float*)d_in[8];
    const float* gm_cqk = (const float*)d_in[9];
    const float* lam    = (const float*)d_in[10];
    const float* pos    = (const float*)d_in[11];
    const float* W_ov   = (const float*)d_in[12];
    const float* b_ov   = (const float*)d_in[13];
    float* out = (float*)d_out;

    __half *Av, *Ac, *Yb, *Bv, *Bc, *Bo;
    float *pv, *pc, *biasv, *biasc, *ssv, *ssc;
    cudaGetSymbolAddress((void**)&Av, g_Av);
    cudaGetSymbolAddress((void**)&Ac, g_Ac);
    cudaGetSymbolAddress((void**)&Yb, g_Yb);
    cudaGetSymbolAddress((void**)&Bv, g_Bv);
    cudaGetSymbolAddress((void**)&Bc, g_Bc);
    cudaGetSymbolAddress((void**)&Bo, g_Bo);
    cudaGetSymbolAddress((void**)&pv, g_pv);
    cudaGetSymbolAddress((void**)&pc, g_pc);
    cudaGetSymbolAddress((void**)&biasv, g_biasv);
    cudaGetSymbolAddress((void**)&biasc, g_biasc);
    cudaGetSymbolAddress((void**)&ssv, g_ssv);
    cudaGetSymbolAddress((void**)&ssc, g_ssc);

    // 1) fused pack + ss-zero + meta permute
    pack_all<<<(int)((T6 + 255) / 256), 256>>>(values, coords, W_vqk, W_vv, W_cqk, W_ov,
                                               b_vqk, b_vv, gm_vqk, b_cqk, gm_cqk);

    const int gsm = 65536;
    cudaFuncSetAttribute(gemm_mma, cudaFuncAttributeMaxDynamicSharedMemorySize, gsm);

    // 2) coords projection, 3) values projection
    gemm_mma<<<dim3(768 / 128,  NTOK / 128), 256, gsm>>>(Ac, Bc, biasc, pc, 256,  768, ssc, 2);
    gemm_mma<<<dim3(1152 / 128, NTOK / 128), 256, gsm>>>(Av, Bv, biasv, pv, 768, 1152, ssv, 1);

    // 4) attention
    cudaFuncSetAttribute(attn_k, cudaFuncAttributeMaxDynamicSharedMemorySize, ASMB);
    attn_k<<<Bb * NH_ * NW_ * NW_, 256, ASMB>>>(pos, lam);

    // 5) output projection
    gemm_mma<<<dim3(384 / 128, NTOK / 128), 256, gsm>>>(Yb, Bo, b_ov, out, 768, 384, nullptr, 0);
}

// round 9
// speedup vs baseline: 1.6752x; 1.0531x over previous
#include <cuda_runtime.h>
#include <cuda_fp16.h>
#include <math.h>
#include <stdint.h>

#define Bb   2
#define Hh   192
#define Wd   192
#define NH_  8
#define HD_  48
#define NW_  24
#define NTOK (Bb*Hh*Wd)   // 73728

// ---------------- scratch (device globals; no runtime alloc) ----------------
__device__ __half g_Av[(size_t)NTOK * 768];    // values split [hi|lo]
__device__ __half g_Ac[(size_t)NTOK * 256];    // coords split
__device__ __half g_Yb[(size_t)NTOK * 768];    // attn out split
__device__ __half g_Bv[1152 * 768];            // W' permuted vqk|vv [N, hi|hi]
__device__ __half g_Bc[768 * 256];             // W' permuted cqk
__device__ __half g_Bo[384 * 768];             // W' ov
__device__ float g_biasv[1152];
__device__ float g_biasc[768];
__device__ float g_gvp[1152];
__device__ float g_gcp[768];
__device__ float g_pv[(size_t)NTOK * 1152];    // proj out: [Q|K|V] head-major, +bias
__device__ float g_pc[(size_t)NTOK * 768];     // proj out: [Qc|Kc] head-major, +bias
__device__ float g_ssv[NTOK];
__device__ float g_ssc[NTOK];

// ------------------------------ PTX helpers ---------------------------------
__device__ __forceinline__ uint32_t s2u(const void* p) {
    uint32_t a;
    asm("{ .reg .u64 t; cvta.to.shared.u64 t, %1; cvt.u32.u64 %0, t; }" : "=r"(a) : "l"(p));
    return a;
}
__device__ __forceinline__ void cp16(uint32_t dst, const void* src) {
    asm volatile("cp.async.cg.shared.global [%0], [%1], 16;" :: "r"(dst), "l"(src));
}
#define CP_COMMIT() asm volatile("cp.async.commit_group;" ::: "memory")
#define CP_WAIT1()  asm volatile("cp.async.wait_group 1;" ::: "memory")
#define CP_WAIT0()  asm volatile("cp.async.wait_group 0;" ::: "memory")

#define LDSM4(R0,R1,R2,R3,ADDR) \
    asm volatile("ldmatrix.sync.aligned.m8n8.x4.shared.b16 {%0,%1,%2,%3}, [%4];" \
                 : "=r"(R0), "=r"(R1), "=r"(R2), "=r"(R3) : "r"(ADDR))
#define LDSM2(R0,R1,ADDR) \
    asm volatile("ldmatrix.sync.aligned.m8n8.x2.shared.b16 {%0,%1}, [%2];" \
                 : "=r"(R0), "=r"(R1) : "r"(ADDR))

#define MMA16816(D,A0,A1,A2,A3,B0,B1) \
    asm volatile("mma.sync.aligned.m16n8k16.row.col.f32.f16.f16.f32 " \
                 "{%0,%1,%2,%3},{%4,%5,%6,%7},{%8,%9},{%0,%1,%2,%3};" \
                 : "+f"(D[0]), "+f"(D[1]), "+f"(D[2]), "+f"(D[3]) \
                 : "r"(A0), "r"(A1), "r"(A2), "r"(A3), "r"(B0), "r"(B1))

__device__ __forceinline__ uint32_t packh(__half a, __half b) {
    return (uint32_t)__half_as_ushort(a) | ((uint32_t)__half_as_ushort(b) << 16);
}

// ---------------- fused pack + metaperm + ss-zero (1 launch) -----------------
#define T0 ((size_t)NTOK * 384)
#define T1 (T0 + (size_t)NTOK * 128)
#define T2 (T1 + 1152 * 384)
#define T3 (T2 + 768 * 128)
#define T4 (T3 + 384 * 384)
#define T5 (T4 + NTOK)
#define T6 (T5 + 1920)
__global__ void pack_all(const float* __restrict__ values, const float* __restrict__ coords,
                         const float* __restrict__ Wqk, const float* __restrict__ Wvv,
                         const float* __restrict__ Wcqk, const float* __restrict__ Wov,
                         const float* __restrict__ bqk, const float* __restrict__ bvv,
                         const float* __restrict__ gvqk,
                         const float* __restrict__ bcqk, const float* __restrict__ gcqk)
{
    size_t i = (size_t)blockIdx.x * 256 + threadIdx.x;
    if (i < T0) {
        size_t t = i / 384; int k = (int)(i - t * 384);
        float x = values[i];
        __half hi = __float2half_rn(x);
        __half lo = __float2half_rn(x - __half2float(hi));
        __half* row = g_Av + t * 768;
        row[k] = hi; row[384 + k] = lo;
    } else if (i < T1) {
        size_t j = i - T0;
        size_t t = j / 128; int k = (int)(j - t * 128);
        float x = coords[j];
        __half hi = __float2half_rn(x);
        __half lo = __float2half_rn(x - __half2float(hi));
        __half* row = g_Ac + t * 256;
        row[k] = hi; row[128 + k] = lo;
    } else if (i < T2) {                // B_v permuted de-interleave [Q|K|V] head-major
        int j = (int)(i - T1);
        int n = j / 384, k = j - (j / 384) * 384;
        const int blk = n / 384;
        const int hm = (n % 384) / 48, e = n % 48;
        const int c = 3 * (e * 8 + hm) + blk;
        float w = (c < 768) ? Wqk[(size_t)k * 768 + c] : Wvv[(size_t)k * 384 + (c - 768)];
        __half hi = __float2half_rn(w);
        __half* row = g_Bv + (size_t)n * 768;
        row[k] = hi; row[384 + k] = hi;
    } else if (i < T3) {                // B_c permuted [Qc|Kc]
        int j = (int)(i - T2);
        int n = j / 128, k = j - (j / 128) * 128;
        const int blk = n / 384;
        const int hm = (n % 384) / 48, e = n % 48;
        const int c = 2 * (e * 8 + hm) + blk;
        float w = Wcqk[(size_t)k * 768 + c];
        __half hi = __float2half_rn(w);
        __half* row = g_Bc + (size_t)n * 256;
        row[k] = hi; row[128 + k] = hi;
    } else if (i < T4) {                // B_o
        int j = (int)(i - T3);
        int n = j / 384, k = j - (j / 384) * 384;
        float w = Wov[(size_t)k * 384 + n];
        __half hi = __float2half_rn(w);
        __half* row = g_Bo + (size_t)n * 768;
        row[k] = hi; row[384 + k] = hi;
    } else if (i < T5) {                // ss zero
        const int t = (int)(i - T4);
        g_ssv[t] = 0.f; g_ssc[t] = 0.f;
    } else if (i < T6) {                // bias/gamma permute
        int n = (int)(i - T5);
        if (n < 1152) {
            const int blk = n / 384, hm = (n % 384) / 48, e = n % 48;
            const int c = 3 * (e * 8 + hm) + blk;
            g_biasv[n] = (c < 768) ? bqk[c] : bvv[c - 768];
            g_gvp[n]   = (c < 768) ? gvqk[c] : 1.0f;
        } else {
            const int n2 = n - 1152;
            const int blk = n2 / 384, hm = (n2 % 384) / 48, e = n2 % 48;
            const int c = 2 * (e * 8 + hm) + blk;
            g_biasc[n2] = bcqk[c];
            g_gcp[n2]   = gcqk[c];
        }
    }
}

// --------- HMMA GEMM: C = A'[M,K'] @ B'[N,K']^T + bias; optional ss ---------
__global__ __launch_bounds__(256, 2) void gemm_mma(
    const __half* __restrict__ A, const __half* __restrict__ B,
    const float* __restrict__ bias, float* __restrict__ C, int Kp, int ldc,
    float* __restrict__ ss, int smode)
{
    extern __shared__ __align__(1024) char smem[];
    const uint32_t sb = s2u(smem);
    const int tid = threadIdx.x, lane = tid & 31, wid = tid >> 5;
    const int mB = blockIdx.y * 128, n0 = blockIdx.x * 128;
    const int wm = (wid & 3) << 5;
    const int wn = (wid >> 2) << 6;

    const int lrow = tid >> 3, lu = tid & 7;
    const size_t ldk = (size_t)Kp * 2;
    const char* Asrc = (const char*)A + (size_t)(mB + lrow) * ldk + lu * 16;
    const char* Bsrc = (const char*)B + (size_t)(n0 + lrow) * ldk + lu * 16;
    uint32_t dsto[4];
#pragma unroll
    for (int r = 0; r < 4; r++) {
        const int row = lrow + r * 32;
        dsto[r] = row * 128 + ((lu ^ (row & 7)) << 4);
    }

    const int q = lane >> 3, tr = lane & 7;
    const int qA = q >> 1, qB = q & 1;
    uint32_t rowoffA[2], xrA[2];
#pragma unroll
    for (int fm = 0; fm < 2; fm++) {
        const int row = wm + fm * 16 + tr + ((q & 1) << 3);
        rowoffA[fm] = row * 128; xrA[fm] = row & 7;
    }
    uint32_t rowoffB[4], xrB[4];
#pragma unroll
    for (int fn = 0; fn < 4; fn++) {
        const int row = wn + fn * 16 + tr + ((q >> 1) << 3);
        rowoffB[fn] = row * 128; xrB[fn] = row & 7;
    }

    float acc[2][8][4] = {};

    const int NC = Kp >> 6;
#pragma unroll
    for (int r = 0; r < 4; r++) {
        cp16(sb + dsto[r],          Asrc + (size_t)r * 32 * ldk);
        cp16(sb + 32768u + dsto[r], Bsrc + (size_t)r * 32 * ldk);
    }
    CP_COMMIT();

    for (int c = 0; c < NC; c++) {
        const int buf = c & 1;
        if (c + 1 < NC) {
            const uint32_t ab = sb + (buf ^ 1) * 16384u;
            const uint32_t bb = sb + 32768u + (buf ^ 1) * 16384u;
            const char* An = Asrc + (size_t)(c + 1) * 128;
            const char* Bn = Bsrc + (size_t)(c + 1) * 128;
#pragma unroll
            for (int r = 0; r < 4; r++) {
                cp16(ab + dsto[r], An + (size_t)r * 32 * ldk);
                cp16(bb + dsto[r], Bn + (size_t)r * 32 * ldk);
            }
            CP_COMMIT();
            CP_WAIT1();
        } else {
            CP_WAIT0();
        }
        __syncthreads();

        const uint32_t Ab = sb + buf * 16384u;
        const uint32_t Bs = sb + 32768u + buf * 16384u;
#pragma unroll
        for (int ks = 0; ks < 4; ks++) {
            uint32_t a[2][4], bf[4][4];
#pragma unroll
            for (int fm = 0; fm < 2; fm++) {
                const uint32_t ad = Ab + rowoffA[fm] + ((((uint32_t)(ks * 2 + qA)) ^ xrA[fm]) << 4);
                LDSM4(a[fm][0], a[fm][1], a[fm][2], a[fm][3], ad);
            }
#pragma unroll
            for (int fn = 0; fn < 4; fn++) {
                const uint32_t bd = Bs + rowoffB[fn] + ((((uint32_t)(ks * 2 + qB)) ^ xrB[fn]) << 4);
                LDSM4(bf[fn][0], bf[fn][1], bf[fn][2], bf[fn][3], bd);
            }
#pragma unroll
            for (int fm = 0; fm < 2; fm++)
#pragma unroll
                for (int fn = 0; fn < 4; fn++) {
                    MMA16816(acc[fm][2 * fn],     a[fm][0], a[fm][1], a[fm][2], a[fm][3],
                             bf[fn][0], bf[fn][1]);
                    MMA16816(acc[fm][2 * fn + 1], a[fm][0], a[fm][1], a[fm][2], a[fm][3],
                             bf[fn][2], bf[fn][3]);
                }
        }
        __syncthreads();
    }

    const int er = lane >> 2, ec = (lane & 3) << 1;
    float ssa[2][2] = {{0.f, 0.f}, {0.f, 0.f}};
#pragma unroll
    for (int fm = 0; fm < 2; fm++) {
#pragma unroll
        for (int fn = 0; fn < 8; fn++) {
            const int gm = mB + wm + fm * 16 + er;
            const int gn = n0 + wn + fn * 8 + ec;
            const float2 bv = *(const float2*)(bias + gn);
            float2 o0, o1;
            o0.x = acc[fm][fn][0] + bv.x; o0.y = acc[fm][fn][1] + bv.y;
            o1.x = acc[fm][fn][2] + bv.x; o1.y = acc[fm][fn][3] + bv.y;
            *(float2*)(C + (size_t)gm * ldc + gn) = o0;
            *(float2*)(C + (size_t)(gm + 8) * ldc + gn) = o1;
            if (smode) {
                const bool m0 = (smode == 2) || ((gn % 48) < 32);
                const bool m1 = (smode == 2) || (((gn + 1) % 48) < 32);
                ssa[fm][0] += (m0 ? o0.x * o0.x : 0.f) + (m1 ? o0.y * o0.y : 0.f);
                ssa[fm][1] += (m0 ? o1.x * o1.x : 0.f) + (m1 ? o1.y * o1.y : 0.f);
            }
        }
    }
    if (smode) {
#pragma unroll
        for (int fm = 0; fm < 2; fm++)
#pragma unroll
            for (int h = 0; h < 2; h++) {
                float v = ssa[fm][h];
                v += __shfl_xor_sync(0xffffffffu, v, 1);
                v += __shfl_xor_sync(0xffffffffu, v, 2);
                if ((lane & 3) == 0)
                    atomicAdd(ss + mB + wm + fm * 16 + er + h * 8, v);
            }
    }
}

// ---------------------------- windowed attention ----------------------------
// smem layout (bytes) — Ds/Ph/Pl ALIAS the Q2/K2 region (dead after QK MMA):
#define Q2_OFF  0u            // 64 x 400  (96 hi + 96 lo halves + pad)
#define K2_OFF  25600u
#define DS_OFF  0u            // 64 x 65 f32 (16640) — aliases Q2
#define PH_OFF  16640u        // 64 x 144  (P hi, 9216)
#define PL_OFF  25856u        // 64 x 144  (P lo, 9216) — ends 35072 < 51200
#define VTH_OFF 51200u        // 48 x 144  (V^T hi only)
#define PS_OFF  58112u        // 225 f32
#define TS_OFF  59012u
#define RV_OFF  59268u
#define RC_OFF  59524u
#define ASMB    59780
__global__ __launch_bounds__(256, 3) void attn_k(const float* __restrict__ pos_emb,
                                                 const float* __restrict__ lamp)
{
    extern __shared__ __align__(128) char smx[];
    float* Ds = (float*)(smx + DS_OFF);
    float* Ps = (float*)(smx + PS_OFF);
    int*   ts = (int*)(smx + TS_OFF);
    float* rv = (float*)(smx + RV_OFF);
    float* rc = (float*)(smx + RC_OFF);

    int blk = blockIdx.x;
    const int wx = blk % NW_; blk /= NW_;
    const int wy = blk % NW_; blk /= NW_;
    const int head = blk % NH_;
    const int b = blk / NH_;
    const int tid = threadIdx.x;

    if (tid < 64) {
        const int ry = tid >> 3, rx = tid & 7;
        const int y = (wy * 8 + ry + 4) % Hh;
        const int x = (wx * 8 + rx + 4) % Wd;
        const int t = b * (Hh * Wd) + y * Wd + x;
        ts[tid] = t;
        rv[tid] = rsqrtf(g_ssv[t] * (1.f / 768.f) + 1e-6f);
        rc[tid] = rsqrtf(g_ssc[t] * (1.f / 768.f) + 1e-6f);
    }
    for (int i = tid; i < 225; i += 256) Ps[i] = pos_emb[i];
    __syncthreads();

    const float lam = lamp[0];
    const int hb = head * 48;

    // ---- Q/K gather: float4 loads, hi/lo split, 8B smem stores ----
    for (int i = tid; i < 64 * 24; i += 256) {
        const int tok = i / 24, u = i - tok * 24;
        const int t = ts[tok];
        float4 qr, kr, gq, gk;
        int ch;
        if (u < 12) {
            ch = u * 4;
            const float* pvr = g_pv + (size_t)t * 1152;
            qr = *(const float4*)(pvr + hb + ch);
            kr = *(const float4*)(pvr + 384 + hb + ch);
            if (u < 8) {
                const float r1 = rv[tok];
                gq = *(const float4*)(g_gvp + hb + ch);
                gk = *(const float4*)(g_gvp + 384 + hb + ch);
                gq.x *= r1; gq.y *= r1; gq.z *= r1; gq.w *= r1;
                gk.x *= r1; gk.y *= r1; gk.z *= r1; gk.w *= r1;
            } else {
                gq = make_float4(1.f, 1.f, 1.f, 1.f);
                gk = gq;
            }
        } else {
            const int c2 = (u - 12) * 4;
            ch = 48 + c2;
            const float* pcr = g_pc + (size_t)t * 768;
            qr = *(const float4*)(pcr + hb + c2);
            kr = *(const float4*)(pcr + 384 + hb + c2);
            const float r2 = rc[tok];
            const float r2l = r2 * lam;
            gq = *(const float4*)(g_gcp + hb + c2);
            gk = *(const float4*)(g_gcp + 384 + hb + c2);
            gq.x *= r2l; gq.y *= r2l; gq.z *= r2l; gq.w *= r2l;
            gk.x *= r2;  gk.y *= r2;  gk.z *= r2;  gk.w *= r2;
        }
        const float q0 = qr.x * gq.x, q1 = qr.y * gq.y, q2 = qr.z * gq.z, q3 = qr.w * gq.w;
        const float k0 = kr.x * gk.x, k1 = kr.y * gk.y, k2 = kr.z * gk.z, k3 = kr.w * gk.w;
        __half qh0 = __float2half_rn(q0), qh1 = __float2half_rn(q1),
               qh2 = __float2half_rn(q2), qh3 = __float2half_rn(q3);
        __half kh0 = __float2half_rn(k0), kh1 = __float2half_rn(k1),
               kh2 = __float2half_rn(k2), kh3 = __float2half_rn(k3);
        uint2 qh = make_uint2(packh(qh0, qh1), packh(qh2, qh3));
        uint2 kh = make_uint2(packh(kh0, kh1), packh(kh2, kh3));
        uint2 ql = make_uint2(
            packh(__float2half_rn(q0 - __half2float(qh0)), __float2half_rn(q1 - __half2float(qh1))),
            packh(__float2half_rn(q2 - __half2float(qh2)), __float2half_rn(q3 - __half2float(qh3))));
        uint2 kl = make_uint2(
            packh(__float2half_rn(k0 - __half2float(kh0)), __float2half_rn(k1 - __half2float(kh1))),
            packh(__float2half_rn(k2 - __half2float(kh2)), __float2half_rn(k3 - __half2float(kh3))));
        char* qrow = smx + Q2_OFF + tok * 400;
        char* krow = smx + K2_OFF + tok * 400;
        *(uint2*)(qrow + ch * 2)       = qh;
        *(uint2*)(qrow + 192 + ch * 2) = ql;
        *(uint2*)(krow + ch * 2)       = kh;
        *(uint2*)(krow + 192 + ch * 2) = kl;
    }
    // ---- V gather: transposed e-major, hi only ----
    {
        __half* vh = (__half*)(smx + VTH_OFF);
        for (int i = tid; i < 64 * 12; i += 256) {
            const int tok = i / 12, u = i - tok * 12;
            const int t = ts[tok];
            const int ch = u * 4;
            float4 raw = *(const float4*)(g_pv + (size_t)t * 1152 + 768 + hb + ch);
            float4 g;
            if (u < 8) {
                const float r1 = rv[tok];
                g = *(const float4*)(g_gvp + 768 + hb + ch);
                g.x *= r1; g.y *= r1; g.z *= r1; g.w *= r1;
            } else g = make_float4(1.f, 1.f, 1.f, 1.f);
            vh[(ch + 0) * 72 + tok] = __float2half_rn(raw.x * g.x);
            vh[(ch + 1) * 72 + tok] = __float2half_rn(raw.y * g.y);
            vh[(ch + 2) * 72 + tok] = __float2half_rn(raw.z * g.z);
            vh[(ch + 3) * 72 + tok] = __float2half_rn(raw.w * g.w);
        }
    }
    __syncthreads();

    // ---- QK^T via HMMA, exact 3-pass fp16 split ----
    const int lane = tid & 31, w = tid >> 5;
    const int wq = w & 3, wk = w >> 2;
    const int q = lane >> 3, tr = lane & 7;
    const uint32_t sQ = s2u(smx + Q2_OFF), sK = s2u(smx + K2_OFF);
    const uint32_t aBase = sQ + (uint32_t)(16 * wq + tr + ((q & 1) << 3)) * 400 + ((q >> 1) << 4);
    uint32_t bBase[2];
    bBase[0] = sK + (uint32_t)(32 * wk + tr + ((q >> 1) << 3)) * 400 + ((q & 1) << 4);
    bBase[1] = bBase[0] + 16 * 400;

    float acc[4][4] = {};
#pragma unroll
    for (int s = 0; s < 18; s++) {
        const int ca = (s < 12) ? s : s - 12;
        const int cb = (s < 6) ? s : s - 6;
        uint32_t a0, a1, a2, a3;
        LDSM4(a0, a1, a2, a3, aBase + ca * 32);
#pragma unroll
        for (int fn = 0; fn < 2; fn++) {
            uint32_t b0, b1, b2, b3;
            LDSM4(b0, b1, b2, b3, bBase[fn] + cb * 32);
            MMA16816(acc[2 * fn],     a0, a1, a2, a3, b0, b1);
            MMA16816(acc[2 * fn + 1], a0, a1, a2, a3, b2, b3);
        }
    }
    __syncthreads();   // Q2/K2 now dead everywhere; safe to write aliased Ds

    const float scale = 0.14433756729740643f;   // 1/sqrt(48)
    const bool lastR = (wy == NW_ - 1), lastC = (wx == NW_ - 1);
#pragma unroll
    for (int f = 0; f < 4; f++) {
#pragma unroll
        for (int r = 0; r < 4; r++) {
            const int i = 16 * wq + (lane >> 2) + ((r >> 1) << 3);
            const int j = 32 * wk + 8 * f + ((lane & 3) << 1) + (r & 1);
            float v = acc[f][r] * scale
                    + Ps[((j >> 3) - (i >> 3) + 7) * 15 + ((j & 7) - (i & 7) + 7)];
            if (lastR && (((i >= 32) ? 1 : 0) ^ ((j >= 32) ? 1 : 0)))           v = -INFINITY;
            if (lastC && ((((i & 7) >= 4) ? 1 : 0) ^ (((j & 7) >= 4) ? 1 : 0))) v = -INFINITY;
            Ds[i * 65 + j] = v;
        }
    }
    __syncthreads();

    // ---- softmax -> P hi/lo fp16 ----
    {
        const int r = tid >> 2, qd = tid & 3;
        float m = -INFINITY;
#pragma unroll
        for (int j = 0; j < 16; j++) m = fmaxf(m, Ds[r * 65 + qd * 16 + j]);
        m = fmaxf(m, __shfl_xor_sync(0xffffffffu, m, 1));
        m = fmaxf(m, __shfl_xor_sync(0xffffffffu, m, 2));
        float ev[16];
        float s = 0.f;
#pragma unroll
        for (int j = 0; j < 16; j++) {
            ev[j] = __expf(Ds[r * 65 + qd * 16 + j] - m);
            s += ev[j];
        }
        s += __shfl_xor_sync(0xffffffffu, s, 1);
        s += __shfl_xor_sync(0xffffffffu, s, 2);
        const float inv = 1.f / s;
        char* PhB = smx + PH_OFF + r * 144 + qd * 32;
        char* PlB = smx + PL_OFF + r * 144 + qd * 32;
#pragma unroll
        for (int j = 0; j < 16; j += 2) {
            const float p0 = ev[j] * inv, p1 = ev[j + 1] * inv;
            const __half h0 = __float2half_rn(p0), h1 = __float2half_rn(p1);
            *(uint32_t*)(PhB + j * 2) = packh(h0, h1);
            *(uint32_t*)(PlB + j * 2) = packh(__float2half_rn(p0 - __half2float(h0)),
                                              __float2half_rn(p1 - __half2float(h1)));
        }
    }
    __syncthreads();

    // ---- AV via HMMA: 2-pass  PhVh + PlVh ----
    const int wq2 = w & 3, wn2 = w >> 2;   // m16 slice, n24 slice
    const uint32_t sPh = s2u(smx + PH_OFF), sPl = s2u(smx + PL_OFF);
    const uint32_t sVh = s2u(smx + VTH_OFF);
    const uint32_t aOff = (uint32_t)(16 * wq2 + tr + ((q & 1) << 3)) * 144 + ((q >> 1) << 4);
    const uint32_t b4Off = (uint32_t)(24 * wn2 + tr + ((q >> 1) << 3)) * 144 + ((q & 1) << 4);
    const int tr2 = lane & 7, q01 = (lane >> 3) & 1;
    const uint32_t b2Off = (uint32_t)(24 * wn2 + 16 + tr2) * 144 + (q01 << 4);

    float acc3[3][4] = {};
#pragma unroll
    for (int p = 0; p < 2; p++) {
        const uint32_t aB = (p == 1 ? sPl : sPh);
#pragma unroll
        for (int ks = 0; ks < 4; ks++) {
            uint32_t a0, a1, a2, a3, b0, b1, b2, b3, b4, b5;
            LDSM4(a0, a1, a2, a3, aB + aOff + ks * 32);
            LDSM4(b0, b1, b2, b3, sVh + b4Off + ks * 32);
            LDSM2(b4, b5, sVh + b2Off + ks * 32);
            MMA16816(acc3[0], a0, a1, a2, a3, b0, b1);
            MMA16816(acc3[1], a0, a1, a2, a3, b2, b3);
            MMA16816(acc3[2], a0, a1, a2, a3, b4, b5);
        }
    }

    // ---- output: hi/lo fp16 split straight to g_Yb ----
    const int er2 = lane >> 2, ec2 = (lane & 3) << 1;
#pragma unroll
    for (int h = 0; h < 2; h++) {
        const int i = 16 * wq2 + er2 + h * 8;
        const int Y = wy * 8 + (i >> 3), X = wx * 8 + (i & 7);
        const size_t t = ((size_t)b * Hh + Y) * Wd + X;
        __half* op = g_Yb + t * 768 + hb;
#pragma unroll
        for (int f = 0; f < 3; f++) {
            const int e = 24 * wn2 + 8 * f + ec2;
            const float v0 = acc3[f][h * 2], v1 = acc3[f][h * 2 + 1];
            const __half h0 = __float2half_rn(v0), h1 = __float2half_rn(v1);
            *(__half2*)(op + e) = __halves2half2(h0, h1);
            *(__half2*)(op + 384 + e) = __halves2half2(
                __float2half_rn(v0 - __half2float(h0)),
                __float2half_rn(v1 - __half2float(h1)));
        }
    }
}

// ------------------------------- launcher -----------------------------------
extern "C" void kernel_launch(void* const* d_in, const int* in_sizes, int n_in,
                              void* d_out, int out_size)
{
    const float* values = (const float*)d_in[0];
    const float* coords = (const float*)d_in[1];
    const float* W_vqk  = (const float*)d_in[2];
    const float* b_vqk  = (const float*)d_in[3];
    const float* gm_vqk = (const float*)d_in[4];
    const float* W_vv   = (const float*)d_in[5];
    const float* b_vv   = (const float*)d_in[6];
    const float* W_cqk  = (const float*)d_in[7];
    const float* b_cqk  = (const float*)d_in[8];
    const float* gm_cqk = (const float*)d_in[9];
    const float* lam    = (const float*)d_in[10];
    const float* pos    = (const float*)d_in[11];
    const float* W_ov   = (const float*)d_in[12];
    const float* b_ov   = (const float*)d_in[13];
    float* out = (float*)d_out;

    __half *Av, *Ac, *Yb, *Bv, *Bc, *Bo;
    float *pv, *pc, *biasv, *biasc, *ssv, *ssc;
    cudaGetSymbolAddress((void**)&Av, g_Av);
    cudaGetSymbolAddress((void**)&Ac, g_Ac);
    cudaGetSymbolAddress((void**)&Yb, g_Yb);
    cudaGetSymbolAddress((void**)&Bv, g_Bv);
    cudaGetSymbolAddress((void**)&Bc, g_Bc);
    cudaGetSymbolAddress((void**)&Bo, g_Bo);
    cudaGetSymbolAddress((void**)&pv, g_pv);
    cudaGetSymbolAddress((void**)&pc, g_pc);
    cudaGetSymbolAddress((void**)&biasv, g_biasv);
    cudaGetSymbolAddress((void**)&biasc, g_biasc);
    cudaGetSymbolAddress((void**)&ssv, g_ssv);
    cudaGetSymbolAddress((void**)&ssc, g_ssc);

    // 1) fused pack + ss-zero + meta permute
    pack_all<<<(int)((T6 + 255) / 256), 256>>>(values, coords, W_vqk, W_vv, W_cqk, W_ov,
                                               b_vqk, b_vv, gm_vqk, b_cqk, gm_cqk);

    const int gsm = 65536;
    cudaFuncSetAttribute(gemm_mma, cudaFuncAttributeMaxDynamicSharedMemorySize, gsm);

    // 2) coords projection, 3) values projection
    gemm_mma<<<dim3(768 / 128,  NTOK / 128), 256, gsm>>>(Ac, Bc, biasc, pc, 256,  768, ssc, 2);
    gemm_mma<<<dim3(1152 / 128, NTOK / 128), 256, gsm>>>(Av, Bv, biasv, pv, 768, 1152, ssv, 1);

    // 4) attention
    cudaFuncSetAttribute(attn_k, cudaFuncAttributeMaxDynamicSharedMemorySize, ASMB);
    attn_k<<<Bb * NH_ * NW_ * NW_, 256, ASMB>>>(pos, lam);

    // 5) output projection
    gemm_mma<<<dim3(384 / 128, NTOK / 128), 256, gsm>>>(Yb, Bo, b_ov, out, 768, 384, nullptr, 0);
}

// round 10
// speedup vs baseline: 1.8952x; 1.1313x over previous
#include <cuda_runtime.h>
#include <cuda_fp16.h>
#include <math.h>
#include <stdint.h>

#define Bb   2
#define Hh   192
#define Wd   192
#define NH_  8
#define HD_  48
#define NW_  24
#define NTOK (Bb*Hh*Wd)   // 73728

// ---------------- scratch (device globals; no runtime alloc) ----------------
__device__ __half g_Av[(size_t)NTOK * 768];    // values split [hi|lo]
__device__ __half g_Ac[(size_t)NTOK * 256];    // coords split
__device__ __half g_Yb[(size_t)NTOK * 384];    // attn out (fp16 hi only)
__device__ __half g_Bv[1152 * 768];            // W' permuted vqk|vv [N, hi|hi]
__device__ __half g_Bc[768 * 256];             // W' permuted cqk
__device__ __half g_Bo[384 * 384];             // W' ov (hi only)
__device__ float g_biasv[1152];
__device__ float g_biasc[768];
__device__ float g_gvp[1152];
__device__ float g_gcp[768];
__device__ float g_pv[(size_t)NTOK * 1152];    // proj out: [Q|K|V] head-major, +bias
__device__ float g_pc[(size_t)NTOK * 768];     // proj out: [Qc|Kc] head-major, +bias
__device__ float g_ssv[NTOK];
__device__ float g_ssc[NTOK];

// ------------------------------ PTX helpers ---------------------------------
__device__ __forceinline__ uint32_t s2u(const void* p) {
    uint32_t a;
    asm("{ .reg .u64 t; cvta.to.shared.u64 t, %1; cvt.u32.u64 %0, t; }" : "=r"(a) : "l"(p));
    return a;
}
__device__ __forceinline__ void cp16(uint32_t dst, const void* src) {
    asm volatile("cp.async.cg.shared.global [%0], [%1], 16;" :: "r"(dst), "l"(src));
}
#define CP_COMMIT() asm volatile("cp.async.commit_group;" ::: "memory")
#define CP_WAIT1()  asm volatile("cp.async.wait_group 1;" ::: "memory")
#define CP_WAIT0()  asm volatile("cp.async.wait_group 0;" ::: "memory")

#define LDSM4(R0,R1,R2,R3,ADDR) \
    asm volatile("ldmatrix.sync.aligned.m8n8.x4.shared.b16 {%0,%1,%2,%3}, [%4];" \
                 : "=r"(R0), "=r"(R1), "=r"(R2), "=r"(R3) : "r"(ADDR))
#define LDSM2(R0,R1,ADDR) \
    asm volatile("ldmatrix.sync.aligned.m8n8.x2.shared.b16 {%0,%1}, [%2];" \
                 : "=r"(R0), "=r"(R1) : "r"(ADDR))

#define MMA16816(D,A0,A1,A2,A3,B0,B1) \
    asm volatile("mma.sync.aligned.m16n8k16.row.col.f32.f16.f16.f32 " \
                 "{%0,%1,%2,%3},{%4,%5,%6,%7},{%8,%9},{%0,%1,%2,%3};" \
                 : "+f"(D[0]), "+f"(D[1]), "+f"(D[2]), "+f"(D[3]) \
                 : "r"(A0), "r"(A1), "r"(A2), "r"(A3), "r"(B0), "r"(B1))

__device__ __forceinline__ uint32_t packh(__half a, __half b) {
    return (uint32_t)__half_as_ushort(a) | ((uint32_t)__half_as_ushort(b) << 16);
}

// ---------------- fused pack + metaperm + ss-zero (1 launch) -----------------
#define T0 ((size_t)NTOK * 384)
#define T1 (T0 + (size_t)NTOK * 128)
#define T2 (T1 + 1152 * 384)
#define T3 (T2 + 768 * 128)
#define T4 (T3 + 384 * 384)
#define T5 (T4 + NTOK)
#define T6 (T5 + 1920)
__global__ void pack_all(const float* __restrict__ values, const float* __restrict__ coords,
                         const float* __restrict__ Wqk, const float* __restrict__ Wvv,
                         const float* __restrict__ Wcqk, const float* __restrict__ Wov,
                         const float* __restrict__ bqk, const float* __restrict__ bvv,
                         const float* __restrict__ gvqk,
                         const float* __restrict__ bcqk, const float* __restrict__ gcqk)
{
    size_t i = (size_t)blockIdx.x * 256 + threadIdx.x;
    if (i < T0) {
        size_t t = i / 384; int k = (int)(i - t * 384);
        float x = values[i];
        __half hi = __float2half_rn(x);
        __half lo = __float2half_rn(x - __half2float(hi));
        __half* row = g_Av + t * 768;
        row[k] = hi; row[384 + k] = lo;
    } else if (i < T1) {
        size_t j = i - T0;
        size_t t = j / 128; int k = (int)(j - t * 128);
        float x = coords[j];
        __half hi = __float2half_rn(x);
        __half lo = __float2half_rn(x - __half2float(hi));
        __half* row = g_Ac + t * 256;
        row[k] = hi; row[128 + k] = lo;
    } else if (i < T2) {                // B_v permuted de-interleave [Q|K|V] head-major
        int j = (int)(i - T1);
        int n = j / 384, k = j - (j / 384) * 384;
        const int blk = n / 384;
        const int hm = (n % 384) / 48, e = n % 48;
        const int c = 3 * (e * 8 + hm) + blk;
        float w = (c < 768) ? Wqk[(size_t)k * 768 + c] : Wvv[(size_t)k * 384 + (c - 768)];
        __half hi = __float2half_rn(w);
        __half* row = g_Bv + (size_t)n * 768;
        row[k] = hi; row[384 + k] = hi;
    } else if (i < T3) {                // B_c permuted [Qc|Kc]
        int j = (int)(i - T2);
        int n = j / 128, k = j - (j / 128) * 128;
        const int blk = n / 384;
        const int hm = (n % 384) / 48, e = n % 48;
        const int c = 2 * (e * 8 + hm) + blk;
        float w = Wcqk[(size_t)k * 768 + c];
        __half hi = __float2half_rn(w);
        __half* row = g_Bc + (size_t)n * 256;
        row[k] = hi; row[128 + k] = hi;
    } else if (i < T4) {                // B_o (hi only, K=384)
        int j = (int)(i - T3);
        int n = j / 384, k = j - (j / 384) * 384;
        g_Bo[(size_t)n * 384 + k] = __float2half_rn(Wov[(size_t)k * 384 + n]);
    } else if (i < T5) {                // ss zero
        const int t = (int)(i - T4);
        g_ssv[t] = 0.f; g_ssc[t] = 0.f;
    } else if (i < T6) {                // bias/gamma permute
        int n = (int)(i - T5);
        if (n < 1152) {
            const int blk = n / 384, hm = (n % 384) / 48, e = n % 48;
            const int c = 3 * (e * 8 + hm) + blk;
            g_biasv[n] = (c < 768) ? bqk[c] : bvv[c - 768];
            g_gvp[n]   = (c < 768) ? gvqk[c] : 1.0f;
        } else {
            const int n2 = n - 1152;
            const int blk = n2 / 384, hm = (n2 % 384) / 48, e = n2 % 48;
            const int c = 2 * (e * 8 + hm) + blk;
            g_biasc[n2] = bcqk[c];
            g_gcp[n2]   = gcqk[c];
        }
    }
}

// --------- HMMA GEMM: C = A'[M,K'] @ B'[N,K']^T + bias; optional ss ---------
// 3-stage cp.async pipeline, ONE __syncthreads per K-chunk.
// smem: A buffers 3x16KB @0, B buffers 3x16KB @49152 -> 96KB dynamic.
__global__ __launch_bounds__(256, 2) void gemm_mma(
    const __half* __restrict__ A, const __half* __restrict__ B,
    const float* __restrict__ bias, float* __restrict__ C, int Kp, int ldc,
    float* __restrict__ ss, int smode)
{
    extern __shared__ __align__(1024) char smem[];
    const uint32_t sb = s2u(smem);
    const int tid = threadIdx.x, lane = tid & 31, wid = tid >> 5;
    const int mB = blockIdx.y * 128, n0 = blockIdx.x * 128;
    const int wm = (wid & 3) << 5;
    const int wn = (wid >> 2) << 6;

    const int lrow = tid >> 3, lu = tid & 7;
    const size_t ldk = (size_t)Kp * 2;
    const char* Asrc = (const char*)A + (size_t)(mB + lrow) * ldk + lu * 16;
    const char* Bsrc = (const char*)B + (size_t)(n0 + lrow) * ldk + lu * 16;
    uint32_t dsto[4];
#pragma unroll
    for (int r = 0; r < 4; r++) {
        const int row = lrow + r * 32;
        dsto[r] = row * 128 + ((lu ^ (row & 7)) << 4);
    }

    const int q = lane >> 3, tr = lane & 7;
    const int qA = q >> 1, qB = q & 1;
    uint32_t rowoffA[2], xrA[2];
#pragma unroll
    for (int fm = 0; fm < 2; fm++) {
        const int row = wm + fm * 16 + tr + ((q & 1) << 3);
        rowoffA[fm] = row * 128; xrA[fm] = row & 7;
    }
    uint32_t rowoffB[4], xrB[4];
#pragma unroll
    for (int fn = 0; fn < 4; fn++) {
        const int row = wn + fn * 16 + tr + ((q >> 1) << 3);
        rowoffB[fn] = row * 128; xrB[fn] = row & 7;
    }

    float acc[2][8][4] = {};

    const int NC = Kp >> 6;
    // prefetch chunks 0 and 1 (separate commit groups)
#pragma unroll
    for (int pc = 0; pc < 2; pc++) {
        if (pc < NC) {
            const uint32_t ab = sb + pc * 16384u;
            const uint32_t bb = sb + 49152u + pc * 16384u;
            const char* An = Asrc + (size_t)pc * 128;
            const char* Bn = Bsrc + (size_t)pc * 128;
#pragma unroll
            for (int r = 0; r < 4; r++) {
                cp16(ab + dsto[r], An + (size_t)r * 32 * ldk);
                cp16(bb + dsto[r], Bn + (size_t)r * 32 * ldk);
            }
            CP_COMMIT();
        }
    }

    int bidx = 0, pidx = 2;
    for (int c = 0; c < NC; c++) {
        if (c + 1 < NC) { CP_WAIT1(); } else { CP_WAIT0(); }
        __syncthreads();
        if (c + 2 < NC) {
            const uint32_t ab = sb + pidx * 16384u;
            const uint32_t bb = sb + 49152u + pidx * 16384u;
            const char* An = Asrc + (size_t)(c + 2) * 128;
            const char* Bn = Bsrc + (size_t)(c + 2) * 128;
#pragma unroll
            for (int r = 0; r < 4; r++) {
                cp16(ab + dsto[r], An + (size_t)r * 32 * ldk);
                cp16(bb + dsto[r], Bn + (size_t)r * 32 * ldk);
            }
            CP_COMMIT();
            if (++pidx == 3) pidx = 0;
        }

        const uint32_t Ab = sb + bidx * 16384u;
        const uint32_t Bs = sb + 49152u + bidx * 16384u;
#pragma unroll
        for (int ks = 0; ks < 4; ks++) {
            uint32_t a[2][4], bf[4][4];
#pragma unroll
            for (int fm = 0; fm < 2; fm++) {
                const uint32_t ad = Ab + rowoffA[fm] + ((((uint32_t)(ks * 2 + qA)) ^ xrA[fm]) << 4);
                LDSM4(a[fm][0], a[fm][1], a[fm][2], a[fm][3], ad);
            }
#pragma unroll
            for (int fn = 0; fn < 4; fn++) {
                const uint32_t bd = Bs + rowoffB[fn] + ((((uint32_t)(ks * 2 + qB)) ^ xrB[fn]) << 4);
                LDSM4(bf[fn][0], bf[fn][1], bf[fn][2], bf[fn][3], bd);
            }
#pragma unroll
            for (int fm = 0; fm < 2; fm++)
#pragma unroll
                for (int fn = 0; fn < 4; fn++) {
                    MMA16816(acc[fm][2 * fn],     a[fm][0], a[fm][1], a[fm][2], a[fm][3],
                             bf[fn][0], bf[fn][1]);
                    MMA16816(acc[fm][2 * fn + 1], a[fm][0], a[fm][1], a[fm][2], a[fm][3],
                             bf[fn][2], bf[fn][3]);
                }
        }
        if (++bidx == 3) bidx = 0;
    }

    const int er = lane >> 2, ec = (lane & 3) << 1;
    float ssa[2][2] = {{0.f, 0.f}, {0.f, 0.f}};
#pragma unroll
    for (int fm = 0; fm < 2; fm++) {
#pragma unroll
        for (int fn = 0; fn < 8; fn++) {
            const int gm = mB + wm + fm * 16 + er;
            const int gn = n0 + wn + fn * 8 + ec;
            const float2 bv = *(const float2*)(bias + gn);
            float2 o0, o1;
            o0.x = acc[fm][fn][0] + bv.x; o0.y = acc[fm][fn][1] + bv.y;
            o1.x = acc[fm][fn][2] + bv.x; o1.y = acc[fm][fn][3] + bv.y;
            *(float2*)(C + (size_t)gm * ldc + gn) = o0;
            *(float2*)(C + (size_t)(gm + 8) * ldc + gn) = o1;
            if (smode) {
                const bool m0 = (smode == 2) || ((gn % 48) < 32);
                const bool m1 = (smode == 2) || (((gn + 1) % 48) < 32);
                ssa[fm][0] += (m0 ? o0.x * o0.x : 0.f) + (m1 ? o0.y * o0.y : 0.f);
                ssa[fm][1] += (m0 ? o1.x * o1.x : 0.f) + (m1 ? o1.y * o1.y : 0.f);
            }
        }
    }
    if (smode) {
#pragma unroll
        for (int fm = 0; fm < 2; fm++)
#pragma unroll
            for (int h = 0; h < 2; h++) {
                float v = ssa[fm][h];
                v += __shfl_xor_sync(0xffffffffu, v, 1);
                v += __shfl_xor_sync(0xffffffffu, v, 2);
                if ((lane & 3) == 0)
                    atomicAdd(ss + mB + wm + fm * 16 + er + h * 8, v);
            }
    }
}

// ---------------------------- windowed attention ----------------------------
// smem layout (bytes) — Ph/Pl ALIAS the Q2 region (dead after QK MMA):
#define Q2_OFF  0u            // 64 x 400  (96 hi + 96 lo halves + pad)
#define K2_OFF  25600u
#define PH_OFF  0u            // 64 x 144  (P hi, 9216) — aliases Q2
#define PL_OFF  9216u         // 64 x 144  (P lo) — ends 18432 < 25600
#define VTH_OFF 51200u        // 48 x 144  (V^T hi only)
#define PS_OFF  58112u        // 225 f32
#define TS_OFF  59012u
#define RV_OFF  59268u
#define RC_OFF  59524u
#define MR_OFF  59780u        // rowred 2 x 64 f32
#define SR_OFF  60292u        // sumred 2 x 64 f32
#define ASMB    60804
__global__ __launch_bounds__(256, 3) void attn_k(const float* __restrict__ pos_emb,
                                                 const float* __restrict__ lamp)
{
    extern __shared__ __align__(128) char smx[];
    float* Ps = (float*)(smx + PS_OFF);
    int*   ts = (int*)(smx + TS_OFF);
    float* rv = (float*)(smx + RV_OFF);
    float* rc = (float*)(smx + RC_OFF);
    float* mred = (float*)(smx + MR_OFF);
    float* sred = (float*)(smx + SR_OFF);

    int blk = blockIdx.x;
    const int wx = blk % NW_; blk /= NW_;
    const int wy = blk % NW_; blk /= NW_;
    const int head = blk % NH_;
    const int b = blk / NH_;
    const int tid = threadIdx.x;

    if (tid < 64) {
        const int ry = tid >> 3, rx = tid & 7;
        const int y = (wy * 8 + ry + 4) % Hh;
        const int x = (wx * 8 + rx + 4) % Wd;
        const int t = b * (Hh * Wd) + y * Wd + x;
        ts[tid] = t;
        rv[tid] = rsqrtf(g_ssv[t] * (1.f / 768.f) + 1e-6f);
        rc[tid] = rsqrtf(g_ssc[t] * (1.f / 768.f) + 1e-6f);
    }
    for (int i = tid; i < 225; i += 256) Ps[i] = pos_emb[i];
    __syncthreads();

    const float lam = lamp[0];
    const int hb = head * 48;

    // ---- Q/K gather: float4 loads, hi/lo split, 8B smem stores ----
    for (int i = tid; i < 64 * 24; i += 256) {
        const int tok = i / 24, u = i - tok * 24;
        const int t = ts[tok];
        float4 qr, kr, gq, gk;
        int ch;
        if (u < 12) {
            ch = u * 4;
            const float* pvr = g_pv + (size_t)t * 1152;
            qr = *(const float4*)(pvr + hb + ch);
            kr = *(const float4*)(pvr + 384 + hb + ch);
            if (u < 8) {
                const float r1 = rv[tok];
                gq = *(const float4*)(g_gvp + hb + ch);
                gk = *(const float4*)(g_gvp + 384 + hb + ch);
                gq.x *= r1; gq.y *= r1; gq.z *= r1; gq.w *= r1;
                gk.x *= r1; gk.y *= r1; gk.z *= r1; gk.w *= r1;
            } else {
                gq = make_float4(1.f, 1.f, 1.f, 1.f);
                gk = gq;
            }
        } else {
            const int c2 = (u - 12) * 4;
            ch = 48 + c2;
            const float* pcr = g_pc + (size_t)t * 768;
            qr = *(const float4*)(pcr + hb + c2);
            kr = *(const float4*)(pcr + 384 + hb + c2);
            const float r2 = rc[tok];
            const float r2l = r2 * lam;
            gq = *(const float4*)(g_gcp + hb + c2);
            gk = *(const float4*)(g_gcp + 384 + hb + c2);
            gq.x *= r2l; gq.y *= r2l; gq.z *= r2l; gq.w *= r2l;
            gk.x *= r2;  gk.y *= r2;  gk.z *= r2;  gk.w *= r2;
        }
        const float q0 = qr.x * gq.x, q1 = qr.y * gq.y, q2 = qr.z * gq.z, q3 = qr.w * gq.w;
        const float k0 = kr.x * gk.x, k1 = kr.y * gk.y, k2 = kr.z * gk.z, k3 = kr.w * gk.w;
        __half qh0 = __float2half_rn(q0), qh1 = __float2half_rn(q1),
               qh2 = __float2half_rn(q2), qh3 = __float2half_rn(q3);
        __half kh0 = __float2half_rn(k0), kh1 = __float2half_rn(k1),
               kh2 = __float2half_rn(k2), kh3 = __float2half_rn(k3);
        uint2 qh = make_uint2(packh(qh0, qh1), packh(qh2, qh3));
        uint2 kh = make_uint2(packh(kh0, kh1), packh(kh2, kh3));
        uint2 ql = make_uint2(
            packh(__float2half_rn(q0 - __half2float(qh0)), __float2half_rn(q1 - __half2float(qh1))),
            packh(__float2half_rn(q2 - __half2float(qh2)), __float2half_rn(q3 - __half2float(qh3))));
        uint2 kl = make_uint2(
            packh(__float2half_rn(k0 - __half2float(kh0)), __float2half_rn(k1 - __half2float(kh1))),
            packh(__float2half_rn(k2 - __half2float(kh2)), __float2half_rn(k3 - __half2float(kh3))));
        char* qrow = smx + Q2_OFF + tok * 400;
        char* krow = smx + K2_OFF + tok * 400;
        *(uint2*)(qrow + ch * 2)       = qh;
        *(uint2*)(qrow + 192 + ch * 2) = ql;
        *(uint2*)(krow + ch * 2)       = kh;
        *(uint2*)(krow + 192 + ch * 2) = kl;
    }
    // ---- V gather: transposed e-major, hi only ----
    {
        __half* vh = (__half*)(smx + VTH_OFF);
        for (int i = tid; i < 64 * 12; i += 256) {
            const int tok = i / 12, u = i - tok * 12;
            const int t = ts[tok];
            const int ch = u * 4;
            float4 raw = *(const float4*)(g_pv + (size_t)t * 1152 + 768 + hb + ch);
            float4 g;
            if (u < 8) {
                const float r1 = rv[tok];
                g = *(const float4*)(g_gvp + 768 + hb + ch);
                g.x *= r1; g.y *= r1; g.z *= r1; g.w *= r1;
            } else g = make_float4(1.f, 1.f, 1.f, 1.f);
            vh[(ch + 0) * 72 + tok] = __float2half_rn(raw.x * g.x);
            vh[(ch + 1) * 72 + tok] = __float2half_rn(raw.y * g.y);
            vh[(ch + 2) * 72 + tok] = __float2half_rn(raw.z * g.z);
            vh[(ch + 3) * 72 + tok] = __float2half_rn(raw.w * g.w);
        }
    }
    __syncthreads();

    // ---- QK^T via HMMA, exact 3-pass fp16 split ----
    const int lane = tid & 31, w = tid >> 5;
    const int wq = w & 3, wk = w >> 2;
    const int q = lane >> 3, tr = lane & 7;
    const uint32_t sQ = s2u(smx + Q2_OFF), sK = s2u(smx + K2_OFF);
    const uint32_t aBase = sQ + (uint32_t)(16 * wq + tr + ((q & 1) << 3)) * 400 + ((q >> 1) << 4);
    uint32_t bBase[2];
    bBase[0] = sK + (uint32_t)(32 * wk + tr + ((q >> 1) << 3)) * 400 + ((q & 1) << 4);
    bBase[1] = bBase[0] + 16 * 400;

    float acc[4][4] = {};
#pragma unroll
    for (int s = 0; s < 18; s++) {
        const int ca = (s < 12) ? s : s - 12;
        const int cb = (s < 6) ? s : s - 6;
        uint32_t a0, a1, a2, a3;
        LDSM4(a0, a1, a2, a3, aBase + ca * 32);
#pragma unroll
        for (int fn = 0; fn < 2; fn++) {
            uint32_t b0, b1, b2, b3;
            LDSM4(b0, b1, b2, b3, bBase[fn] + cb * 32);
            MMA16816(acc[2 * fn],     a0, a1, a2, a3, b0, b1);
            MMA16816(acc[2 * fn + 1], a0, a1, a2, a3, b2, b3);
        }
    }

    // ---- register epilogue: scale + bias + mask; row max via shuffles ----
    const float scale = 0.14433756729740643f;   // 1/sqrt(48)
    const bool lastR = (wy == NW_ - 1), lastC = (wx == NW_ - 1);
    const int i0 = 16 * wq + (lane >> 2);
    const int jbase = 32 * wk + ((lane & 3) << 1);
    float rmax[2] = {-INFINITY, -INFINITY};
#pragma unroll
    for (int f = 0; f < 4; f++) {
#pragma unroll
        for (int r = 0; r < 4; r++) {
            const int i = i0 + ((r >> 1) << 3);
            const int j = jbase + 8 * f + (r & 1);
            float v = acc[f][r] * scale
                    + Ps[((j >> 3) - (i >> 3) + 7) * 15 + ((j & 7) - (i & 7) + 7)];
            if (lastR && (((i >= 32) ? 1 : 0) ^ ((j >= 32) ? 1 : 0)))           v = -INFINITY;
            if (lastC && ((((i & 7) >= 4) ? 1 : 0) ^ (((j & 7) >= 4) ? 1 : 0))) v = -INFINITY;
            acc[f][r] = v;
            rmax[r >> 1] = fmaxf(rmax[r >> 1], v);
        }
    }
#pragma unroll
    for (int h = 0; h < 2; h++) {
        rmax[h] = fmaxf(rmax[h], __shfl_xor_sync(0xffffffffu, rmax[h], 1));
        rmax[h] = fmaxf(rmax[h], __shfl_xor_sync(0xffffffffu, rmax[h], 2));
    }
    if ((lane & 3) == 0) {
        mred[wk * 64 + i0]     = rmax[0];
        mred[wk * 64 + i0 + 8] = rmax[1];
    }
    __syncthreads();
    float gmax[2], rsum[2] = {0.f, 0.f};
    gmax[0] = fmaxf(mred[i0],     mred[64 + i0]);
    gmax[1] = fmaxf(mred[i0 + 8], mred[64 + i0 + 8]);
#pragma unroll
    for (int f = 0; f < 4; f++) {
#pragma unroll
        for (int r = 0; r < 4; r++) {
            const float e = __expf(acc[f][r] - gmax[r >> 1]);
            acc[f][r] = e;
            rsum[r >> 1] += e;
        }
    }
#pragma unroll
    for (int h = 0; h < 2; h++) {
        rsum[h] += __shfl_xor_sync(0xffffffffu, rsum[h], 1);
        rsum[h] += __shfl_xor_sync(0xffffffffu, rsum[h], 2);
    }
    if ((lane & 3) == 0) {
        sred[wk * 64 + i0]     = rsum[0];
        sred[wk * 64 + i0 + 8] = rsum[1];
    }
    __syncthreads();   // also: all QK ldmatrix reads of Q2 done -> Ph/Pl alias safe
    float inv[2];
    inv[0] = 1.f / (sred[i0] + sred[64 + i0]);
    inv[1] = 1.f / (sred[i0 + 8] + sred[64 + i0 + 8]);

    // ---- write P hi/lo straight from registers ----
#pragma unroll
    for (int h = 0; h < 2; h++) {
        const int i = i0 + h * 8;
        char* PhB = smx + PH_OFF + i * 144;
        char* PlB = smx + PL_OFF + i * 144;
#pragma unroll
        for (int f = 0; f < 4; f++) {
            const float p0 = acc[f][h * 2] * inv[h];
            const float p1 = acc[f][h * 2 + 1] * inv[h];
            const __half h0 = __float2half_rn(p0), h1 = __float2half_rn(p1);
            const int off = (jbase + 8 * f) * 2;
            *(uint32_t*)(PhB + off) = packh(h0, h1);
            *(uint32_t*)(PlB + off) = packh(__float2half_rn(p0 - __half2float(h0)),
                                            __float2half_rn(p1 - __half2float(h1)));
        }
    }
    __syncthreads();

    // ---- AV via HMMA: 2-pass  PhVh + PlVh ----
    const int wq2 = w & 3, wn2 = w >> 2;   // m16 slice, n24 slice
    const uint32_t sPh = s2u(smx + PH_OFF), sPl = s2u(smx + PL_OFF);
    const uint32_t sVh = s2u(smx + VTH_OFF);
    const uint32_t aOff = (uint32_t)(16 * wq2 + tr + ((q & 1) << 3)) * 144 + ((q >> 1) << 4);
    const uint32_t b4Off = (uint32_t)(24 * wn2 + tr + ((q >> 1) << 3)) * 144 + ((q & 1) << 4);
    const int tr2 = lane & 7, q01 = (lane >> 3) & 1;
    const uint32_t b2Off = (uint32_t)(24 * wn2 + 16 + tr2) * 144 + (q01 << 4);

    float acc3[3][4] = {};
#pragma unroll
    for (int p = 0; p < 2; p++) {
        const uint32_t aB = (p == 1 ? sPl : sPh);
#pragma unroll
        for (int ks = 0; ks < 4; ks++) {
            uint32_t a0, a1, a2, a3, b0, b1, b2, b3, b4, b5;
            LDSM4(a0, a1, a2, a3, aB + aOff + ks * 32);
            LDSM4(b0, b1, b2, b3, sVh + b4Off + ks * 32);
            LDSM2(b4, b5, sVh + b2Off + ks * 32);
            MMA16816(acc3[0], a0, a1, a2, a3, b0, b1);
            MMA16816(acc3[1], a0, a1, a2, a3, b2, b3);
            MMA16816(acc3[2], a0, a1, a2, a3, b4, b5);
        }
    }

    // ---- output: fp16 hi only -> g_Yb ----
    const int er2 = lane >> 2, ec2 = (lane & 3) << 1;
#pragma unroll
    for (int h = 0; h < 2; h++) {
        const int i = 16 * wq2 + er2 + h * 8;
        const int Y = wy * 8 + (i >> 3), X = wx * 8 + (i & 7);
        const size_t t = ((size_t)b * Hh + Y) * Wd + X;
        __half* op = g_Yb + t * 384 + hb;
#pragma unroll
        for (int f = 0; f < 3; f++) {
            const int e = 24 * wn2 + 8 * f + ec2;
            *(__half2*)(op + e) = __halves2half2(__float2half_rn(acc3[f][h * 2]),
                                                 __float2half_rn(acc3[f][h * 2 + 1]));
        }
    }
}

// ------------------------------- launcher -----------------------------------
extern "C" void kernel_launch(void* const* d_in, const int* in_sizes, int n_in,
                              void* d_out, int out_size)
{
    const float* values = (const float*)d_in[0];
    const float* coords = (const float*)d_in[1];
    const float* W_vqk  = (const float*)d_in[2];
    const float* b_vqk  = (const float*)d_in[3];
    const float* gm_vqk = (const float*)d_in[4];
    const float* W_vv   = (const float*)d_in[5];
    const float* b_vv   = (const float*)d_in[6];
    const float* W_cqk  = (const float*)d_in[7];
    const float* b_cqk  = (const float*)d_in[8];
    const float* gm_cqk = (const float*)d_in[9];
    const float* lam    = (const float*)d_in[10];
    const float* pos    = (const float*)d_in[11];
    const float* W_ov   = (const float*)d_in[12];
    const float* b_ov   = (const float*)d_in[13];
    float* out = (float*)d_out;

    __half *Av, *Ac, *Yb, *Bv, *Bc, *Bo;
    float *pv, *pc, *biasv, *biasc, *ssv, *ssc;
    cudaGetSymbolAddress((void**)&Av, g_Av);
    cudaGetSymbolAddress((void**)&Ac, g_Ac);
    cudaGetSymbolAddress((void**)&Yb, g_Yb);
    cudaGetSymbolAddress((void**)&Bv, g_Bv);
    cudaGetSymbolAddress((void**)&Bc, g_Bc);
    cudaGetSymbolAddress((void**)&Bo, g_Bo);
    cudaGetSymbolAddress((void**)&pv, g_pv);
    cudaGetSymbolAddress((void**)&pc, g_pc);
    cudaGetSymbolAddress((void**)&biasv, g_biasv);
    cudaGetSymbolAddress((void**)&biasc, g_biasc);
    cudaGetSymbolAddress((void**)&ssv, g_ssv);
    cudaGetSymbolAddress((void**)&ssc, g_ssc);

    // 1) fused pack + ss-zero + meta permute
    pack_all<<<(int)((T6 + 255) / 256), 256>>>(values, coords, W_vqk, W_vv, W_cqk, W_ov,
                                               b_vqk, b_vv, gm_vqk, b_cqk, gm_cqk);

    const int gsm = 98304;
    cudaFuncSetAttribute(gemm_mma, cudaFuncAttributeMaxDynamicSharedMemorySize, gsm);

    // 2) coords projection, 3) values projection
    gemm_mma<<<dim3(768 / 128,  NTOK / 128), 256, gsm>>>(Ac, Bc, biasc, pc, 256,  768, ssc, 2);
    gemm_mma<<<dim3(1152 / 128, NTOK / 128), 256, gsm>>>(Av, Bv, biasv, pv, 768, 1152, ssv, 1);

    // 4) attention
    cudaFuncSetAttribute(attn_k, cudaFuncAttributeMaxDynamicSharedMemorySize, ASMB);
    attn_k<<<Bb * NH_ * NW_ * NW_, 256, ASMB>>>(pos, lam);

    // 5) output projection (K halved: fp16 hi-only activations)
    gemm_mma<<<dim3(384 / 128, NTOK / 128), 256, gsm>>>(Yb, Bo, b_ov, out, 384, 384, nullptr, 0);
}

// round 11
// speedup vs baseline: 1.9450x; 1.0263x over previous
#include <cuda_runtime.h>
#include <cuda_fp16.h>
#include <math.h>
#include <stdint.h>

#define Bb   2
#define Hh   192
#define Wd   192
#define NH_  8
#define HD_  48
#define NW_  24
#define NTOK (Bb*Hh*Wd)   // 73728

// ---------------- scratch (device globals; no runtime alloc) ----------------
__device__ __half g_Av[(size_t)NTOK * 768];    // values split [hi|lo]
__device__ __half g_Ac[(size_t)NTOK * 256];    // coords split
__device__ __half g_Yb[(size_t)NTOK * 384];    // attn out (fp16 hi only)
__device__ __half g_Bv[1152 * 768];            // W' permuted+γ-folded vqk|vv
__device__ __half g_Bc[768 * 256];             // W' permuted+γλ-folded cqk
__device__ __half g_Bo[384 * 384];             // W' ov (hi only)
__device__ float g_biasv[1152];                // γ-folded permuted bias
__device__ float g_biasc[768];
__device__ float g_igv[1152];                  // 1/γ (pre-norm recovery)
__device__ float g_igc[768];                   // 1/(γ[λ])
__device__ float g_pv[(size_t)NTOK * 1152];    // proj out: [Q|K|V] head-major, γ-folded, +bias
__device__ float g_pc[(size_t)NTOK * 768];     // proj out: [Qc|Kc], γλ-folded, +bias
__device__ float g_ssv[NTOK];
__device__ float g_ssc[NTOK];

// ------------------------------ PTX helpers ---------------------------------
__device__ __forceinline__ uint32_t s2u(const void* p) {
    uint32_t a;
    asm("{ .reg .u64 t; cvta.to.shared.u64 t, %1; cvt.u32.u64 %0, t; }" : "=r"(a) : "l"(p));
    return a;
}
__device__ __forceinline__ void cp16(uint32_t dst, const void* src) {
    asm volatile("cp.async.cg.shared.global [%0], [%1], 16;" :: "r"(dst), "l"(src));
}
#define CP_COMMIT() asm volatile("cp.async.commit_group;" ::: "memory")
#define CP_WAIT1()  asm volatile("cp.async.wait_group 1;" ::: "memory")
#define CP_WAIT0()  asm volatile("cp.async.wait_group 0;" ::: "memory")

#define LDSM4(R0,R1,R2,R3,ADDR) \
    asm volatile("ldmatrix.sync.aligned.m8n8.x4.shared.b16 {%0,%1,%2,%3}, [%4];" \
                 : "=r"(R0), "=r"(R1), "=r"(R2), "=r"(R3) : "r"(ADDR))
#define LDSM2(R0,R1,ADDR) \
    asm volatile("ldmatrix.sync.aligned.m8n8.x2.shared.b16 {%0,%1}, [%2];" \
                 : "=r"(R0), "=r"(R1) : "r"(ADDR))

#define MMA16816(D,A0,A1,A2,A3,B0,B1) \
    asm volatile("mma.sync.aligned.m16n8k16.row.col.f32.f16.f16.f32 " \
                 "{%0,%1,%2,%3},{%4,%5,%6,%7},{%8,%9},{%0,%1,%2,%3};" \
                 : "+f"(D[0]), "+f"(D[1]), "+f"(D[2]), "+f"(D[3]) \
                 : "r"(A0), "r"(A1), "r"(A2), "r"(A3), "r"(B0), "r"(B1))

__device__ __forceinline__ uint32_t packh(__half a, __half b) {
    return (uint32_t)__half_as_ushort(a) | ((uint32_t)__half_as_ushort(b) << 16);
}

// ---------------- fused pack + metaperm + ss-zero (1 launch) -----------------
#define T0 ((size_t)NTOK * 384)
#define T1 (T0 + (size_t)NTOK * 128)
#define T2 (T1 + 1152 * 384)
#define T3 (T2 + 768 * 128)
#define T4 (T3 + 384 * 384)
#define T5 (T4 + NTOK)
#define T6 (T5 + 1920)
__global__ void pack_all(const float* __restrict__ values, const float* __restrict__ coords,
                         const float* __restrict__ Wqk, const float* __restrict__ Wvv,
                         const float* __restrict__ Wcqk, const float* __restrict__ Wov,
                         const float* __restrict__ bqk, const float* __restrict__ bvv,
                         const float* __restrict__ gvqk,
                         const float* __restrict__ bcqk, const float* __restrict__ gcqk,
                         const float* __restrict__ lamp)
{
    size_t i = (size_t)blockIdx.x * 256 + threadIdx.x;
    if (i < T0) {
        size_t t = i / 384; int k = (int)(i - t * 384);
        float x = values[i];
        __half hi = __float2half_rn(x);
        __half lo = __float2half_rn(x - __half2float(hi));
        __half* row = g_Av + t * 768;
        row[k] = hi; row[384 + k] = lo;
    } else if (i < T1) {
        size_t j = i - T0;
        size_t t = j / 128; int k = (int)(j - t * 128);
        float x = coords[j];
        __half hi = __float2half_rn(x);
        __half lo = __float2half_rn(x - __half2float(hi));
        __half* row = g_Ac + t * 256;
        row[k] = hi; row[128 + k] = lo;
    } else if (i < T2) {                // B_v permuted [Q|K|V] head-major, γ-folded
        int j = (int)(i - T1);
        int n = j / 384, k = j - (j / 384) * 384;
        const int blk = n / 384;
        const int hm = (n % 384) / 48, e = n % 48;
        const int c = 3 * (e * 8 + hm) + blk;
        float w = (c < 768) ? Wqk[(size_t)k * 768 + c] : Wvv[(size_t)k * 384 + (c - 768)];
        const float gf = (c < 768) ? gvqk[c] : 1.0f;
        __half hi = __float2half_rn(w * gf);
        __half* row = g_Bv + (size_t)n * 768;
        row[k] = hi; row[384 + k] = hi;
    } else if (i < T3) {                // B_c permuted [Qc|Kc], γλ-folded
        int j = (int)(i - T2);
        int n = j / 128, k = j - (j / 128) * 128;
        const int blk = n / 384;
        const int hm = (n % 384) / 48, e = n % 48;
        const int c = 2 * (e * 8 + hm) + blk;
        const float gf = gcqk[c] * (blk == 0 ? lamp[0] : 1.0f);
        __half hi = __float2half_rn(Wcqk[(size_t)k * 768 + c] * gf);
        __half* row = g_Bc + (size_t)n * 256;
        row[k] = hi; row[128 + k] = hi;
    } else if (i < T4) {                // B_o (hi only, K=384)
        int j = (int)(i - T3);
        int n = j / 384, k = j - (j / 384) * 384;
        g_Bo[(size_t)n * 384 + k] = __float2half_rn(Wov[(size_t)k * 384 + n]);
    } else if (i < T5) {                // ss zero
        const int t = (int)(i - T4);
        g_ssv[t] = 0.f; g_ssc[t] = 0.f;
    } else if (i < T6) {                // bias + 1/γ permute
        int n = (int)(i - T5);
        if (n < 1152) {
            const int blk = n / 384, hm = (n % 384) / 48, e = n % 48;
            const int c = 3 * (e * 8 + hm) + blk;
            const float gf = (c < 768) ? gvqk[c] : 1.0f;
            g_biasv[n] = ((c < 768) ? bqk[c] : bvv[c - 768]) * gf;
            g_igv[n]   = (gf != 0.f) ? 1.f / gf : 0.f;
        } else {
            const int n2 = n - 1152;
            const int blk = n2 / 384, hm = (n2 % 384) / 48, e = n2 % 48;
            const int c = 2 * (e * 8 + hm) + blk;
            const float gf = gcqk[c] * (blk == 0 ? lamp[0] : 1.0f);
            g_biasc[n2] = bcqk[c] * gf;
            g_igc[n2]   = (gf != 0.f) ? 1.f / gf : 0.f;
        }
    }
}

// --------- HMMA GEMM: C = A'[M,K'] @ B'[N,K']^T + bias; optional ss ---------
// 3-stage cp.async pipeline, ONE __syncthreads per K-chunk.
__global__ __launch_bounds__(256, 2) void gemm_mma(
    const __half* __restrict__ A, const __half* __restrict__ B,
    const float* __restrict__ bias, float* __restrict__ C, int Kp, int ldc,
    float* __restrict__ ss, const float* __restrict__ ig, int smode)
{
    extern __shared__ __align__(1024) char smem[];
    const uint32_t sb = s2u(smem);
    const int tid = threadIdx.x, lane = tid & 31, wid = tid >> 5;
    const int mB = blockIdx.y * 128, n0 = blockIdx.x * 128;
    const int wm = (wid & 3) << 5;
    const int wn = (wid >> 2) << 6;

    const int lrow = tid >> 3, lu = tid & 7;
    const size_t ldk = (size_t)Kp * 2;
    const char* Asrc = (const char*)A + (size_t)(mB + lrow) * ldk + lu * 16;
    const char* Bsrc = (const char*)B + (size_t)(n0 + lrow) * ldk + lu * 16;
    uint32_t dsto[4];
#pragma unroll
    for (int r = 0; r < 4; r++) {
        const int row = lrow + r * 32;
        dsto[r] = row * 128 + ((lu ^ (row & 7)) << 4);
    }

    const int q = lane >> 3, tr = lane & 7;
    const int qA = q >> 1, qB = q & 1;
    uint32_t rowoffA[2], xrA[2];
#pragma unroll
    for (int fm = 0; fm < 2; fm++) {
        const int row = wm + fm * 16 + tr + ((q & 1) << 3);
        rowoffA[fm] = row * 128; xrA[fm] = row & 7;
    }
    uint32_t rowoffB[4], xrB[4];
#pragma unroll
    for (int fn = 0; fn < 4; fn++) {
        const int row = wn + fn * 16 + tr + ((q >> 1) << 3);
        rowoffB[fn] = row * 128; xrB[fn] = row & 7;
    }

    float acc[2][8][4] = {};

    const int NC = Kp >> 6;
#pragma unroll
    for (int pc = 0; pc < 2; pc++) {
        if (pc < NC) {
            const uint32_t ab = sb + pc * 16384u;
            const uint32_t bb = sb + 49152u + pc * 16384u;
            const char* An = Asrc + (size_t)pc * 128;
            const char* Bn = Bsrc + (size_t)pc * 128;
#pragma unroll
            for (int r = 0; r < 4; r++) {
                cp16(ab + dsto[r], An + (size_t)r * 32 * ldk);
                cp16(bb + dsto[r], Bn + (size_t)r * 32 * ldk);
            }
            CP_COMMIT();
        }
    }

    int bidx = 0, pidx = 2;
    for (int c = 0; c < NC; c++) {
        if (c + 1 < NC) { CP_WAIT1(); } else { CP_WAIT0(); }
        __syncthreads();
        if (c + 2 < NC) {
            const uint32_t ab = sb + pidx * 16384u;
            const uint32_t bb = sb + 49152u + pidx * 16384u;
            const char* An = Asrc + (size_t)(c + 2) * 128;
            const char* Bn = Bsrc + (size_t)(c + 2) * 128;
#pragma unroll
            for (int r = 0; r < 4; r++) {
                cp16(ab + dsto[r], An + (size_t)r * 32 * ldk);
                cp16(bb + dsto[r], Bn + (size_t)r * 32 * ldk);
            }
            CP_COMMIT();
            if (++pidx == 3) pidx = 0;
        }

        const uint32_t Ab = sb + bidx * 16384u;
        const uint32_t Bs = sb + 49152u + bidx * 16384u;
#pragma unroll
        for (int ks = 0; ks < 4; ks++) {
            uint32_t a[2][4], bf[4][4];
#pragma unroll
            for (int fm = 0; fm < 2; fm++) {
                const uint32_t ad = Ab + rowoffA[fm] + ((((uint32_t)(ks * 2 + qA)) ^ xrA[fm]) << 4);
                LDSM4(a[fm][0], a[fm][1], a[fm][2], a[fm][3], ad);
            }
#pragma unroll
            for (int fn = 0; fn < 4; fn++) {
                const uint32_t bd = Bs + rowoffB[fn] + ((((uint32_t)(ks * 2 + qB)) ^ xrB[fn]) << 4);
                LDSM4(bf[fn][0], bf[fn][1], bf[fn][2], bf[fn][3], bd);
            }
#pragma unroll
            for (int fm = 0; fm < 2; fm++)
#pragma unroll
                for (int fn = 0; fn < 4; fn++) {
                    MMA16816(acc[fm][2 * fn],     a[fm][0], a[fm][1], a[fm][2], a[fm][3],
                             bf[fn][0], bf[fn][1]);
                    MMA16816(acc[fm][2 * fn + 1], a[fm][0], a[fm][1], a[fm][2], a[fm][3],
                             bf[fn][2], bf[fn][3]);
                }
        }
        if (++bidx == 3) bidx = 0;
    }

    const int er = lane >> 2, ec = (lane & 3) << 1;
    float ssa[2][2] = {{0.f, 0.f}, {0.f, 0.f}};
#pragma unroll
    for (int fm = 0; fm < 2; fm++) {
#pragma unroll
        for (int fn = 0; fn < 8; fn++) {
            const int gm = mB + wm + fm * 16 + er;
            const int gn = n0 + wn + fn * 8 + ec;
            const float2 bv = *(const float2*)(bias + gn);
            float2 o0, o1;
            o0.x = acc[fm][fn][0] + bv.x; o0.y = acc[fm][fn][1] + bv.y;
            o1.x = acc[fm][fn][2] + bv.x; o1.y = acc[fm][fn][3] + bv.y;
            *(float2*)(C + (size_t)gm * ldc + gn) = o0;
            *(float2*)(C + (size_t)(gm + 8) * ldc + gn) = o1;
            if (smode) {
                const float2 iv = *(const float2*)(ig + gn);
                const float p0 = o0.x * iv.x, p1 = o0.y * iv.y;
                const float p2 = o1.x * iv.x, p3 = o1.y * iv.y;
                const bool m0 = (smode == 2) || ((gn % 48) < 32);
                const bool m1 = (smode == 2) || (((gn + 1) % 48) < 32);
                ssa[fm][0] += (m0 ? p0 * p0 : 0.f) + (m1 ? p1 * p1 : 0.f);
                ssa[fm][1] += (m0 ? p2 * p2 : 0.f) + (m1 ? p3 * p3 : 0.f);
            }
        }
    }
    if (smode) {
#pragma unroll
        for (int fm = 0; fm < 2; fm++)
#pragma unroll
            for (int h = 0; h < 2; h++) {
                float v = ssa[fm][h];
                v += __shfl_xor_sync(0xffffffffu, v, 1);
                v += __shfl_xor_sync(0xffffffffu, v, 2);
                if ((lane & 3) == 0)
                    atomicAdd(ss + mB + wm + fm * 16 + er + h * 8, v);
            }
    }
}

// ---------------------------- windowed attention ----------------------------
// smem layout (bytes) — Ph/Pl ALIAS the Q2 region (dead after QK MMA):
#define Q2_OFF  0u
#define K2_OFF  25600u
#define PH_OFF  0u
#define PL_OFF  9216u
#define VTH_OFF 51200u
#define PS_OFF  58112u
#define TS_OFF  59012u
#define RV_OFF  59268u
#define RC_OFF  59524u
#define MR_OFF  59780u
#define SR_OFF  60292u
#define ASMB    60804
__global__ __launch_bounds__(256, 3) void attn_k(const float* __restrict__ pos_emb)
{
    extern __shared__ __align__(128) char smx[];
    float* Ps = (float*)(smx + PS_OFF);
    int*   ts = (int*)(smx + TS_OFF);
    float* rv = (float*)(smx + RV_OFF);
    float* rc = (float*)(smx + RC_OFF);
    float* mred = (float*)(smx + MR_OFF);
    float* sred = (float*)(smx + SR_OFF);

    int blk = blockIdx.x;
    const int wx = blk % NW_; blk /= NW_;
    const int wy = blk % NW_; blk /= NW_;
    const int head = blk % NH_;
    const int b = blk / NH_;
    const int tid = threadIdx.x;

    if (tid < 64) {
        const int ry = tid >> 3, rx = tid & 7;
        const int y = (wy * 8 + ry + 4) % Hh;
        const int x = (wx * 8 + rx + 4) % Wd;
        const int t = b * (Hh * Wd) + y * Wd + x;
        ts[tid] = t;
        rv[tid] = rsqrtf(g_ssv[t] * (1.f / 768.f) + 1e-6f);
        rc[tid] = rsqrtf(g_ssc[t] * (1.f / 768.f) + 1e-6f);
    }
    for (int i = tid; i < 225; i += 256) Ps[i] = pos_emb[i];
    __syncthreads();

    const int hb = head * 48;

    // ---- Q/K gather: γ/λ pre-folded; single per-token scalar f ----
    for (int i = tid; i < 64 * 24; i += 256) {
        const int tok = i / 24, u = i - tok * 24;
        const int t = ts[tok];
        float4 qr, kr;
        float f;
        int ch;
        if (u < 12) {
            ch = u * 4;
            const float* pvr = g_pv + (size_t)t * 1152;
            qr = *(const float4*)(pvr + hb + ch);
            kr = *(const float4*)(pvr + 384 + hb + ch);
            f = (u < 8) ? rv[tok] : 1.f;
        } else {
            const int c2 = (u - 12) * 4;
            ch = 48 + c2;
            const float* pcr = g_pc + (size_t)t * 768;
            qr = *(const float4*)(pcr + hb + c2);
            kr = *(const float4*)(pcr + 384 + hb + c2);
            f = rc[tok];
        }
        const float q0 = qr.x * f, q1 = qr.y * f, q2 = qr.z * f, q3 = qr.w * f;
        const float k0 = kr.x * f, k1 = kr.y * f, k2 = kr.z * f, k3 = kr.w * f;
        __half qh0 = __float2half_rn(q0), qh1 = __float2half_rn(q1),
               qh2 = __float2half_rn(q2), qh3 = __float2half_rn(q3);
        __half kh0 = __float2half_rn(k0), kh1 = __float2half_rn(k1),
               kh2 = __float2half_rn(k2), kh3 = __float2half_rn(k3);
        uint2 qh = make_uint2(packh(qh0, qh1), packh(qh2, qh3));
        uint2 kh = make_uint2(packh(kh0, kh1), packh(kh2, kh3));
        uint2 ql = make_uint2(
            packh(__float2half_rn(q0 - __half2float(qh0)), __float2half_rn(q1 - __half2float(qh1))),
            packh(__float2half_rn(q2 - __half2float(qh2)), __float2half_rn(q3 - __half2float(qh3))));
        uint2 kl = make_uint2(
            packh(__float2half_rn(k0 - __half2float(kh0)), __float2half_rn(k1 - __half2float(kh1))),
            packh(__float2half_rn(k2 - __half2float(kh2)), __float2half_rn(k3 - __half2float(kh3))));
        char* qrow = smx + Q2_OFF + tok * 400;
        char* krow = smx + K2_OFF + tok * 400;
        *(uint2*)(qrow + ch * 2)       = qh;
        *(uint2*)(qrow + 192 + ch * 2) = ql;
        *(uint2*)(krow + ch * 2)       = kh;
        *(uint2*)(krow + 192 + ch * 2) = kl;
    }
    // ---- V gather: transposed e-major, hi only ----
    {
        __half* vh = (__half*)(smx + VTH_OFF);
        for (int i = tid; i < 64 * 12; i += 256) {
            const int tok = i / 12, u = i - tok * 12;
            const int t = ts[tok];
            const int ch = u * 4;
            float4 raw = *(const float4*)(g_pv + (size_t)t * 1152 + 768 + hb + ch);
            const float f = (u < 8) ? rv[tok] : 1.f;
            vh[(ch + 0) * 72 + tok] = __float2half_rn(raw.x * f);
            vh[(ch + 1) * 72 + tok] = __float2half_rn(raw.y * f);
            vh[(ch + 2) * 72 + tok] = __float2half_rn(raw.z * f);
            vh[(ch + 3) * 72 + tok] = __float2half_rn(raw.w * f);
        }
    }
    __syncthreads();

    // ---- QK^T via HMMA, exact 3-pass fp16 split ----
    const int lane = tid & 31, w = tid >> 5;
    const int wq = w & 3, wk = w >> 2;
    const int q = lane >> 3, tr = lane & 7;
    const uint32_t sQ = s2u(smx + Q2_OFF), sK = s2u(smx + K2_OFF);
    const uint32_t aBase = sQ + (uint32_t)(16 * wq + tr + ((q & 1) << 3)) * 400 + ((q >> 1) << 4);
    uint32_t bBase[2];
    bBase[0] = sK + (uint32_t)(32 * wk + tr + ((q >> 1) << 3)) * 400 + ((q & 1) << 4);
    bBase[1] = bBase[0] + 16 * 400;

    float acc[4][4] = {};
#pragma unroll
    for (int s = 0; s < 18; s++) {
        const int ca = (s < 12) ? s : s - 12;
        const int cb = (s < 6) ? s : s - 6;
        uint32_t a0, a1, a2, a3;
        LDSM4(a0, a1, a2, a3, aBase + ca * 32);
#pragma unroll
        for (int fn = 0; fn < 2; fn++) {
            uint32_t b0, b1, b2, b3;
            LDSM4(b0, b1, b2, b3, bBase[fn] + cb * 32);
            MMA16816(acc[2 * fn],     a0, a1, a2, a3, b0, b1);
            MMA16816(acc[2 * fn + 1], a0, a1, a2, a3, b2, b3);
        }
    }

    // ---- register epilogue: scale + bias + mask; row max via shuffles ----
    const float scale = 0.14433756729740643f;   // 1/sqrt(48)
    const bool lastR = (wy == NW_ - 1), lastC = (wx == NW_ - 1);
    const int i0 = 16 * wq + (lane >> 2);
    const int jbase = 32 * wk + ((lane & 3) << 1);
    float rmax[2] = {-INFINITY, -INFINITY};
#pragma unroll
    for (int f = 0; f < 4; f++) {
#pragma unroll
        for (int r = 0; r < 4; r++) {
            const int i = i0 + ((r >> 1) << 3);
            const int j = jbase + 8 * f + (r & 1);
            float v = acc[f][r] * scale
                    + Ps[((j >> 3) - (i >> 3) + 7) * 15 + ((j & 7) - (i & 7) + 7)];
            if (lastR && (((i >= 32) ? 1 : 0) ^ ((j >= 32) ? 1 : 0)))           v = -INFINITY;
            if (lastC && ((((i & 7) >= 4) ? 1 : 0) ^ (((j & 7) >= 4) ? 1 : 0))) v = -INFINITY;
            acc[f][r] = v;
            rmax[r >> 1] = fmaxf(rmax[r >> 1], v);
        }
    }
#pragma unroll
    for (int h = 0; h < 2; h++) {
        rmax[h] = fmaxf(rmax[h], __shfl_xor_sync(0xffffffffu, rmax[h], 1));
        rmax[h] = fmaxf(rmax[h], __shfl_xor_sync(0xffffffffu, rmax[h], 2));
    }
    if ((lane & 3) == 0) {
        mred[wk * 64 + i0]     = rmax[0];
        mred[wk * 64 + i0 + 8] = rmax[1];
    }
    __syncthreads();
    float gmax[2], rsum[2] = {0.f, 0.f};
    gmax[0] = fmaxf(mred[i0],     mred[64 + i0]);
    gmax[1] = fmaxf(mred[i0 + 8], mred[64 + i0 + 8]);
#pragma unroll
    for (int f = 0; f < 4; f++) {
#pragma unroll
        for (int r = 0; r < 4; r++) {
            const float e = __expf(acc[f][r] - gmax[r >> 1]);
            acc[f][r] = e;
            rsum[r >> 1] += e;
        }
    }
#pragma unroll
    for (int h = 0; h < 2; h++) {
        rsum[h] += __shfl_xor_sync(0xffffffffu, rsum[h], 1);
        rsum[h] += __shfl_xor_sync(0xffffffffu, rsum[h], 2);
    }
    if ((lane & 3) == 0) {
        sred[wk * 64 + i0]     = rsum[0];
        sred[wk * 64 + i0 + 8] = rsum[1];
    }
    __syncthreads();   // also: all QK ldmatrix reads of Q2 done -> Ph/Pl alias safe
    float inv[2];
    inv[0] = 1.f / (sred[i0] + sred[64 + i0]);
    inv[1] = 1.f / (sred[i0 + 8] + sred[64 + i0 + 8]);

    // ---- write P hi/lo straight from registers ----
#pragma unroll
    for (int h = 0; h < 2; h++) {
        const int i = i0 + h * 8;
        char* PhB = smx + PH_OFF + i * 144;
        char* PlB = smx + PL_OFF + i * 144;
#pragma unroll
        for (int f = 0; f < 4; f++) {
            const float p0 = acc[f][h * 2] * inv[h];
            const float p1 = acc[f][h * 2 + 1] * inv[h];
            const __half h0 = __float2half_rn(p0), h1 = __float2half_rn(p1);
            const int off = (jbase + 8 * f) * 2;
            *(uint32_t*)(PhB + off) = packh(h0, h1);
            *(uint32_t*)(PlB + off) = packh(__float2half_rn(p0 - __half2float(h0)),
                                            __float2half_rn(p1 - __half2float(h1)));
        }
    }
    __syncthreads();

    // ---- AV via HMMA: 2-pass  PhVh + PlVh ----
    const int wq2 = w & 3, wn2 = w >> 2;
    const uint32_t sPh = s2u(smx + PH_OFF), sPl = s2u(smx + PL_OFF);
    const uint32_t sVh = s2u(smx + VTH_OFF);
    const uint32_t aOff = (uint32_t)(16 * wq2 + tr + ((q & 1) << 3)) * 144 + ((q >> 1) << 4);
    const uint32_t b4Off = (uint32_t)(24 * wn2 + tr + ((q >> 1) << 3)) * 144 + ((q & 1) << 4);
    const int tr2 = lane & 7, q01 = (lane >> 3) & 1;
    const uint32_t b2Off = (uint32_t)(24 * wn2 + 16 + tr2) * 144 + (q01 << 4);

    float acc3[3][4] = {};
#pragma unroll
    for (int p = 0; p < 2; p++) {
        const uint32_t aB = (p == 1 ? sPl : sPh);
#pragma unroll
        for (int ks = 0; ks < 4; ks++) {
            uint32_t a0, a1, a2, a3, b0, b1, b2, b3, b4, b5;
            LDSM4(a0, a1, a2, a3, aB + aOff + ks * 32);
            LDSM4(b0, b1, b2, b3, sVh + b4Off + ks * 32);
            LDSM2(b4, b5, sVh + b2Off + ks * 32);
            MMA16816(acc3[0], a0, a1, a2, a3, b0, b1);
            MMA16816(acc3[1], a0, a1, a2, a3, b2, b3);
            MMA16816(acc3[2], a0, a1, a2, a3, b4, b5);
        }
    }

    // ---- output: fp16 hi only -> g_Yb ----
    const int er2 = lane >> 2, ec2 = (lane & 3) << 1;
#pragma unroll
    for (int h = 0; h < 2; h++) {
        const int i = 16 * wq2 + er2 + h * 8;
        const int Y = wy * 8 + (i >> 3), X = wx * 8 + (i & 7);
        const size_t t = ((size_t)b * Hh + Y) * Wd + X;
        __half* op = g_Yb + t * 384 + hb;
#pragma unroll
        for (int f = 0; f < 3; f++) {
            const int e = 24 * wn2 + 8 * f + ec2;
            *(__half2*)(op + e) = __halves2half2(__float2half_rn(acc3[f][h * 2]),
                                                 __float2half_rn(acc3[f][h * 2 + 1]));
        }
    }
}

// ------------------------------- launcher -----------------------------------
extern "C" void kernel_launch(void* const* d_in, const int* in_sizes, int n_in,
                              void* d_out, int out_size)
{
    const float* values = (const float*)d_in[0];
    const float* coords = (const float*)d_in[1];
    const float* W_vqk  = (const float*)d_in[2];
    const float* b_vqk  = (const float*)d_in[3];
    const float* gm_vqk = (const float*)d_in[4];
    const float* W_vv   = (const float*)d_in[5];
    const float* b_vv   = (const float*)d_in[6];
    const float* W_cqk  = (const float*)d_in[7];
    const float* b_cqk  = (const float*)d_in[8];
    const float* gm_cqk = (const float*)d_in[9];
    const float* lam    = (const float*)d_in[10];
    const float* pos    = (const float*)d_in[11];
    const float* W_ov   = (const float*)d_in[12];
    const float* b_ov   = (const float*)d_in[13];
    float* out = (float*)d_out;

    __half *Av, *Ac, *Yb, *Bv, *Bc, *Bo;
    float *pv, *pc, *biasv, *biasc, *ssv, *ssc, *igv, *igc;
    cudaGetSymbolAddress((void**)&Av, g_Av);
    cudaGetSymbolAddress((void**)&Ac, g_Ac);
    cudaGetSymbolAddress((void**)&Yb, g_Yb);
    cudaGetSymbolAddress((void**)&Bv, g_Bv);
    cudaGetSymbolAddress((void**)&Bc, g_Bc);
    cudaGetSymbolAddress((void**)&Bo, g_Bo);
    cudaGetSymbolAddress((void**)&pv, g_pv);
    cudaGetSymbolAddress((void**)&pc, g_pc);
    cudaGetSymbolAddress((void**)&biasv, g_biasv);
    cudaGetSymbolAddress((void**)&biasc, g_biasc);
    cudaGetSymbolAddress((void**)&ssv, g_ssv);
    cudaGetSymbolAddress((void**)&ssc, g_ssc);
    cudaGetSymbolAddress((void**)&igv, g_igv);
    cudaGetSymbolAddress((void**)&igc, g_igc);

    // 1) fused pack (γ/λ folding) + ss-zero + bias/invγ permute
    pack_all<<<(int)((T6 + 255) / 256), 256>>>(values, coords, W_vqk, W_vv, W_cqk, W_ov,
                                               b_vqk, b_vv, gm_vqk, b_cqk, gm_cqk, lam);

    const int gsm = 98304;
    cudaFuncSetAttribute(gemm_mma, cudaFuncAttributeMaxDynamicSharedMemorySize, gsm);

    // 2) coords projection, 3) values projection
    gemm_mma<<<dim3(768 / 128,  NTOK / 128), 256, gsm>>>(Ac, Bc, biasc, pc, 256,  768, ssc, igc, 2);
    gemm_mma<<<dim3(1152 / 128, NTOK / 128), 256, gsm>>>(Av, Bv, biasv, pv, 768, 1152, ssv, igv, 1);

    // 4) attention
    cudaFuncSetAttribute(attn_k, cudaFuncAttributeMaxDynamicSharedMemorySize, ASMB);
    attn_k<<<Bb * NH_ * NW_ * NW_, 256, ASMB>>>(pos);

    // 5) output projection (fp16 hi-only activations)
    gemm_mma<<<dim3(384 / 128, NTOK / 128), 256, gsm>>>(Yb, Bo, b_ov, out, 384, 384, nullptr, nullptr, 0);
}

// round 12
// speedup vs baseline: 2.4140x; 1.2412x over previous
#include <cuda_runtime.h>
#include <cuda_fp16.h>
#include <math.h>
#include <stdint.h>

#define Bb   2
#define Hh   192
#define Wd   192
#define NH_  8
#define HD_  48
#define NW_  24
#define NTOK (Bb*Hh*Wd)   // 73728

// ---------------- scratch (device globals; no runtime alloc) ----------------
__device__ __half g_Av[(size_t)NTOK * 384];    // values fp16 (hi only)
__device__ __half g_Ac[(size_t)NTOK * 128];    // coords fp16
__device__ __half g_Yb[(size_t)NTOK * 384];    // attn out fp16
__device__ __half g_Bv[1152 * 384];            // W' permuted+γ-folded vqk|vv
__device__ __half g_Bc[768 * 128];             // W' permuted+γλ-folded cqk
__device__ __half g_Bo[384 * 384];             // W' ov
__device__ float g_biasv[1152];                // γ-folded permuted bias
__device__ float g_biasc[768];
__device__ float g_igv[1152];                  // 1/γ (pre-norm recovery)
__device__ float g_igc[768];                   // 1/(γ[λ])
__device__ float g_pv[(size_t)NTOK * 1152];    // proj out: [Q|K|V] head-major, γ-folded, +bias
__device__ float g_pc[(size_t)NTOK * 768];     // proj out: [Qc|Kc], γλ-folded, +bias
__device__ float g_ssv[NTOK];
__device__ float g_ssc[NTOK];

// ------------------------------ PTX helpers ---------------------------------
__device__ __forceinline__ uint32_t s2u(const void* p) {
    uint32_t a;
    asm("{ .reg .u64 t; cvta.to.shared.u64 t, %1; cvt.u32.u64 %0, t; }" : "=r"(a) : "l"(p));
    return a;
}
__device__ __forceinline__ void cp16(uint32_t dst, const void* src) {
    asm volatile("cp.async.cg.shared.global [%0], [%1], 16;" :: "r"(dst), "l"(src));
}
#define CP_COMMIT() asm volatile("cp.async.commit_group;" ::: "memory")
#define CP_WAIT1()  asm volatile("cp.async.wait_group 1;" ::: "memory")
#define CP_WAIT0()  asm volatile("cp.async.wait_group 0;" ::: "memory")

#define LDSM4(R0,R1,R2,R3,ADDR) \
    asm volatile("ldmatrix.sync.aligned.m8n8.x4.shared.b16 {%0,%1,%2,%3}, [%4];" \
                 : "=r"(R0), "=r"(R1), "=r"(R2), "=r"(R3) : "r"(ADDR))
#define LDSM2(R0,R1,ADDR) \
    asm volatile("ldmatrix.sync.aligned.m8n8.x2.shared.b16 {%0,%1}, [%2];" \
                 : "=r"(R0), "=r"(R1) : "r"(ADDR))

#define MMA16816(D,A0,A1,A2,A3,B0,B1) \
    asm volatile("mma.sync.aligned.m16n8k16.row.col.f32.f16.f16.f32 " \
                 "{%0,%1,%2,%3},{%4,%5,%6,%7},{%8,%9},{%0,%1,%2,%3};" \
                 : "+f"(D[0]), "+f"(D[1]), "+f"(D[2]), "+f"(D[3]) \
                 : "r"(A0), "r"(A1), "r"(A2), "r"(A3), "r"(B0), "r"(B1))

__device__ __forceinline__ uint32_t packh(__half a, __half b) {
    return (uint32_t)__half_as_ushort(a) | ((uint32_t)__half_as_ushort(b) << 16);
}

// ---------------- fused pack + metaperm + ss-zero (1 launch) -----------------
#define T0 ((size_t)NTOK * 384)
#define T1 (T0 + (size_t)NTOK * 128)
#define T2 (T1 + 1152 * 384)
#define T3 (T2 + 768 * 128)
#define T4 (T3 + 384 * 384)
#define T5 (T4 + NTOK)
#define T6 (T5 + 1920)
__global__ void pack_all(const float* __restrict__ values, const float* __restrict__ coords,
                         const float* __restrict__ Wqk, const float* __restrict__ Wvv,
                         const float* __restrict__ Wcqk, const float* __restrict__ Wov,
                         const float* __restrict__ bqk, const float* __restrict__ bvv,
                         const float* __restrict__ gvqk,
                         const float* __restrict__ bcqk, const float* __restrict__ gcqk,
                         const float* __restrict__ lamp)
{
    size_t i = (size_t)blockIdx.x * 256 + threadIdx.x;
    if (i < T0) {                       // A_v fp16 (layout-preserving)
        g_Av[i] = __float2half_rn(values[i]);
    } else if (i < T1) {                // A_c fp16
        const size_t j = i - T0;
        g_Ac[j] = __float2half_rn(coords[j]);
    } else if (i < T2) {                // B_v permuted [Q|K|V] head-major, γ-folded
        int j = (int)(i - T1);
        int n = j / 384, k = j - (j / 384) * 384;
        const int blk = n / 384;
        const int hm = (n % 384) / 48, e = n % 48;
        const int c = 3 * (e * 8 + hm) + blk;
        float w = (c < 768) ? Wqk[(size_t)k * 768 + c] : Wvv[(size_t)k * 384 + (c - 768)];
        const float gf = (c < 768) ? gvqk[c] : 1.0f;
        g_Bv[(size_t)n * 384 + k] = __float2half_rn(w * gf);
    } else if (i < T3) {                // B_c permuted [Qc|Kc], γλ-folded
        int j = (int)(i - T2);
        int n = j / 128, k = j - (j / 128) * 128;
        const int blk = n / 384;
        const int hm = (n % 384) / 48, e = n % 48;
        const int c = 2 * (e * 8 + hm) + blk;
        const float gf = gcqk[c] * (blk == 0 ? lamp[0] : 1.0f);
        g_Bc[(size_t)n * 128 + k] = __float2half_rn(Wcqk[(size_t)k * 768 + c] * gf);
    } else if (i < T4) {                // B_o
        int j = (int)(i - T3);
        int n = j / 384, k = j - (j / 384) * 384;
        g_Bo[(size_t)n * 384 + k] = __float2half_rn(Wov[(size_t)k * 384 + n]);
    } else if (i < T5) {                // ss zero
        const int t = (int)(i - T4);
        g_ssv[t] = 0.f; g_ssc[t] = 0.f;
    } else if (i < T6) {                // bias + 1/γ permute
        int n = (int)(i - T5);
        if (n < 1152) {
            const int blk = n / 384, hm = (n % 384) / 48, e = n % 48;
            const int c = 3 * (e * 8 + hm) + blk;
            const float gf = (c < 768) ? gvqk[c] : 1.0f;
            g_biasv[n] = ((c < 768) ? bqk[c] : bvv[c - 768]) * gf;
            g_igv[n]   = (gf != 0.f) ? 1.f / gf : 0.f;
        } else {
            const int n2 = n - 1152;
            const int blk = n2 / 384, hm = (n2 % 384) / 48, e = n2 % 48;
            const int c = 2 * (e * 8 + hm) + blk;
            const float gf = gcqk[c] * (blk == 0 ? lamp[0] : 1.0f);
            g_biasc[n2] = bcqk[c] * gf;
            g_igc[n2]   = (gf != 0.f) ? 1.f / gf : 0.f;
        }
    }
}

// --------- HMMA GEMM: C = A[M,K] @ B[N,K]^T + bias; optional ss -------------
// 3-stage cp.async pipeline, ONE __syncthreads per K-chunk.
__global__ __launch_bounds__(256, 2) void gemm_mma(
    const __half* __restrict__ A, const __half* __restrict__ B,
    const float* __restrict__ bias, float* __restrict__ C, int Kp, int ldc,
    float* __restrict__ ss, const float* __restrict__ ig, int smode)
{
    extern __shared__ __align__(1024) char smem[];
    const uint32_t sb = s2u(smem);
    const int tid = threadIdx.x, lane = tid & 31, wid = tid >> 5;
    const int mB = blockIdx.y * 128, n0 = blockIdx.x * 128;
    const int wm = (wid & 3) << 5;
    const int wn = (wid >> 2) << 6;

    const int lrow = tid >> 3, lu = tid & 7;
    const size_t ldk = (size_t)Kp * 2;
    const char* Asrc = (const char*)A + (size_t)(mB + lrow) * ldk + lu * 16;
    const char* Bsrc = (const char*)B + (size_t)(n0 + lrow) * ldk + lu * 16;
    uint32_t dsto[4];
#pragma unroll
    for (int r = 0; r < 4; r++) {
        const int row = lrow + r * 32;
        dsto[r] = row * 128 + ((lu ^ (row & 7)) << 4);
    }

    const int q = lane >> 3, tr = lane & 7;
    const int qA = q >> 1, qB = q & 1;
    uint32_t rowoffA[2], xrA[2];
#pragma unroll
    for (int fm = 0; fm < 2; fm++) {
        const int row = wm + fm * 16 + tr + ((q & 1) << 3);
        rowoffA[fm] = row * 128; xrA[fm] = row & 7;
    }
    uint32_t rowoffB[4], xrB[4];
#pragma unroll
    for (int fn = 0; fn < 4; fn++) {
        const int row = wn + fn * 16 + tr + ((q >> 1) << 3);
        rowoffB[fn] = row * 128; xrB[fn] = row & 7;
    }

    float acc[2][8][4] = {};

    const int NC = Kp >> 6;
#pragma unroll
    for (int pc = 0; pc < 2; pc++) {
        if (pc < NC) {
            const uint32_t ab = sb + pc * 16384u;
            const uint32_t bb = sb + 49152u + pc * 16384u;
            const char* An = Asrc + (size_t)pc * 128;
            const char* Bn = Bsrc + (size_t)pc * 128;
#pragma unroll
            for (int r = 0; r < 4; r++) {
                cp16(ab + dsto[r], An + (size_t)r * 32 * ldk);
                cp16(bb + dsto[r], Bn + (size_t)r * 32 * ldk);
            }
            CP_COMMIT();
        }
    }

    int bidx = 0, pidx = 2;
    for (int c = 0; c < NC; c++) {
        if (c + 1 < NC) { CP_WAIT1(); } else { CP_WAIT0(); }
        __syncthreads();
        if (c + 2 < NC) {
            const uint32_t ab = sb + pidx * 16384u;
            const uint32_t bb = sb + 49152u + pidx * 16384u;
            const char* An = Asrc + (size_t)(c + 2) * 128;
            const char* Bn = Bsrc + (size_t)(c + 2) * 128;
#pragma unroll
            for (int r = 0; r < 4; r++) {
                cp16(ab + dsto[r], An + (size_t)r * 32 * ldk);
                cp16(bb + dsto[r], Bn + (size_t)r * 32 * ldk);
            }
            CP_COMMIT();
            if (++pidx == 3) pidx = 0;
        }

        const uint32_t Ab = sb + bidx * 16384u;
        const uint32_t Bs = sb + 49152u + bidx * 16384u;
#pragma unroll
        for (int ks = 0; ks < 4; ks++) {
            uint32_t a[2][4], bf[4][4];
#pragma unroll
            for (int fm = 0; fm < 2; fm++) {
                const uint32_t ad = Ab + rowoffA[fm] + ((((uint32_t)(ks * 2 + qA)) ^ xrA[fm]) << 4);
                LDSM4(a[fm][0], a[fm][1], a[fm][2], a[fm][3], ad);
            }
#pragma unroll
            for (int fn = 0; fn < 4; fn++) {
                const uint32_t bd = Bs + rowoffB[fn] + ((((uint32_t)(ks * 2 + qB)) ^ xrB[fn]) << 4);
                LDSM4(bf[fn][0], bf[fn][1], bf[fn][2], bf[fn][3], bd);
            }
#pragma unroll
            for (int fm = 0; fm < 2; fm++)
#pragma unroll
                for (int fn = 0; fn < 4; fn++) {
                    MMA16816(acc[fm][2 * fn],     a[fm][0], a[fm][1], a[fm][2], a[fm][3],
                             bf[fn][0], bf[fn][1]);
                    MMA16816(acc[fm][2 * fn + 1], a[fm][0], a[fm][1], a[fm][2], a[fm][3],
                             bf[fn][2], bf[fn][3]);
                }
        }
        if (++bidx == 3) bidx = 0;
    }

    const int er = lane >> 2, ec = (lane & 3) << 1;
    float ssa[2][2] = {{0.f, 0.f}, {0.f, 0.f}};
#pragma unroll
    for (int fm = 0; fm < 2; fm++) {
#pragma unroll
        for (int fn = 0; fn < 8; fn++) {
            const int gm = mB + wm + fm * 16 + er;
            const int gn = n0 + wn + fn * 8 + ec;
            const float2 bv = *(const float2*)(bias + gn);
            float2 o0, o1;
            o0.x = acc[fm][fn][0] + bv.x; o0.y = acc[fm][fn][1] + bv.y;
            o1.x = acc[fm][fn][2] + bv.x; o1.y = acc[fm][fn][3] + bv.y;
            *(float2*)(C + (size_t)gm * ldc + gn) = o0;
            *(float2*)(C + (size_t)(gm + 8) * ldc + gn) = o1;
            if (smode) {
                const float2 iv = *(const float2*)(ig + gn);
                const float p0 = o0.x * iv.x, p1 = o0.y * iv.y;
                const float p2 = o1.x * iv.x, p3 = o1.y * iv.y;
                const bool m0 = (smode == 2) || ((gn % 48) < 32);
                const bool m1 = (smode == 2) || (((gn + 1) % 48) < 32);
                ssa[fm][0] += (m0 ? p0 * p0 : 0.f) + (m1 ? p1 * p1 : 0.f);
                ssa[fm][1] += (m0 ? p2 * p2 : 0.f) + (m1 ? p3 * p3 : 0.f);
            }
        }
    }
    if (smode) {
#pragma unroll
        for (int fm = 0; fm < 2; fm++)
#pragma unroll
            for (int h = 0; h < 2; h++) {
                float v = ssa[fm][h];
                v += __shfl_xor_sync(0xffffffffu, v, 1);
                v += __shfl_xor_sync(0xffffffffu, v, 2);
                if ((lane & 3) == 0)
                    atomicAdd(ss + mB + wm + fm * 16 + er + h * 8, v);
            }
    }
}

// ---------------------------- windowed attention ----------------------------
// smem layout (bytes) — Ph ALIASES the Q2 region (dead after QK MMA):
#define Q2_OFF  0u
#define K2_OFF  25600u
#define PH_OFF  0u            // 64 x 144 (9216) — aliases Q2
#define VTH_OFF 51200u        // 48 x 144  (V^T hi)
#define PS_OFF  58112u        // 225 f32
#define TS_OFF  59012u
#define RV_OFF  59268u
#define RC_OFF  59524u
#define MR_OFF  59780u
#define SR_OFF  60292u
#define ASMB    60804
__global__ __launch_bounds__(256, 3) void attn_k(const float* __restrict__ pos_emb)
{
    extern __shared__ __align__(128) char smx[];
    float* Ps = (float*)(smx + PS_OFF);
    int*   ts = (int*)(smx + TS_OFF);
    float* rv = (float*)(smx + RV_OFF);
    float* rc = (float*)(smx + RC_OFF);
    float* mred = (float*)(smx + MR_OFF);
    float* sred = (float*)(smx + SR_OFF);

    int blk = blockIdx.x;
    const int wx = blk % NW_; blk /= NW_;
    const int wy = blk % NW_; blk /= NW_;
    const int head = blk % NH_;
    const int b = blk / NH_;
    const int tid = threadIdx.x;

    if (tid < 64) {
        const int ry = tid >> 3, rx = tid & 7;
        const int y = (wy * 8 + ry + 4) % Hh;
        const int x = (wx * 8 + rx + 4) % Wd;
        const int t = b * (Hh * Wd) + y * Wd + x;
        ts[tid] = t;
        rv[tid] = rsqrtf(g_ssv[t] * (1.f / 768.f) + 1e-6f);
        rc[tid] = rsqrtf(g_ssc[t] * (1.f / 768.f) + 1e-6f);
    }
    for (int i = tid; i < 225; i += 256) Ps[i] = pos_emb[i];
    __syncthreads();

    const int hb = head * 48;

    // ---- Q/K gather: γ/λ pre-folded; single per-token scalar f ----
    for (int i = tid; i < 64 * 24; i += 256) {
        const int tok = i / 24, u = i - tok * 24;
        const int t = ts[tok];
        float4 qr, kr;
        float f;
        int ch;
        if (u < 12) {
            ch = u * 4;
            const float* pvr = g_pv + (size_t)t * 1152;
            qr = *(const float4*)(pvr + hb + ch);
            kr = *(const float4*)(pvr + 384 + hb + ch);
            f = (u < 8) ? rv[tok] : 1.f;
        } else {
            const int c2 = (u - 12) * 4;
            ch = 48 + c2;
            const float* pcr = g_pc + (size_t)t * 768;
            qr = *(const float4*)(pcr + hb + c2);
            kr = *(const float4*)(pcr + 384 + hb + c2);
            f = rc[tok];
        }
        const float q0 = qr.x * f, q1 = qr.y * f, q2 = qr.z * f, q3 = qr.w * f;
        const float k0 = kr.x * f, k1 = kr.y * f, k2 = kr.z * f, k3 = kr.w * f;
        __half qh0 = __float2half_rn(q0), qh1 = __float2half_rn(q1),
               qh2 = __float2half_rn(q2), qh3 = __float2half_rn(q3);
        __half kh0 = __float2half_rn(k0), kh1 = __float2half_rn(k1),
               kh2 = __float2half_rn(k2), kh3 = __float2half_rn(k3);
        uint2 qh = make_uint2(packh(qh0, qh1), packh(qh2, qh3));
        uint2 kh = make_uint2(packh(kh0, kh1), packh(kh2, kh3));
        uint2 ql = make_uint2(
            packh(__float2half_rn(q0 - __half2float(qh0)), __float2half_rn(q1 - __half2float(qh1))),
            packh(__float2half_rn(q2 - __half2float(qh2)), __float2half_rn(q3 - __half2float(qh3))));
        uint2 kl = make_uint2(
            packh(__float2half_rn(k0 - __half2float(kh0)), __float2half_rn(k1 - __half2float(kh1))),
            packh(__float2half_rn(k2 - __half2float(kh2)), __float2half_rn(k3 - __half2float(kh3))));
        char* qrow = smx + Q2_OFF + tok * 400;
        char* krow = smx + K2_OFF + tok * 400;
        *(uint2*)(qrow + ch * 2)       = qh;
        *(uint2*)(qrow + 192 + ch * 2) = ql;
        *(uint2*)(krow + ch * 2)       = kh;
        *(uint2*)(krow + 192 + ch * 2) = kl;
    }
    // ---- V gather: transposed e-major, hi only ----
    {
        __half* vh = (__half*)(smx + VTH_OFF);
        for (int i = tid; i < 64 * 12; i += 256) {
            const int tok = i / 12, u = i - tok * 12;
            const int t = ts[tok];
            const int ch = u * 4;
            float4 raw = *(const float4*)(g_pv + (size_t)t * 1152 + 768 + hb + ch);
            const float f = (u < 8) ? rv[tok] : 1.f;
            vh[(ch + 0) * 72 + tok] = __float2half_rn(raw.x * f);
            vh[(ch + 1) * 72 + tok] = __float2half_rn(raw.y * f);
            vh[(ch + 2) * 72 + tok] = __float2half_rn(raw.z * f);
            vh[(ch + 3) * 72 + tok] = __float2half_rn(raw.w * f);
        }
    }
    __syncthreads();

    // ---- QK^T via HMMA, exact 3-pass fp16 split ----
    const int lane = tid & 31, w = tid >> 5;
    const int wq = w & 3, wk = w >> 2;
    const int q = lane >> 3, tr = lane & 7;
    const uint32_t sQ = s2u(smx + Q2_OFF), sK = s2u(smx + K2_OFF);
    const uint32_t aBase = sQ + (uint32_t)(16 * wq + tr + ((q & 1) << 3)) * 400 + ((q >> 1) << 4);
    uint32_t bBase[2];
    bBase[0] = sK + (uint32_t)(32 * wk + tr + ((q >> 1) << 3)) * 400 + ((q & 1) << 4);
    bBase[1] = bBase[0] + 16 * 400;

    float acc[4][4] = {};
#pragma unroll
    for (int s = 0; s < 18; s++) {
        const int ca = (s < 12) ? s : s - 12;
        const int cb = (s < 6) ? s : s - 6;
        uint32_t a0, a1, a2, a3;
        LDSM4(a0, a1, a2, a3, aBase + ca * 32);
#pragma unroll
        for (int fn = 0; fn < 2; fn++) {
            uint32_t b0, b1, b2, b3;
            LDSM4(b0, b1, b2, b3, bBase[fn] + cb * 32);
            MMA16816(acc[2 * fn],     a0, a1, a2, a3, b0, b1);
            MMA16816(acc[2 * fn + 1], a0, a1, a2, a3, b2, b3);
        }
    }

    // ---- register epilogue: scale + bias + mask; row max via shuffles ----
    const float scale = 0.14433756729740643f;   // 1/sqrt(48)
    const bool lastR = (wy == NW_ - 1), lastC = (wx == NW_ - 1);
    const int i0 = 16 * wq + (lane >> 2);
    const int jbase = 32 * wk + ((lane & 3) << 1);
    float rmax[2] = {-INFINITY, -INFINITY};
#pragma unroll
    for (int f = 0; f < 4; f++) {
#pragma unroll
        for (int r = 0; r < 4; r++) {
            const int i = i0 + ((r >> 1) << 3);
            const int j = jbase + 8 * f + (r & 1);
            float v = acc[f][r] * scale
                    + Ps[((j >> 3) - (i >> 3) + 7) * 15 + ((j & 7) - (i & 7) + 7)];
            if (lastR && (((i >= 32) ? 1 : 0) ^ ((j >= 32) ? 1 : 0)))           v = -INFINITY;
            if (lastC && ((((i & 7) >= 4) ? 1 : 0) ^ (((j & 7) >= 4) ? 1 : 0))) v = -INFINITY;
            acc[f][r] = v;
            rmax[r >> 1] = fmaxf(rmax[r >> 1], v);
        }
    }
#pragma unroll
    for (int h = 0; h < 2; h++) {
        rmax[h] = fmaxf(rmax[h], __shfl_xor_sync(0xffffffffu, rmax[h], 1));
        rmax[h] = fmaxf(rmax[h], __shfl_xor_sync(0xffffffffu, rmax[h], 2));
    }
    if ((lane & 3) == 0) {
        mred[wk * 64 + i0]     = rmax[0];
        mred[wk * 64 + i0 + 8] = rmax[1];
    }
    __syncthreads();
    float gmax[2], rsum[2] = {0.f, 0.f};
    gmax[0] = fmaxf(mred[i0],     mred[64 + i0]);
    gmax[1] = fmaxf(mred[i0 + 8], mred[64 + i0 + 8]);
#pragma unroll
    for (int f = 0; f < 4; f++) {
#pragma unroll
        for (int r = 0; r < 4; r++) {
            const float e = __expf(acc[f][r] - gmax[r >> 1]);
            acc[f][r] = e;
            rsum[r >> 1] += e;
        }
    }
#pragma unroll
    for (int h = 0; h < 2; h++) {
        rsum[h] += __shfl_xor_sync(0xffffffffu, rsum[h], 1);
        rsum[h] += __shfl_xor_sync(0xffffffffu, rsum[h], 2);
    }
    if ((lane & 3) == 0) {
        sred[wk * 64 + i0]     = rsum[0];
        sred[wk * 64 + i0 + 8] = rsum[1];
    }
    __syncthreads();   // all QK ldmatrix reads of Q2 done -> Ph alias safe
    float inv[2];
    inv[0] = 1.f / (sred[i0] + sred[64 + i0]);
    inv[1] = 1.f / (sred[i0 + 8] + sred[64 + i0 + 8]);

    // ---- write P (fp16 hi only) straight from registers ----
#pragma unroll
    for (int h = 0; h < 2; h++) {
        const int i = i0 + h * 8;
        char* PhB = smx + PH_OFF + i * 144;
#pragma unroll
        for (int f = 0; f < 4; f++) {
            const float p0 = acc[f][h * 2] * inv[h];
            const float p1 = acc[f][h * 2 + 1] * inv[h];
            *(uint32_t*)(PhB + (jbase + 8 * f) * 2) =
                packh(__float2half_rn(p0), __float2half_rn(p1));
        }
    }
    __syncthreads();

    // ---- AV via HMMA: single pass PhVh ----
    const int wq2 = w & 3, wn2 = w >> 2;
    const uint32_t sPh = s2u(smx + PH_OFF);
    const uint32_t sVh = s2u(smx + VTH_OFF);
    const uint32_t aOff = (uint32_t)(16 * wq2 + tr + ((q & 1) << 3)) * 144 + ((q >> 1) << 4);
    const uint32_t b4Off = (uint32_t)(24 * wn2 + tr + ((q >> 1) << 3)) * 144 + ((q & 1) << 4);
    const int tr2 = lane & 7, q01 = (lane >> 3) & 1;
    const uint32_t b2Off = (uint32_t)(24 * wn2 + 16 + tr2) * 144 + (q01 << 4);

    float acc3[3][4] = {};
#pragma unroll
    for (int ks = 0; ks < 4; ks++) {
        uint32_t a0, a1, a2, a3, b0, b1, b2, b3, b4, b5;
        LDSM4(a0, a1, a2, a3, sPh + aOff + ks * 32);
        LDSM4(b0, b1, b2, b3, sVh + b4Off + ks * 32);
        LDSM2(b4, b5, sVh + b2Off + ks * 32);
        MMA16816(acc3[0], a0, a1, a2, a3, b0, b1);
        MMA16816(acc3[1], a0, a1, a2, a3, b2, b3);
        MMA16816(acc3[2], a0, a1, a2, a3, b4, b5);
    }

    // ---- output: fp16 hi only -> g_Yb ----
    const int er2 = lane >> 2, ec2 = (lane & 3) << 1;
#pragma unroll
    for (int h = 0; h < 2; h++) {
        const int i = 16 * wq2 + er2 + h * 8;
        const int Y = wy * 8 + (i >> 3), X = wx * 8 + (i & 7);
        const size_t t = ((size_t)b * Hh + Y) * Wd + X;
        __half* op = g_Yb + t * 384 + hb;
#pragma unroll
        for (int f = 0; f < 3; f++) {
            const int e = 24 * wn2 + 8 * f + ec2;
            *(__half2*)(op + e) = __halves2half2(__float2half_rn(acc3[f][h * 2]),
                                                 __float2half_rn(acc3[f][h * 2 + 1]));
        }
    }
}

// ------------------------------- launcher -----------------------------------
extern "C" void kernel_launch(void* const* d_in, const int* in_sizes, int n_in,
                              void* d_out, int out_size)
{
    const float* values = (const float*)d_in[0];
    const float* coords = (const float*)d_in[1];
    const float* W_vqk  = (const float*)d_in[2];
    const float* b_vqk  = (const float*)d_in[3];
    const float* gm_vqk = (const float*)d_in[4];
    const float* W_vv   = (const float*)d_in[5];
    const float* b_vv   = (const float*)d_in[6];
    const float* W_cqk  = (const float*)d_in[7];
    const float* b_cqk  = (const float*)d_in[8];
    const float* gm_cqk = (const float*)d_in[9];
    const float* lam    = (const float*)d_in[10];
    const float* pos    = (const float*)d_in[11];
    const float* W_ov   = (const float*)d_in[12];
    const float* b_ov   = (const float*)d_in[13];
    float* out = (float*)d_out;

    __half *Av, *Ac, *Yb, *Bv, *Bc, *Bo;
    float *pv, *pc, *biasv, *biasc, *ssv, *ssc, *igv, *igc;
    cudaGetSymbolAddress((void**)&Av, g_Av);
    cudaGetSymbolAddress((void**)&Ac, g_Ac);
    cudaGetSymbolAddress((void**)&Yb, g_Yb);
    cudaGetSymbolAddress((void**)&Bv, g_Bv);
    cudaGetSymbolAddress((void**)&Bc, g_Bc);
    cudaGetSymbolAddress((void**)&Bo, g_Bo);
    cudaGetSymbolAddress((void**)&pv, g_pv);
    cudaGetSymbolAddress((void**)&pc, g_pc);
    cudaGetSymbolAddress((void**)&biasv, g_biasv);
    cudaGetSymbolAddress((void**)&biasc, g_biasc);
    cudaGetSymbolAddress((void**)&ssv, g_ssv);
    cudaGetSymbolAddress((void**)&ssc, g_ssc);
    cudaGetSymbolAddress((void**)&igv, g_igv);
    cudaGetSymbolAddress((void**)&igc, g_igc);

    // 1) fused pack (γ/λ folding) + ss-zero + bias/invγ permute
    pack_all<<<(int)((T6 + 255) / 256), 256>>>(values, coords, W_vqk, W_vv, W_cqk, W_ov,
                                               b_vqk, b_vv, gm_vqk, b_cqk, gm_cqk, lam);

    const int gsm = 98304;
    cudaFuncSetAttribute(gemm_mma, cudaFuncAttributeMaxDynamicSharedMemorySize, gsm);

    // 2) coords projection (K=128), 3) values projection (K=384)
    gemm_mma<<<dim3(768 / 128,  NTOK / 128), 256, gsm>>>(Ac, Bc, biasc, pc, 128,  768, ssc, igc, 2);
    gemm_mma<<<dim3(1152 / 128, NTOK / 128), 256, gsm>>>(Av, Bv, biasv, pv, 384, 1152, ssv, igv, 1);

    // 4) attention
    cudaFuncSetAttribute(attn_k, cudaFuncAttributeMaxDynamicSharedMemorySize, ASMB);
    attn_k<<<Bb * NH_ * NW_ * NW_, 256, ASMB>>>(pos);

    // 5) output projection (K=384)
    gemm_mma<<<dim3(384 / 128, NTOK / 128), 256, gsm>>>(Yb, Bo, b_ov, out, 384, 384, nullptr, nullptr, 0);
}

// round 13
// speedup vs baseline: 2.6883x; 1.1136x over previous
#include <cuda_runtime.h>
#include <cuda_fp16.h>
#include <math.h>
#include <stdint.h>

#define Bb   2
#define Hh   192
#define Wd   192
#define NH_  8
#define HD_  48
#define NW_  24
#define NTOK (Bb*Hh*Wd)   // 73728

// ---------------- scratch (device globals; no runtime alloc) ----------------
__device__ __half g_Av[(size_t)NTOK * 384];    // values fp16
__device__ __half g_Ac[(size_t)NTOK * 128];    // coords fp16
__device__ __half g_Yb[(size_t)NTOK * 384];    // attn out fp16
__device__ __half g_Bv[1152 * 384];            // W' permuted+γ-folded vqk|vv
__device__ __half g_Bc[768 * 128];             // W' permuted+γλ-folded cqk
__device__ __half g_Bo[384 * 384];             // W' ov
__device__ float g_biasv[1152];                // γ-folded permuted bias
__device__ float g_biasc[768];
__device__ float g_igv[1152];                  // 1/γ (pre-norm recovery)
__device__ float g_igc[768];                   // 1/(γ[λ])
__device__ float g_pv[(size_t)NTOK * 1152];    // proj out: [Q|K|V] head-major, γ-folded, +bias
__device__ float g_pc[(size_t)NTOK * 768];     // proj out: [Qc|Kc], γλ-folded, +bias
__device__ float g_ssv[NTOK];
__device__ float g_ssc[NTOK];

// ------------------------------ PTX helpers ---------------------------------
__device__ __forceinline__ uint32_t s2u(const void* p) {
    uint32_t a;
    asm("{ .reg .u64 t; cvta.to.shared.u64 t, %1; cvt.u32.u64 %0, t; }" : "=r"(a) : "l"(p));
    return a;
}
__device__ __forceinline__ void cp16(uint32_t dst, const void* src) {
    asm volatile("cp.async.cg.shared.global [%0], [%1], 16;" :: "r"(dst), "l"(src));
}
#define CP_COMMIT() asm volatile("cp.async.commit_group;" ::: "memory")
#define CP_WAIT1()  asm volatile("cp.async.wait_group 1;" ::: "memory")
#define CP_WAIT0()  asm volatile("cp.async.wait_group 0;" ::: "memory")

#define LDSM4(R0,R1,R2,R3,ADDR) \
    asm volatile("ldmatrix.sync.aligned.m8n8.x4.shared.b16 {%0,%1,%2,%3}, [%4];" \
                 : "=r"(R0), "=r"(R1), "=r"(R2), "=r"(R3) : "r"(ADDR))
#define LDSM2(R0,R1,ADDR) \
    asm volatile("ldmatrix.sync.aligned.m8n8.x2.shared.b16 {%0,%1}, [%2];" \
                 : "=r"(R0), "=r"(R1) : "r"(ADDR))

#define MMA16816(D,A0,A1,A2,A3,B0,B1) \
    asm volatile("mma.sync.aligned.m16n8k16.row.col.f32.f16.f16.f32 " \
                 "{%0,%1,%2,%3},{%4,%5,%6,%7},{%8,%9},{%0,%1,%2,%3};" \
                 : "+f"(D[0]), "+f"(D[1]), "+f"(D[2]), "+f"(D[3]) \
                 : "r"(A0), "r"(A1), "r"(A2), "r"(A3), "r"(B0), "r"(B1))

__device__ __forceinline__ uint32_t packh(__half a, __half b) {
    return (uint32_t)__half_as_ushort(a) | ((uint32_t)__half_as_ushort(b) << 16);
}

// ---------------- fused pack + metaperm + ss-zero (1 launch) -----------------
#define T0 ((size_t)NTOK * 384)
#define T1 (T0 + (size_t)NTOK * 128)
#define T2 (T1 + 1152 * 384)
#define T3 (T2 + 768 * 128)
#define T4 (T3 + 384 * 384)
#define T5 (T4 + NTOK)
#define T6 (T5 + 1920)
__global__ void pack_all(const float* __restrict__ values, const float* __restrict__ coords,
                         const float* __restrict__ Wqk, const float* __restrict__ Wvv,
                         const float* __restrict__ Wcqk, const float* __restrict__ Wov,
                         const float* __restrict__ bqk, const float* __restrict__ bvv,
                         const float* __restrict__ gvqk,
                         const float* __restrict__ bcqk, const float* __restrict__ gcqk,
                         const float* __restrict__ lamp)
{
    size_t i = (size_t)blockIdx.x * 256 + threadIdx.x;
    if (i < T0) {                       // A_v fp16 (layout-preserving)
        g_Av[i] = __float2half_rn(values[i]);
    } else if (i < T1) {                // A_c fp16
        const size_t j = i - T0;
        g_Ac[j] = __float2half_rn(coords[j]);
    } else if (i < T2) {                // B_v permuted [Q|K|V] head-major, γ-folded
        int j = (int)(i - T1);
        int n = j / 384, k = j - (j / 384) * 384;
        const int blk = n / 384;
        const int hm = (n % 384) / 48, e = n % 48;
        const int c = 3 * (e * 8 + hm) + blk;
        float w = (c < 768) ? Wqk[(size_t)k * 768 + c] : Wvv[(size_t)k * 384 + (c - 768)];
        const float gf = (c < 768) ? gvqk[c] : 1.0f;
        g_Bv[(size_t)n * 384 + k] = __float2half_rn(w * gf);
    } else if (i < T3) {                // B_c permuted [Qc|Kc], γλ-folded
        int j = (int)(i - T2);
        int n = j / 128, k = j - (j / 128) * 128;
        const int blk = n / 384;
        const int hm = (n % 384) / 48, e = n % 48;
        const int c = 2 * (e * 8 + hm) + blk;
        const float gf = gcqk[c] * (blk == 0 ? lamp[0] : 1.0f);
        g_Bc[(size_t)n * 128 + k] = __float2half_rn(Wcqk[(size_t)k * 768 + c] * gf);
    } else if (i < T4) {                // B_o
        int j = (int)(i - T3);
        int n = j / 384, k = j - (j / 384) * 384;
        g_Bo[(size_t)n * 384 + k] = __float2half_rn(Wov[(size_t)k * 384 + n]);
    } else if (i < T5) {                // ss zero
        const int t = (int)(i - T4);
        g_ssv[t] = 0.f; g_ssc[t] = 0.f;
    } else if (i < T6) {                // bias + 1/γ permute
        int n = (int)(i - T5);
        if (n < 1152) {
            const int blk = n / 384, hm = (n % 384) / 48, e = n % 48;
            const int c = 3 * (e * 8 + hm) + blk;
            const float gf = (c < 768) ? gvqk[c] : 1.0f;
            g_biasv[n] = ((c < 768) ? bqk[c] : bvv[c - 768]) * gf;
            g_igv[n]   = (gf != 0.f) ? 1.f / gf : 0.f;
        } else {
            const int n2 = n - 1152;
            const int blk = n2 / 384, hm = (n2 % 384) / 48, e = n2 % 48;
            const int c = 2 * (e * 8 + hm) + blk;
            const float gf = gcqk[c] * (blk == 0 ? lamp[0] : 1.0f);
            g_biasc[n2] = bcqk[c] * gf;
            g_igc[n2]   = (gf != 0.f) ? 1.f / gf : 0.f;
        }
    }
}

// --------- HMMA GEMM: C = A[M,K] @ B[N,K]^T + bias; optional ss -------------
// 3-stage cp.async pipeline, ONE __syncthreads per K-chunk.
__global__ __launch_bounds__(256, 2) void gemm_mma(
    const __half* __restrict__ A, const __half* __restrict__ B,
    const float* __restrict__ bias, float* __restrict__ C, int Kp, int ldc,
    float* __restrict__ ss, const float* __restrict__ ig, int smode)
{
    extern __shared__ __align__(1024) char smem[];
    const uint32_t sb = s2u(smem);
    const int tid = threadIdx.x, lane = tid & 31, wid = tid >> 5;
    const int mB = blockIdx.y * 128, n0 = blockIdx.x * 128;
    const int wm = (wid & 3) << 5;
    const int wn = (wid >> 2) << 6;

    const int lrow = tid >> 3, lu = tid & 7;
    const size_t ldk = (size_t)Kp * 2;
    const char* Asrc = (const char*)A + (size_t)(mB + lrow) * ldk + lu * 16;
    const char* Bsrc = (const char*)B + (size_t)(n0 + lrow) * ldk + lu * 16;
    uint32_t dsto[4];
#pragma unroll
    for (int r = 0; r < 4; r++) {
        const int row = lrow + r * 32;
        dsto[r] = row * 128 + ((lu ^ (row & 7)) << 4);
    }

    const int q = lane >> 3, tr = lane & 7;
    const int qA = q >> 1, qB = q & 1;
    uint32_t rowoffA[2], xrA[2];
#pragma unroll
    for (int fm = 0; fm < 2; fm++) {
        const int row = wm + fm * 16 + tr + ((q & 1) << 3);
        rowoffA[fm] = row * 128; xrA[fm] = row & 7;
    }
    uint32_t rowoffB[4], xrB[4];
#pragma unroll
    for (int fn = 0; fn < 4; fn++) {
        const int row = wn + fn * 16 + tr + ((q >> 1) << 3);
        rowoffB[fn] = row * 128; xrB[fn] = row & 7;
    }

    float acc[2][8][4] = {};

    const int NC = Kp >> 6;
#pragma unroll
    for (int pc = 0; pc < 2; pc++) {
        if (pc < NC) {
            const uint32_t ab = sb + pc * 16384u;
            const uint32_t bb = sb + 49152u + pc * 16384u;
            const char* An = Asrc + (size_t)pc * 128;
            const char* Bn = Bsrc + (size_t)pc * 128;
#pragma unroll
            for (int r = 0; r < 4; r++) {
                cp16(ab + dsto[r], An + (size_t)r * 32 * ldk);
                cp16(bb + dsto[r], Bn + (size_t)r * 32 * ldk);
            }
            CP_COMMIT();
        }
    }

    int bidx = 0, pidx = 2;
    for (int c = 0; c < NC; c++) {
        if (c + 1 < NC) { CP_WAIT1(); } else { CP_WAIT0(); }
        __syncthreads();
        if (c + 2 < NC) {
            const uint32_t ab = sb + pidx * 16384u;
            const uint32_t bb = sb + 49152u + pidx * 16384u;
            const char* An = Asrc + (size_t)(c + 2) * 128;
            const char* Bn = Bsrc + (size_t)(c + 2) * 128;
#pragma unroll
            for (int r = 0; r < 4; r++) {
                cp16(ab + dsto[r], An + (size_t)r * 32 * ldk);
                cp16(bb + dsto[r], Bn + (size_t)r * 32 * ldk);
            }
            CP_COMMIT();
            if (++pidx == 3) pidx = 0;
        }

        const uint32_t Ab = sb + bidx * 16384u;
        const uint32_t Bs = sb + 49152u + bidx * 16384u;
#pragma unroll
        for (int ks = 0; ks < 4; ks++) {
            uint32_t a[2][4], bf[4][4];
#pragma unroll
            for (int fm = 0; fm < 2; fm++) {
                const uint32_t ad = Ab + rowoffA[fm] + ((((uint32_t)(ks * 2 + qA)) ^ xrA[fm]) << 4);
                LDSM4(a[fm][0], a[fm][1], a[fm][2], a[fm][3], ad);
            }
#pragma unroll
            for (int fn = 0; fn < 4; fn++) {
                const uint32_t bd = Bs + rowoffB[fn] + ((((uint32_t)(ks * 2 + qB)) ^ xrB[fn]) << 4);
                LDSM4(bf[fn][0], bf[fn][1], bf[fn][2], bf[fn][3], bd);
            }
#pragma unroll
            for (int fm = 0; fm < 2; fm++)
#pragma unroll
                for (int fn = 0; fn < 4; fn++) {
                    MMA16816(acc[fm][2 * fn],     a[fm][0], a[fm][1], a[fm][2], a[fm][3],
                             bf[fn][0], bf[fn][1]);
                    MMA16816(acc[fm][2 * fn + 1], a[fm][0], a[fm][1], a[fm][2], a[fm][3],
                             bf[fn][2], bf[fn][3]);
                }
        }
        if (++bidx == 3) bidx = 0;
    }

    const int er = lane >> 2, ec = (lane & 3) << 1;
    float ssa[2][2] = {{0.f, 0.f}, {0.f, 0.f}};
#pragma unroll
    for (int fm = 0; fm < 2; fm++) {
#pragma unroll
        for (int fn = 0; fn < 8; fn++) {
            const int gm = mB + wm + fm * 16 + er;
            const int gn = n0 + wn + fn * 8 + ec;
            const float2 bv = *(const float2*)(bias + gn);
            float2 o0, o1;
            o0.x = acc[fm][fn][0] + bv.x; o0.y = acc[fm][fn][1] + bv.y;
            o1.x = acc[fm][fn][2] + bv.x; o1.y = acc[fm][fn][3] + bv.y;
            *(float2*)(C + (size_t)gm * ldc + gn) = o0;
            *(float2*)(C + (size_t)(gm + 8) * ldc + gn) = o1;
            if (smode) {
                const float2 iv = *(const float2*)(ig + gn);
                const float p0 = o0.x * iv.x, p1 = o0.y * iv.y;
                const float p2 = o1.x * iv.x, p3 = o1.y * iv.y;
                const bool m0 = (smode == 2) || ((gn % 48) < 32);
                const bool m1 = (smode == 2) || (((gn + 1) % 48) < 32);
                ssa[fm][0] += (m0 ? p0 * p0 : 0.f) + (m1 ? p1 * p1 : 0.f);
                ssa[fm][1] += (m0 ? p2 * p2 : 0.f) + (m1 ? p3 * p3 : 0.f);
            }
        }
    }
    if (smode) {
#pragma unroll
        for (int fm = 0; fm < 2; fm++)
#pragma unroll
            for (int h = 0; h < 2; h++) {
                float v = ssa[fm][h];
                v += __shfl_xor_sync(0xffffffffu, v, 1);
                v += __shfl_xor_sync(0xffffffffu, v, 2);
                if ((lane & 3) == 0)
                    atomicAdd(ss + mB + wm + fm * 16 + er + h * 8, v);
            }
    }
}

// ---------------------------- windowed attention ----------------------------
// Q,K,P,V all fp16 (hi only). smem (bytes); Ph ALIASES Q2 (dead after QK MMA):
#define Q2_OFF  0u            // 64 x 208 (96 halves + pad)  13312
#define K2_OFF  13312u        // 13312
#define PH_OFF  0u            // 64 x 144 (9216) — aliases Q2
#define VTH_OFF 26624u        // 48 x 144 (6912)
#define PS_OFF  33536u        // 225 f32
#define TS_OFF  34436u
#define RV_OFF  34692u
#define RC_OFF  34948u
#define MR_OFF  35204u
#define SR_OFF  35716u
#define ASMB    36228
__global__ __launch_bounds__(256, 4) void attn_k(const float* __restrict__ pos_emb)
{
    extern __shared__ __align__(128) char smx[];
    float* Ps = (float*)(smx + PS_OFF);
    int*   ts = (int*)(smx + TS_OFF);
    float* rv = (float*)(smx + RV_OFF);
    float* rc = (float*)(smx + RC_OFF);
    float* mred = (float*)(smx + MR_OFF);
    float* sred = (float*)(smx + SR_OFF);

    int blk = blockIdx.x;
    const int wx = blk % NW_; blk /= NW_;
    const int wy = blk % NW_; blk /= NW_;
    const int head = blk % NH_;
    const int b = blk / NH_;
    const int tid = threadIdx.x;

    if (tid < 64) {
        const int ry = tid >> 3, rx = tid & 7;
        const int y = (wy * 8 + ry + 4) % Hh;
        const int x = (wx * 8 + rx + 4) % Wd;
        const int t = b * (Hh * Wd) + y * Wd + x;
        ts[tid] = t;
        rv[tid] = rsqrtf(g_ssv[t] * (1.f / 768.f) + 1e-6f);
        rc[tid] = rsqrtf(g_ssc[t] * (1.f / 768.f) + 1e-6f);
    }
    for (int i = tid; i < 225; i += 256) Ps[i] = pos_emb[i];
    __syncthreads();

    const int hb = head * 48;

    // ---- Q/K gather: fp16 hi only ----
    for (int i = tid; i < 64 * 24; i += 256) {
        const int tok = i / 24, u = i - tok * 24;
        const int t = ts[tok];
        float4 qr, kr;
        float f;
        int ch;
        if (u < 12) {
            ch = u * 4;
            const float* pvr = g_pv + (size_t)t * 1152;
            qr = *(const float4*)(pvr + hb + ch);
            kr = *(const float4*)(pvr + 384 + hb + ch);
            f = (u < 8) ? rv[tok] : 1.f;
        } else {
            const int c2 = (u - 12) * 4;
            ch = 48 + c2;
            const float* pcr = g_pc + (size_t)t * 768;
            qr = *(const float4*)(pcr + hb + c2);
            kr = *(const float4*)(pcr + 384 + hb + c2);
            f = rc[tok];
        }
        uint2 qh = make_uint2(
            packh(__float2half_rn(qr.x * f), __float2half_rn(qr.y * f)),
            packh(__float2half_rn(qr.z * f), __float2half_rn(qr.w * f)));
        uint2 kh = make_uint2(
            packh(__float2half_rn(kr.x * f), __float2half_rn(kr.y * f)),
            packh(__float2half_rn(kr.z * f), __float2half_rn(kr.w * f)));
        *(uint2*)(smx + Q2_OFF + tok * 208 + ch * 2) = qh;
        *(uint2*)(smx + K2_OFF + tok * 208 + ch * 2) = kh;
    }
    // ---- V gather: transposed e-major, fp16 ----
    {
        __half* vh = (__half*)(smx + VTH_OFF);
        for (int i = tid; i < 64 * 12; i += 256) {
            const int tok = i / 12, u = i - tok * 12;
            const int t = ts[tok];
            const int ch = u * 4;
            float4 raw = *(const float4*)(g_pv + (size_t)t * 1152 + 768 + hb + ch);
            const float f = (u < 8) ? rv[tok] : 1.f;
            vh[(ch + 0) * 72 + tok] = __float2half_rn(raw.x * f);
            vh[(ch + 1) * 72 + tok] = __float2half_rn(raw.y * f);
            vh[(ch + 2) * 72 + tok] = __float2half_rn(raw.z * f);
            vh[(ch + 3) * 72 + tok] = __float2half_rn(raw.w * f);
        }
    }
    __syncthreads();

    // ---- QK^T via HMMA: 6 k16 steps ----
    const int lane = tid & 31, w = tid >> 5;
    const int wq = w & 3, wk = w >> 2;
    const int q = lane >> 3, tr = lane & 7;
    const uint32_t sQ = s2u(smx + Q2_OFF), sK = s2u(smx + K2_OFF);
    const uint32_t aBase = sQ + (uint32_t)(16 * wq + tr + ((q & 1) << 3)) * 208 + ((q >> 1) << 4);
    uint32_t bBase[2];
    bBase[0] = sK + (uint32_t)(32 * wk + tr + ((q >> 1) << 3)) * 208 + ((q & 1) << 4);
    bBase[1] = bBase[0] + 16 * 208;

    float acc[4][4] = {};
#pragma unroll
    for (int s = 0; s < 6; s++) {
        uint32_t a0, a1, a2, a3;
        LDSM4(a0, a1, a2, a3, aBase + s * 32);
#pragma unroll
        for (int fn = 0; fn < 2; fn++) {
            uint32_t b0, b1, b2, b3;
            LDSM4(b0, b1, b2, b3, bBase[fn] + s * 32);
            MMA16816(acc[2 * fn],     a0, a1, a2, a3, b0, b1);
            MMA16816(acc[2 * fn + 1], a0, a1, a2, a3, b2, b3);
        }
    }

    // ---- register epilogue: scale + bias + mask; row max via shuffles ----
    const float scale = 0.14433756729740643f;   // 1/sqrt(48)
    const bool lastR = (wy == NW_ - 1), lastC = (wx == NW_ - 1);
    const int i0 = 16 * wq + (lane >> 2);
    const int jbase = 32 * wk + ((lane & 3) << 1);
    float rmax[2] = {-INFINITY, -INFINITY};
#pragma unroll
    for (int f = 0; f < 4; f++) {
#pragma unroll
        for (int r = 0; r < 4; r++) {
            const int i = i0 + ((r >> 1) << 3);
            const int j = jbase + 8 * f + (r & 1);
            float v = acc[f][r] * scale
                    + Ps[((j >> 3) - (i >> 3) + 7) * 15 + ((j & 7) - (i & 7) + 7)];
            if (lastR && (((i >= 32) ? 1 : 0) ^ ((j >= 32) ? 1 : 0)))           v = -INFINITY;
            if (lastC && ((((i & 7) >= 4) ? 1 : 0) ^ (((j & 7) >= 4) ? 1 : 0))) v = -INFINITY;
            acc[f][r] = v;
            rmax[r >> 1] = fmaxf(rmax[r >> 1], v);
        }
    }
#pragma unroll
    for (int h = 0; h < 2; h++) {
        rmax[h] = fmaxf(rmax[h], __shfl_xor_sync(0xffffffffu, rmax[h], 1));
        rmax[h] = fmaxf(rmax[h], __shfl_xor_sync(0xffffffffu, rmax[h], 2));
    }
    if ((lane & 3) == 0) {
        mred[wk * 64 + i0]     = rmax[0];
        mred[wk * 64 + i0 + 8] = rmax[1];
    }
    __syncthreads();
    float gmax[2], rsum[2] = {0.f, 0.f};
    gmax[0] = fmaxf(mred[i0],     mred[64 + i0]);
    gmax[1] = fmaxf(mred[i0 + 8], mred[64 + i0 + 8]);
#pragma unroll
    for (int f = 0; f < 4; f++) {
#pragma unroll
        for (int r = 0; r < 4; r++) {
            const float e = __expf(acc[f][r] - gmax[r >> 1]);
            acc[f][r] = e;
            rsum[r >> 1] += e;
        }
    }
#pragma unroll
    for (int h = 0; h < 2; h++) {
        rsum[h] += __shfl_xor_sync(0xffffffffu, rsum[h], 1);
        rsum[h] += __shfl_xor_sync(0xffffffffu, rsum[h], 2);
    }
    if ((lane & 3) == 0) {
        sred[wk * 64 + i0]     = rsum[0];
        sred[wk * 64 + i0 + 8] = rsum[1];
    }
    __syncthreads();   // all QK ldmatrix reads of Q2 done -> Ph alias safe
    float inv[2];
    inv[0] = 1.f / (sred[i0] + sred[64 + i0]);
    inv[1] = 1.f / (sred[i0 + 8] + sred[64 + i0 + 8]);

    // ---- write P (fp16) straight from registers ----
#pragma unroll
    for (int h = 0; h < 2; h++) {
        const int i = i0 + h * 8;
        char* PhB = smx + PH_OFF + i * 144;
#pragma unroll
        for (int f = 0; f < 4; f++) {
            const float p0 = acc[f][h * 2] * inv[h];
            const float p1 = acc[f][h * 2 + 1] * inv[h];
            *(uint32_t*)(PhB + (jbase + 8 * f) * 2) =
                packh(__float2half_rn(p0), __float2half_rn(p1));
        }
    }
    __syncthreads();

    // ---- AV via HMMA: single pass PhVh ----
    const int wq2 = w & 3, wn2 = w >> 2;
    const uint32_t sPh = s2u(smx + PH_OFF);
    const uint32_t sVh = s2u(smx + VTH_OFF);
    const uint32_t aOff = (uint32_t)(16 * wq2 + tr + ((q & 1) << 3)) * 144 + ((q >> 1) << 4);
    const uint32_t b4Off = (uint32_t)(24 * wn2 + tr + ((q >> 1) << 3)) * 144 + ((q & 1) << 4);
    const int tr2 = lane & 7, q01 = (lane >> 3) & 1;
    const uint32_t b2Off = (uint32_t)(24 * wn2 + 16 + tr2) * 144 + (q01 << 4);

    float acc3[3][4] = {};
#pragma unroll
    for (int ks = 0; ks < 4; ks++) {
        uint32_t a0, a1, a2, a3, b0, b1, b2, b3, b4, b5;
        LDSM4(a0, a1, a2, a3, sPh + aOff + ks * 32);
        LDSM4(b0, b1, b2, b3, sVh + b4Off + ks * 32);
        LDSM2(b4, b5, sVh + b2Off + ks * 32);
        MMA16816(acc3[0], a0, a1, a2, a3, b0, b1);
        MMA16816(acc3[1], a0, a1, a2, a3, b2, b3);
        MMA16816(acc3[2], a0, a1, a2, a3, b4, b5);
    }

    // ---- output: fp16 -> g_Yb ----
    const int er2 = lane >> 2, ec2 = (lane & 3) << 1;
#pragma unroll
    for (int h = 0; h < 2; h++) {
        const int i = 16 * wq2 + er2 + h * 8;
        const int Y = wy * 8 + (i >> 3), X = wx * 8 + (i & 7);
        const size_t t = ((size_t)b * Hh + Y) * Wd + X;
        __half* op = g_Yb + t * 384 + hb;
#pragma unroll
        for (int f = 0; f < 3; f++) {
            const int e = 24 * wn2 + 8 * f + ec2;
            *(__half2*)(op + e) = __halves2half2(__float2half_rn(acc3[f][h * 2]),
                                                 __float2half_rn(acc3[f][h * 2 + 1]));
        }
    }
}

// ------------------------------- launcher -----------------------------------
extern "C" void kernel_launch(void* const* d_in, const int* in_sizes, int n_in,
                              void* d_out, int out_size)
{
    const float* values = (const float*)d_in[0];
    const float* coords = (const float*)d_in[1];
    const float* W_vqk  = (const float*)d_in[2];
    const float* b_vqk  = (const float*)d_in[3];
    const float* gm_vqk = (const float*)d_in[4];
    const float* W_vv   = (const float*)d_in[5];
    const float* b_vv   = (const float*)d_in[6];
    const float* W_cqk  = (const float*)d_in[7];
    const float* b_cqk  = (const float*)d_in[8];
    const float* gm_cqk = (const float*)d_in[9];
    const float* lam    = (const float*)d_in[10];
    const float* pos    = (const float*)d_in[11];
    const float* W_ov   = (const float*)d_in[12];
    const float* b_ov   = (const float*)d_in[13];
    float* out = (float*)d_out;

    __half *Av, *Ac, *Yb, *Bv, *Bc, *Bo;
    float *pv, *pc, *biasv, *biasc, *ssv, *ssc, *igv, *igc;
    cudaGetSymbolAddress((void**)&Av, g_Av);
    cudaGetSymbolAddress((void**)&Ac, g_Ac);
    cudaGetSymbolAddress((void**)&Yb, g_Yb);
    cudaGetSymbolAddress((void**)&Bv, g_Bv);
    cudaGetSymbolAddress((void**)&Bc, g_Bc);
    cudaGetSymbolAddress((void**)&Bo, g_Bo);
    cudaGetSymbolAddress((void**)&pv, g_pv);
    cudaGetSymbolAddress((void**)&pc, g_pc);
    cudaGetSymbolAddress((void**)&biasv, g_biasv);
    cudaGetSymbolAddress((void**)&biasc, g_biasc);
    cudaGetSymbolAddress((void**)&ssv, g_ssv);
    cudaGetSymbolAddress((void**)&ssc, g_ssc);
    cudaGetSymbolAddress((void**)&igv, g_igv);
    cudaGetSymbolAddress((void**)&igc, g_igc);

    // 1) fused pack (γ/λ folding) + ss-zero + bias/invγ permute
    pack_all<<<(int)((T6 + 255) / 256), 256>>>(values, coords, W_vqk, W_vv, W_cqk, W_ov,
                                               b_vqk, b_vv, gm_vqk, b_cqk, gm_cqk, lam);

    const int gsm = 98304;
    cudaFuncSetAttribute(gemm_mma, cudaFuncAttributeMaxDynamicSharedMemorySize, gsm);

    // 2) coords projection (K=128), 3) values projection (K=384)
    gemm_mma<<<dim3(768 / 128,  NTOK / 128), 256, gsm>>>(Ac, Bc, biasc, pc, 128,  768, ssc, igc, 2);
    gemm_mma<<<dim3(1152 / 128, NTOK / 128), 256, gsm>>>(Av, Bv, biasv, pv, 384, 1152, ssv, igv, 1);

    // 4) attention
    cudaFuncSetAttribute(attn_k, cudaFuncAttributeMaxDynamicSharedMemorySize, ASMB);
    attn_k<<<Bb * NH_ * NW_ * NW_, 256, ASMB>>>(pos);

    // 5) output projection (K=384)
    gemm_mma<<<dim3(384 / 128, NTOK / 128), 256, gsm>>>(Yb, Bo, b_ov, out, 384, 384, nullptr, nullptr, 0);
}

// round 14
// speedup vs baseline: 2.9392x; 1.0933x over previous
#include <cuda_runtime.h>
#include <cuda_fp16.h>
#include <math.h>
#include <stdint.h>

#define Bb   2
#define Hh   192
#define Wd   192
#define NH_  8
#define HD_  48
#define NW_  24
#define NTOK (Bb*Hh*Wd)   // 73728

// ---------------- scratch (device globals; no runtime alloc) ----------------
__device__ __half g_Av[(size_t)NTOK * 384];    // values fp16
__device__ __half g_Ac[(size_t)NTOK * 128];    // coords fp16
__device__ __half g_Yb[(size_t)NTOK * 384];    // attn out fp16
__device__ __half g_Bv[1152 * 384];            // W' permuted+γ-folded vqk|vv
__device__ __half g_Bc[768 * 128];             // W' permuted+γλ-folded cqk
__device__ __half g_Bo[384 * 384];             // W' ov
__device__ float g_biasv[1152];                // γ-folded permuted bias
__device__ float g_biasc[768];
__device__ float g_igv[1152];                  // 1/γ (pre-norm recovery)
__device__ float g_igc[768];                   // 1/(γ[λ])
__device__ __half g_pv[(size_t)NTOK * 1152];   // proj out fp16: [Q|K|V] head-major, +bias
__device__ __half g_pc[(size_t)NTOK * 768];    // proj out fp16: [Qc|Kc]
__device__ float g_ssv[NTOK];
__device__ float g_ssc[NTOK];

// ------------------------------ PTX helpers ---------------------------------
__device__ __forceinline__ uint32_t s2u(const void* p) {
    uint32_t a;
    asm("{ .reg .u64 t; cvta.to.shared.u64 t, %1; cvt.u32.u64 %0, t; }" : "=r"(a) : "l"(p));
    return a;
}
__device__ __forceinline__ void cp16(uint32_t dst, const void* src) {
    asm volatile("cp.async.cg.shared.global [%0], [%1], 16;" :: "r"(dst), "l"(src));
}
#define CP_COMMIT() asm volatile("cp.async.commit_group;" ::: "memory")
#define CP_WAIT1()  asm volatile("cp.async.wait_group 1;" ::: "memory")
#define CP_WAIT0()  asm volatile("cp.async.wait_group 0;" ::: "memory")

#define LDSM4(R0,R1,R2,R3,ADDR) \
    asm volatile("ldmatrix.sync.aligned.m8n8.x4.shared.b16 {%0,%1,%2,%3}, [%4];" \
                 : "=r"(R0), "=r"(R1), "=r"(R2), "=r"(R3) : "r"(ADDR))
#define LDSM2(R0,R1,ADDR) \
    asm volatile("ldmatrix.sync.aligned.m8n8.x2.shared.b16 {%0,%1}, [%2];" \
                 : "=r"(R0), "=r"(R1) : "r"(ADDR))

#define MMA16816(D,A0,A1,A2,A3,B0,B1) \
    asm volatile("mma.sync.aligned.m16n8k16.row.col.f32.f16.f16.f32 " \
                 "{%0,%1,%2,%3},{%4,%5,%6,%7},{%8,%9},{%0,%1,%2,%3};" \
                 : "+f"(D[0]), "+f"(D[1]), "+f"(D[2]), "+f"(D[3]) \
                 : "r"(A0), "r"(A1), "r"(A2), "r"(A3), "r"(B0), "r"(B1))

__device__ __forceinline__ uint32_t packh(__half a, __half b) {
    return (uint32_t)__half_as_ushort(a) | ((uint32_t)__half_as_ushort(b) << 16);
}
__device__ __forceinline__ uint32_t scaleh2(uint32_t h2, float f) {
    __half2 h = *(__half2*)&h2;
    float2 v = __half22float2(h);
    __half2 o = __floats2half2_rn(v.x * f, v.y * f);
    return *(uint32_t*)&o;
}

// ---------------- fused pack + metaperm + ss-zero (1 launch) -----------------
#define T0 ((size_t)NTOK * 384)
#define T1 (T0 + (size_t)NTOK * 128)
#define T2 (T1 + 1152 * 384)
#define T3 (T2 + 768 * 128)
#define T4 (T3 + 384 * 384)
#define T5 (T4 + NTOK)
#define T6 (T5 + 1920)
__global__ void pack_all(const float* __restrict__ values, const float* __restrict__ coords,
                         const float* __restrict__ Wqk, const float* __restrict__ Wvv,
                         const float* __restrict__ Wcqk, const float* __restrict__ Wov,
                         const float* __restrict__ bqk, const float* __restrict__ bvv,
                         const float* __restrict__ gvqk,
                         const float* __restrict__ bcqk, const float* __restrict__ gcqk,
                         const float* __restrict__ lamp)
{
    size_t i = (size_t)blockIdx.x * 256 + threadIdx.x;
    if (i < T0) {                       // A_v fp16 (layout-preserving)
        g_Av[i] = __float2half_rn(values[i]);
    } else if (i < T1) {                // A_c fp16
        const size_t j = i - T0;
        g_Ac[j] = __float2half_rn(coords[j]);
    } else if (i < T2) {                // B_v permuted [Q|K|V] head-major, γ-folded
        int j = (int)(i - T1);
        int n = j / 384, k = j - (j / 384) * 384;
        const int blk = n / 384;
        const int hm = (n % 384) / 48, e = n % 48;
        const int c = 3 * (e * 8 + hm) + blk;
        float w = (c < 768) ? Wqk[(size_t)k * 768 + c] : Wvv[(size_t)k * 384 + (c - 768)];
        const float gf = (c < 768) ? gvqk[c] : 1.0f;
        g_Bv[(size_t)n * 384 + k] = __float2half_rn(w * gf);
    } else if (i < T3) {                // B_c permuted [Qc|Kc], γλ-folded
        int j = (int)(i - T2);
        int n = j / 128, k = j - (j / 128) * 128;
        const int blk = n / 384;
        const int hm = (n % 384) / 48, e = n % 48;
        const int c = 2 * (e * 8 + hm) + blk;
        const float gf = gcqk[c] * (blk == 0 ? lamp[0] : 1.0f);
        g_Bc[(size_t)n * 128 + k] = __float2half_rn(Wcqk[(size_t)k * 768 + c] * gf);
    } else if (i < T4) {                // B_o
        int j = (int)(i - T3);
        int n = j / 384, k = j - (j / 384) * 384;
        g_Bo[(size_t)n * 384 + k] = __float2half_rn(Wov[(size_t)k * 384 + n]);
    } else if (i < T5) {                // ss zero
        const int t = (int)(i - T4);
        g_ssv[t] = 0.f; g_ssc[t] = 0.f;
    } else if (i < T6) {                // bias + 1/γ permute
        int n = (int)(i - T5);
        if (n < 1152) {
            const int blk = n / 384, hm = (n % 384) / 48, e = n % 48;
            const int c = 3 * (e * 8 + hm) + blk;
            const float gf = (c < 768) ? gvqk[c] : 1.0f;
            g_biasv[n] = ((c < 768) ? bqk[c] : bvv[c - 768]) * gf;
            g_igv[n]   = (gf != 0.f) ? 1.f / gf : 0.f;
        } else {
            const int n2 = n - 1152;
            const int blk = n2 / 384, hm = (n2 % 384) / 48, e = n2 % 48;
            const int c = 2 * (e * 8 + hm) + blk;
            const float gf = gcqk[c] * (blk == 0 ? lamp[0] : 1.0f);
            g_biasc[n2] = bcqk[c] * gf;
            g_igc[n2]   = (gf != 0.f) ? 1.f / gf : 0.f;
        }
    }
}

// --------- HMMA GEMM: C = A[M,K] @ B[N,K]^T + bias; optional ss -------------
// 3-stage cp.async pipeline, ONE __syncthreads per K-chunk.
// chalf: 1 -> C is __half, 0 -> C is float.
__global__ __launch_bounds__(256, 2) void gemm_mma(
    const __half* __restrict__ A, const __half* __restrict__ B,
    const float* __restrict__ bias, void* __restrict__ Cout, int Kp, int ldc,
    float* __restrict__ ss, const float* __restrict__ ig, int smode, int chalf)
{
    extern __shared__ __align__(1024) char smem[];
    const uint32_t sb = s2u(smem);
    const int tid = threadIdx.x, lane = tid & 31, wid = tid >> 5;
    const int mB = blockIdx.y * 128, n0 = blockIdx.x * 128;
    const int wm = (wid & 3) << 5;
    const int wn = (wid >> 2) << 6;

    const int lrow = tid >> 3, lu = tid & 7;
    const size_t ldk = (size_t)Kp * 2;
    const char* Asrc = (const char*)A + (size_t)(mB + lrow) * ldk + lu * 16;
    const char* Bsrc = (const char*)B + (size_t)(n0 + lrow) * ldk + lu * 16;
    uint32_t dsto[4];
#pragma unroll
    for (int r = 0; r < 4; r++) {
        const int row = lrow + r * 32;
        dsto[r] = row * 128 + ((lu ^ (row & 7)) << 4);
    }

    const int q = lane >> 3, tr = lane & 7;
    const int qA = q >> 1, qB = q & 1;
    uint32_t rowoffA[2], xrA[2];
#pragma unroll
    for (int fm = 0; fm < 2; fm++) {
        const int row = wm + fm * 16 + tr + ((q & 1) << 3);
        rowoffA[fm] = row * 128; xrA[fm] = row & 7;
    }
    uint32_t rowoffB[4], xrB[4];
#pragma unroll
    for (int fn = 0; fn < 4; fn++) {
        const int row = wn + fn * 16 + tr + ((q >> 1) << 3);
        rowoffB[fn] = row * 128; xrB[fn] = row & 7;
    }

    float acc[2][8][4] = {};

    const int NC = Kp >> 6;
#pragma unroll
    for (int pc = 0; pc < 2; pc++) {
        if (pc < NC) {
            const uint32_t ab = sb + pc * 16384u;
            const uint32_t bb = sb + 49152u + pc * 16384u;
            const char* An = Asrc + (size_t)pc * 128;
            const char* Bn = Bsrc + (size_t)pc * 128;
#pragma unroll
            for (int r = 0; r < 4; r++) {
                cp16(ab + dsto[r], An + (size_t)r * 32 * ldk);
                cp16(bb + dsto[r], Bn + (size_t)r * 32 * ldk);
            }
            CP_COMMIT();
        }
    }

    int bidx = 0, pidx = 2;
    for (int c = 0; c < NC; c++) {
        if (c + 1 < NC) { CP_WAIT1(); } else { CP_WAIT0(); }
        __syncthreads();
        if (c + 2 < NC) {
            const uint32_t ab = sb + pidx * 16384u;
            const uint32_t bb = sb + 49152u + pidx * 16384u;
            const char* An = Asrc + (size_t)(c + 2) * 128;
            const char* Bn = Bsrc + (size_t)(c + 2) * 128;
#pragma unroll
            for (int r = 0; r < 4; r++) {
                cp16(ab + dsto[r], An + (size_t)r * 32 * ldk);
                cp16(bb + dsto[r], Bn + (size_t)r * 32 * ldk);
            }
            CP_COMMIT();
            if (++pidx == 3) pidx = 0;
        }

        const uint32_t Ab = sb + bidx * 16384u;
        const uint32_t Bs = sb + 49152u + bidx * 16384u;
#pragma unroll
        for (int ks = 0; ks < 4; ks++) {
            uint32_t a[2][4], bf[4][4];
#pragma unroll
            for (int fm = 0; fm < 2; fm++) {
                const uint32_t ad = Ab + rowoffA[fm] + ((((uint32_t)(ks * 2 + qA)) ^ xrA[fm]) << 4);
                LDSM4(a[fm][0], a[fm][1], a[fm][2], a[fm][3], ad);
            }
#pragma unroll
            for (int fn = 0; fn < 4; fn++) {
                const uint32_t bd = Bs + rowoffB[fn] + ((((uint32_t)(ks * 2 + qB)) ^ xrB[fn]) << 4);
                LDSM4(bf[fn][0], bf[fn][1], bf[fn][2], bf[fn][3], bd);
            }
#pragma unroll
            for (int fm = 0; fm < 2; fm++)
#pragma unroll
                for (int fn = 0; fn < 4; fn++) {
                    MMA16816(acc[fm][2 * fn],     a[fm][0], a[fm][1], a[fm][2], a[fm][3],
                             bf[fn][0], bf[fn][1]);
                    MMA16816(acc[fm][2 * fn + 1], a[fm][0], a[fm][1], a[fm][2], a[fm][3],
                             bf[fn][2], bf[fn][3]);
                }
        }
        if (++bidx == 3) bidx = 0;
    }

    const int er = lane >> 2, ec = (lane & 3) << 1;
    float ssa[2][2] = {{0.f, 0.f}, {0.f, 0.f}};
#pragma unroll
    for (int fm = 0; fm < 2; fm++) {
#pragma unroll
        for (int fn = 0; fn < 8; fn++) {
            const int gm = mB + wm + fm * 16 + er;
            const int gn = n0 + wn + fn * 8 + ec;
            const float2 bv = *(const float2*)(bias + gn);
            float2 o0, o1;
            o0.x = acc[fm][fn][0] + bv.x; o0.y = acc[fm][fn][1] + bv.y;
            o1.x = acc[fm][fn][2] + bv.x; o1.y = acc[fm][fn][3] + bv.y;
            if (chalf) {
                __half* Ch = (__half*)Cout;
                *(__half2*)(Ch + (size_t)gm * ldc + gn) = __floats2half2_rn(o0.x, o0.y);
                *(__half2*)(Ch + (size_t)(gm + 8) * ldc + gn) = __floats2half2_rn(o1.x, o1.y);
            } else {
                float* Cf = (float*)Cout;
                *(float2*)(Cf + (size_t)gm * ldc + gn) = o0;
                *(float2*)(Cf + (size_t)(gm + 8) * ldc + gn) = o1;
            }
            if (smode) {
                const float2 iv = *(const float2*)(ig + gn);
                const float p0 = o0.x * iv.x, p1 = o0.y * iv.y;
                const float p2 = o1.x * iv.x, p3 = o1.y * iv.y;
                const bool m0 = (smode == 2) || ((gn % 48) < 32);
                const bool m1 = (smode == 2) || (((gn + 1) % 48) < 32);
                ssa[fm][0] += (m0 ? p0 * p0 : 0.f) + (m1 ? p1 * p1 : 0.f);
                ssa[fm][1] += (m0 ? p2 * p2 : 0.f) + (m1 ? p3 * p3 : 0.f);
            }
        }
    }
    if (smode) {
#pragma unroll
        for (int fm = 0; fm < 2; fm++)
#pragma unroll
            for (int h = 0; h < 2; h++) {
                float v = ssa[fm][h];
                v += __shfl_xor_sync(0xffffffffu, v, 1);
                v += __shfl_xor_sync(0xffffffffu, v, 2);
                if ((lane & 3) == 0)
                    atomicAdd(ss + mB + wm + fm * 16 + er + h * 8, v);
            }
    }
}

// ---------------------------- windowed attention ----------------------------
// Q,K,P,V all fp16. smem (bytes); Ph ALIASES Q2 (dead after QK MMA):
#define Q2_OFF  0u            // 64 x 208 (96 halves + pad)  13312
#define K2_OFF  13312u        // 13312
#define PH_OFF  0u            // 64 x 144 (9216) — aliases Q2
#define VTH_OFF 26624u        // 48 x 144 (6912)
#define PS_OFF  33536u        // 225 f32
#define TS_OFF  34436u
#define RV_OFF  34692u
#define RC_OFF  34948u
#define MR_OFF  35204u
#define SR_OFF  35716u
#define ASMB    36228
__global__ __launch_bounds__(256, 4) void attn_k(const float* __restrict__ pos_emb)
{
    extern __shared__ __align__(128) char smx[];
    float* Ps = (float*)(smx + PS_OFF);
    int*   ts = (int*)(smx + TS_OFF);
    float* rv = (float*)(smx + RV_OFF);
    float* rc = (float*)(smx + RC_OFF);
    float* mred = (float*)(smx + MR_OFF);
    float* sred = (float*)(smx + SR_OFF);

    int blk = blockIdx.x;
    const int wx = blk % NW_; blk /= NW_;
    const int wy = blk % NW_; blk /= NW_;
    const int head = blk % NH_;
    const int b = blk / NH_;
    const int tid = threadIdx.x;

    if (tid < 64) {
        const int ry = tid >> 3, rx = tid & 7;
        const int y = (wy * 8 + ry + 4) % Hh;
        const int x = (wx * 8 + rx + 4) % Wd;
        const int t = b * (Hh * Wd) + y * Wd + x;
        ts[tid] = t;
        rv[tid] = rsqrtf(g_ssv[t] * (1.f / 768.f) + 1e-6f);
        rc[tid] = rsqrtf(g_ssc[t] * (1.f / 768.f) + 1e-6f);
    }
    for (int i = tid; i < 225; i += 256) Ps[i] = pos_emb[i];
    __syncthreads();

    const int hb = head * 48;

    // ---- Q/K gather: fp16 source, uint4 = 8 halves per load ----
    for (int i = tid; i < 64 * 12; i += 256) {
        const int tok = i / 12, u = i - tok * 12;
        const int t = ts[tok];
        uint4 qr, kr;
        float f;
        int ch;
        if (u < 6) {
            ch = u * 8;
            const __half* pvr = g_pv + (size_t)t * 1152;
            qr = *(const uint4*)(pvr + hb + ch);
            kr = *(const uint4*)(pvr + 384 + hb + ch);
            f = (u < 4) ? rv[tok] : 1.f;
        } else {
            const int c2 = (u - 6) * 8;
            ch = 48 + c2;
            const __half* pcr = g_pc + (size_t)t * 768;
            qr = *(const uint4*)(pcr + hb + c2);
            kr = *(const uint4*)(pcr + 384 + hb + c2);
            f = rc[tok];
        }
        uint4 qo, ko;
        qo.x = scaleh2(qr.x, f); qo.y = scaleh2(qr.y, f);
        qo.z = scaleh2(qr.z, f); qo.w = scaleh2(qr.w, f);
        ko.x = scaleh2(kr.x, f); ko.y = scaleh2(kr.y, f);
        ko.z = scaleh2(kr.z, f); ko.w = scaleh2(kr.w, f);
        *(uint4*)(smx + Q2_OFF + tok * 208 + ch * 2) = qo;
        *(uint4*)(smx + K2_OFF + tok * 208 + ch * 2) = ko;
    }
    // ---- V gather: transposed e-major, fp16 ----
    {
        __half* vh = (__half*)(smx + VTH_OFF);
        for (int i = tid; i < 64 * 6; i += 256) {
            const int tok = i / 6, u = i - tok * 6;
            const int t = ts[tok];
            const int ch = u * 8;
            uint4 raw = *(const uint4*)(g_pv + (size_t)t * 1152 + 768 + hb + ch);
            const float f = (u < 4) ? rv[tok] : 1.f;
            const uint32_t rr[4] = {raw.x, raw.y, raw.z, raw.w};
#pragma unroll
            for (int p = 0; p < 4; p++) {
                const uint32_t sc = scaleh2(rr[p], f);
                vh[(ch + 2 * p + 0) * 72 + tok] = __ushort_as_half((unsigned short)(sc & 0xFFFF));
                vh[(ch + 2 * p + 1) * 72 + tok] = __ushort_as_half((unsigned short)(sc >> 16));
            }
        }
    }
    __syncthreads();

    // ---- QK^T via HMMA: 6 k16 steps ----
    const int lane = tid & 31, w = tid >> 5;
    const int wq = w & 3, wk = w >> 2;
    const int q = lane >> 3, tr = lane & 7;
    const uint32_t sQ = s2u(smx + Q2_OFF), sK = s2u(smx + K2_OFF);
    const uint32_t aBase = sQ + (uint32_t)(16 * wq + tr + ((q & 1) << 3)) * 208 + ((q >> 1) << 4);
    uint32_t bBase[2];
    bBase[0] = sK + (uint32_t)(32 * wk + tr + ((q >> 1) << 3)) * 208 + ((q & 1) << 4);
    bBase[1] = bBase[0] + 16 * 208;

    float acc[4][4] = {};
#pragma unroll
    for (int s = 0; s < 6; s++) {
        uint32_t a0, a1, a2, a3;
        LDSM4(a0, a1, a2, a3, aBase + s * 32);
#pragma unroll
        for (int fn = 0; fn < 2; fn++) {
            uint32_t b0, b1, b2, b3;
            LDSM4(b0, b1, b2, b3, bBase[fn] + s * 32);
            MMA16816(acc[2 * fn],     a0, a1, a2, a3, b0, b1);
            MMA16816(acc[2 * fn + 1], a0, a1, a2, a3, b2, b3);
        }
    }

    // ---- register epilogue: scale + bias + mask; row max via shuffles ----
    const float scale = 0.14433756729740643f;   // 1/sqrt(48)
    const bool lastR = (wy == NW_ - 1), lastC = (wx == NW_ - 1);
    const int i0 = 16 * wq + (lane >> 2);
    const int jbase = 32 * wk + ((lane & 3) << 1);
    float rmax[2] = {-INFINITY, -INFINITY};
#pragma unroll
    for (int f = 0; f < 4; f++) {
#pragma unroll
        for (int r = 0; r < 4; r++) {
            const int i = i0 + ((r >> 1) << 3);
            const int j = jbase + 8 * f + (r & 1);
            float v = acc[f][r] * scale
                    + Ps[((j >> 3) - (i >> 3) + 7) * 15 + ((j & 7) - (i & 7) + 7)];
            if (lastR && (((i >= 32) ? 1 : 0) ^ ((j >= 32) ? 1 : 0)))           v = -INFINITY;
            if (lastC && ((((i & 7) >= 4) ? 1 : 0) ^ (((j & 7) >= 4) ? 1 : 0))) v = -INFINITY;
            acc[f][r] = v;
            rmax[r >> 1] = fmaxf(rmax[r >> 1], v);
        }
    }
#pragma unroll
    for (int h = 0; h < 2; h++) {
        rmax[h] = fmaxf(rmax[h], __shfl_xor_sync(0xffffffffu, rmax[h], 1));
        rmax[h] = fmaxf(rmax[h], __shfl_xor_sync(0xffffffffu, rmax[h], 2));
    }
    if ((lane & 3) == 0) {
        mred[wk * 64 + i0]     = rmax[0];
        mred[wk * 64 + i0 + 8] = rmax[1];
    }
    __syncthreads();
    float gmax[2], rsum[2] = {0.f, 0.f};
    gmax[0] = fmaxf(mred[i0],     mred[64 + i0]);
    gmax[1] = fmaxf(mred[i0 + 8], mred[64 + i0 + 8]);
#pragma unroll
    for (int f = 0; f < 4; f++) {
#pragma unroll
        for (int r = 0; r < 4; r++) {
            const float e = __expf(acc[f][r] - gmax[r >> 1]);
            acc[f][r] = e;
            rsum[r >> 1] += e;
        }
    }
#pragma unroll
    for (int h = 0; h < 2; h++) {
        rsum[h] += __shfl_xor_sync(0xffffffffu, rsum[h], 1);
        rsum[h] += __shfl_xor_sync(0xffffffffu, rsum[h], 2);
    }
    if ((lane & 3) == 0) {
        sred[wk * 64 + i0]     = rsum[0];
        sred[wk * 64 + i0 + 8] = rsum[1];
    }
    __syncthreads();   // all QK ldmatrix reads of Q2 done -> Ph alias safe
    float inv[2];
    inv[0] = 1.f / (sred[i0] + sred[64 + i0]);
    inv[1] = 1.f / (sred[i0 + 8] + sred[64 + i0 + 8]);

    // ---- write P (fp16) straight from registers ----
#pragma unroll
    for (int h = 0; h < 2; h++) {
        const int i = i0 + h * 8;
        char* PhB = smx + PH_OFF + i * 144;
#pragma unroll
        for (int f = 0; f < 4; f++) {
            const float p0 = acc[f][h * 2] * inv[h];
            const float p1 = acc[f][h * 2 + 1] * inv[h];
            *(uint32_t*)(PhB + (jbase + 8 * f) * 2) =
                packh(__float2half_rn(p0), __float2half_rn(p1));
        }
    }
    __syncthreads();

    // ---- AV via HMMA: single pass PhVh ----
    const int wq2 = w & 3, wn2 = w >> 2;
    const uint32_t sPh = s2u(smx + PH_OFF);
    const uint32_t sVh = s2u(smx + VTH_OFF);
    const uint32_t aOff = (uint32_t)(16 * wq2 + tr + ((q & 1) << 3)) * 144 + ((q >> 1) << 4);
    const uint32_t b4Off = (uint32_t)(24 * wn2 + tr + ((q >> 1) << 3)) * 144 + ((q & 1) << 4);
    const int tr2 = lane & 7, q01 = (lane >> 3) & 1;
    const uint32_t b2Off = (uint32_t)(24 * wn2 + 16 + tr2) * 144 + (q01 << 4);

    float acc3[3][4] = {};
#pragma unroll
    for (int ks = 0; ks < 4; ks++) {
        uint32_t a0, a1, a2, a3, b0, b1, b2, b3, b4, b5;
        LDSM4(a0, a1, a2, a3, sPh + aOff + ks * 32);
        LDSM4(b0, b1, b2, b3, sVh + b4Off + ks * 32);
        LDSM2(b4, b5, sVh + b2Off + ks * 32);
        MMA16816(acc3[0], a0, a1, a2, a3, b0, b1);
        MMA16816(acc3[1], a0, a1, a2, a3, b2, b3);
        MMA16816(acc3[2], a0, a1, a2, a3, b4, b5);
    }

    // ---- output: fp16 -> g_Yb ----
    const int er2 = lane >> 2, ec2 = (lane & 3) << 1;
#pragma unroll
    for (int h = 0; h < 2; h++) {
        const int i = 16 * wq2 + er2 + h * 8;
        const int Y = wy * 8 + (i >> 3), X = wx * 8 + (i & 7);
        const size_t t = ((size_t)b * Hh + Y) * Wd + X;
        __half* op = g_Yb + t * 384 + hb;
#pragma unroll
        for (int f = 0; f < 3; f++) {
            const int e = 24 * wn2 + 8 * f + ec2;
            *(__half2*)(op + e) = __halves2half2(__float2half_rn(acc3[f][h * 2]),
                                                 __float2half_rn(acc3[f][h * 2 + 1]));
        }
    }
}

// ------------------------------- launcher -----------------------------------
extern "C" void kernel_launch(void* const* d_in, const int* in_sizes, int n_in,
                              void* d_out, int out_size)
{
    const float* values = (const float*)d_in[0];
    const float* coords = (const float*)d_in[1];
    const float* W_vqk  = (const float*)d_in[2];
    const float* b_vqk  = (const float*)d_in[3];
    const float* gm_vqk = (const float*)d_in[4];
    const float* W_vv   = (const float*)d_in[5];
    const float* b_vv   = (const float*)d_in[6];
    const float* W_cqk  = (const float*)d_in[7];
    const float* b_cqk  = (const float*)d_in[8];
    const float* gm_cqk = (const float*)d_in[9];
    const float* lam    = (const float*)d_in[10];
    const float* pos    = (const float*)d_in[11];
    const float* W_ov   = (const float*)d_in[12];
    const float* b_ov   = (const float*)d_in[13];
    float* out = (float*)d_out;

    __half *Av, *Ac, *Yb, *Bv, *Bc, *Bo, *pv, *pc;
    float *biasv, *biasc, *ssv, *ssc, *igv, *igc;
    cudaGetSymbolAddress((void**)&Av, g_Av);
    cudaGetSymbolAddress((void**)&Ac, g_Ac);
    cudaGetSymbolAddress((void**)&Yb, g_Yb);
    cudaGetSymbolAddress((void**)&Bv, g_Bv);
    cudaGetSymbolAddress((void**)&Bc, g_Bc);
    cudaGetSymbolAddress((void**)&Bo, g_Bo);
    cudaGetSymbolAddress((void**)&pv, g_pv);
    cudaGetSymbolAddress((void**)&pc, g_pc);
    cudaGetSymbolAddress((void**)&biasv, g_biasv);
    cudaGetSymbolAddress((void**)&biasc, g_biasc);
    cudaGetSymbolAddress((void**)&ssv, g_ssv);
    cudaGetSymbolAddress((void**)&ssc, g_ssc);
    cudaGetSymbolAddress((void**)&igv, g_igv);
    cudaGetSymbolAddress((void**)&igc, g_igc);

    // 1) fused pack (γ/λ folding) + ss-zero + bias/invγ permute
    pack_all<<<(int)((T6 + 255) / 256), 256>>>(values, coords, W_vqk, W_vv, W_cqk, W_ov,
                                               b_vqk, b_vv, gm_vqk, b_cqk, gm_cqk, lam);

    const int gsm = 98304;
    cudaFuncSetAttribute(gemm_mma, cudaFuncAttributeMaxDynamicSharedMemorySize, gsm);

    // 2) coords projection (K=128, fp16 out), 3) values projection (K=384, fp16 out)
    gemm_mma<<<dim3(768 / 128,  NTOK / 128), 256, gsm>>>(Ac, Bc, biasc, pc, 128,  768, ssc, igc, 2, 1);
    gemm_mma<<<dim3(1152 / 128, NTOK / 128), 256, gsm>>>(Av, Bv, biasv, pv, 384, 1152, ssv, igv, 1, 1);

    // 4) attention
    cudaFuncSetAttribute(attn_k, cudaFuncAttributeMaxDynamicSharedMemorySize, ASMB);
    attn_k<<<Bb * NH_ * NW_ * NW_, 256, ASMB>>>(pos);

    // 5) output projection (K=384, fp32 out to harness buffer)
    gemm_mma<<<dim3(384 / 128, NTOK / 128), 256, gsm>>>(Yb, Bo, b_ov, out, 384, 384, nullptr, nullptr, 0, 0);
}

// round 15
// speedup vs baseline: 2.9680x; 1.0098x over previous
#include <cuda_runtime.h>
#include <cuda_fp16.h>
#include <math.h>
#include <stdint.h>

#define Bb   2
#define Hh   192
#define Wd   192
#define NH_  8
#define HD_  48
#define NW_  24
#define NTOK (Bb*Hh*Wd)   // 73728

// ---------------- scratch (device globals; no runtime alloc) ----------------
__device__ __half g_Av[(size_t)NTOK * 384];    // values fp16
__device__ __half g_Ac[(size_t)NTOK * 128];    // coords fp16
__device__ __half g_Yb[(size_t)NTOK * 384];    // attn out fp16
__device__ __half g_Bv[1152 * 384];            // W' permuted+γ-folded vqk|vv
__device__ __half g_Bc[768 * 128];             // W' permuted+γλ-folded cqk
__device__ __half g_Bo[384 * 384];             // W' ov
__device__ float g_biasv[1152];                // γ-folded permuted bias
__device__ float g_biasc[768];
__device__ float g_igv[1152];                  // 1/γ (pre-norm recovery)
__device__ float g_igc[768];                   // 1/(γ[λ])
__device__ __half g_pv[(size_t)NTOK * 1152];   // proj out fp16: [Q|K|V] head-major, +bias
__device__ __half g_pc[(size_t)NTOK * 768];    // proj out fp16: [Qc|Kc]
__device__ float g_ssv[NTOK];
__device__ float g_ssc[NTOK];

// ------------------------------ PTX helpers ---------------------------------
__device__ __forceinline__ uint32_t s2u(const void* p) {
    uint32_t a;
    asm("{ .reg .u64 t; cvta.to.shared.u64 t, %1; cvt.u32.u64 %0, t; }" : "=r"(a) : "l"(p));
    return a;
}
__device__ __forceinline__ void cp16(uint32_t dst, const void* src) {
    asm volatile("cp.async.cg.shared.global [%0], [%1], 16;" :: "r"(dst), "l"(src));
}
#define CP_COMMIT() asm volatile("cp.async.commit_group;" ::: "memory")
#define CP_WAIT1()  asm volatile("cp.async.wait_group 1;" ::: "memory")
#define CP_WAIT0()  asm volatile("cp.async.wait_group 0;" ::: "memory")

#define LDSM4(R0,R1,R2,R3,ADDR) \
    asm volatile("ldmatrix.sync.aligned.m8n8.x4.shared.b16 {%0,%1,%2,%3}, [%4];" \
                 : "=r"(R0), "=r"(R1), "=r"(R2), "=r"(R3) : "r"(ADDR))
#define LDSM4T(R0,R1,R2,R3,ADDR) \
    asm volatile("ldmatrix.sync.aligned.m8n8.x4.trans.shared.b16 {%0,%1,%2,%3}, [%4];" \
                 : "=r"(R0), "=r"(R1), "=r"(R2), "=r"(R3) : "r"(ADDR))
#define LDSM2T(R0,R1,ADDR) \
    asm volatile("ldmatrix.sync.aligned.m8n8.x2.trans.shared.b16 {%0,%1}, [%2];" \
                 : "=r"(R0), "=r"(R1) : "r"(ADDR))

#define MMA16816(D,A0,A1,A2,A3,B0,B1) \
    asm volatile("mma.sync.aligned.m16n8k16.row.col.f32.f16.f16.f32 " \
                 "{%0,%1,%2,%3},{%4,%5,%6,%7},{%8,%9},{%0,%1,%2,%3};" \
                 : "+f"(D[0]), "+f"(D[1]), "+f"(D[2]), "+f"(D[3]) \
                 : "r"(A0), "r"(A1), "r"(A2), "r"(A3), "r"(B0), "r"(B1))

__device__ __forceinline__ uint32_t packh(__half a, __half b) {
    return (uint32_t)__half_as_ushort(a) | ((uint32_t)__half_as_ushort(b) << 16);
}
__device__ __forceinline__ uint32_t scaleh2(uint32_t h2, float f) {
    __half2 h = *(__half2*)&h2;
    float2 v = __half22float2(h);
    __half2 o = __floats2half2_rn(v.x * f, v.y * f);
    return *(uint32_t*)&o;
}

// ---------------- fused pack + metaperm + ss-zero (1 launch) -----------------
#define T0 ((size_t)NTOK * 384)
#define T1 (T0 + (size_t)NTOK * 128)
#define T2 (T1 + 1152 * 384)
#define T3 (T2 + 768 * 128)
#define T4 (T3 + 384 * 384)
#define T5 (T4 + NTOK)
#define T6 (T5 + 1920)
__global__ void pack_all(const float* __restrict__ values, const float* __restrict__ coords,
                         const float* __restrict__ Wqk, const float* __restrict__ Wvv,
                         const float* __restrict__ Wcqk, const float* __restrict__ Wov,
                         const float* __restrict__ bqk, const float* __restrict__ bvv,
                         const float* __restrict__ gvqk,
                         const float* __restrict__ bcqk, const float* __restrict__ gcqk,
                         const float* __restrict__ lamp)
{
    size_t i = (size_t)blockIdx.x * 256 + threadIdx.x;
    if (i < T0) {                       // A_v fp16 (layout-preserving)
        g_Av[i] = __float2half_rn(values[i]);
    } else if (i < T1) {                // A_c fp16
        const size_t j = i - T0;
        g_Ac[j] = __float2half_rn(coords[j]);
    } else if (i < T2) {                // B_v permuted [Q|K|V] head-major, γ-folded
        int j = (int)(i - T1);
        int n = j / 384, k = j - (j / 384) * 384;
        const int blk = n / 384;
        const int hm = (n % 384) / 48, e = n % 48;
        const int c = 3 * (e * 8 + hm) + blk;
        float w = (c < 768) ? Wqk[(size_t)k * 768 + c] : Wvv[(size_t)k * 384 + (c - 768)];
        const float gf = (c < 768) ? gvqk[c] : 1.0f;
        g_Bv[(size_t)n * 384 + k] = __float2half_rn(w * gf);
    } else if (i < T3) {                // B_c permuted [Qc|Kc], γλ-folded
        int j = (int)(i - T2);
        int n = j / 128, k = j - (j / 128) * 128;
        const int blk = n / 384;
        const int hm = (n % 384) / 48, e = n % 48;
        const int c = 2 * (e * 8 + hm) + blk;
        const float gf = gcqk[c] * (blk == 0 ? lamp[0] : 1.0f);
        g_Bc[(size_t)n * 128 + k] = __float2half_rn(Wcqk[(size_t)k * 768 + c] * gf);
    } else if (i < T4) {                // B_o
        int j = (int)(i - T3);
        int n = j / 384, k = j - (j / 384) * 384;
        g_Bo[(size_t)n * 384 + k] = __float2half_rn(Wov[(size_t)k * 384 + n]);
    } else if (i < T5) {                // ss zero
        const int t = (int)(i - T4);
        g_ssv[t] = 0.f; g_ssc[t] = 0.f;
    } else if (i < T6) {                // bias + 1/γ permute
        int n = (int)(i - T5);
        if (n < 1152) {
            const int blk = n / 384, hm = (n % 384) / 48, e = n % 48;
            const int c = 3 * (e * 8 + hm) + blk;
            const float gf = (c < 768) ? gvqk[c] : 1.0f;
            g_biasv[n] = ((c < 768) ? bqk[c] : bvv[c - 768]) * gf;
            g_igv[n]   = (gf != 0.f) ? 1.f / gf : 0.f;
        } else {
            const int n2 = n - 1152;
            const int blk = n2 / 384, hm = (n2 % 384) / 48, e = n2 % 48;
            const int c = 2 * (e * 8 + hm) + blk;
            const float gf = gcqk[c] * (blk == 0 ? lamp[0] : 1.0f);
            g_biasc[n2] = bcqk[c] * gf;
            g_igc[n2]   = (gf != 0.f) ? 1.f / gf : 0.f;
        }
    }
}

// --------- HMMA GEMM: C = A[M,K] @ B[N,K]^T + bias; optional ss -------------
// 3-stage cp.async pipeline, ONE __syncthreads per K-chunk.
// chalf: 1 -> C is __half, 0 -> C is float.
__global__ __launch_bounds__(256, 2) void gemm_mma(
    const __half* __restrict__ A, const __half* __restrict__ B,
    const float* __restrict__ bias, void* __restrict__ Cout, int Kp, int ldc,
    float* __restrict__ ss, const float* __restrict__ ig, int smode, int chalf)
{
    extern __shared__ __align__(1024) char smem[];
    const uint32_t sb = s2u(smem);
    const int tid = threadIdx.x, lane = tid & 31, wid = tid >> 5;
    const int mB = blockIdx.y * 128, n0 = blockIdx.x * 128;
    const int wm = (wid & 3) << 5;
    const int wn = (wid >> 2) << 6;

    const int lrow = tid >> 3, lu = tid & 7;
    const size_t ldk = (size_t)Kp * 2;
    const char* Asrc = (const char*)A + (size_t)(mB + lrow) * ldk + lu * 16;
    const char* Bsrc = (const char*)B + (size_t)(n0 + lrow) * ldk + lu * 16;
    uint32_t dsto[4];
#pragma unroll
    for (int r = 0; r < 4; r++) {
        const int row = lrow + r * 32;
        dsto[r] = row * 128 + ((lu ^ (row & 7)) << 4);
    }

    const int q = lane >> 3, tr = lane & 7;
    const int qA = q >> 1, qB = q & 1;
    uint32_t rowoffA[2], xrA[2];
#pragma unroll
    for (int fm = 0; fm < 2; fm++) {
        const int row = wm + fm * 16 + tr + ((q & 1) << 3);
        rowoffA[fm] = row * 128; xrA[fm] = row & 7;
    }
    uint32_t rowoffB[4], xrB[4];
#pragma unroll
    for (int fn = 0; fn < 4; fn++) {
        const int row = wn + fn * 16 + tr + ((q >> 1) << 3);
        rowoffB[fn] = row * 128; xrB[fn] = row & 7;
    }

    float acc[2][8][4] = {};

    const int NC = Kp >> 6;
#pragma unroll
    for (int pc = 0; pc < 2; pc++) {
        if (pc < NC) {
            const uint32_t ab = sb + pc * 16384u;
            const uint32_t bb = sb + 49152u + pc * 16384u;
            const char* An = Asrc + (size_t)pc * 128;
            const char* Bn = Bsrc + (size_t)pc * 128;
#pragma unroll
            for (int r = 0; r < 4; r++) {
                cp16(ab + dsto[r], An + (size_t)r * 32 * ldk);
                cp16(bb + dsto[r], Bn + (size_t)r * 32 * ldk);
            }
            CP_COMMIT();
        }
    }

    int bidx = 0, pidx = 2;
    for (int c = 0; c < NC; c++) {
        if (c + 1 < NC) { CP_WAIT1(); } else { CP_WAIT0(); }
        __syncthreads();
        if (c + 2 < NC) {
            const uint32_t ab = sb + pidx * 16384u;
            const uint32_t bb = sb + 49152u + pidx * 16384u;
            const char* An = Asrc + (size_t)(c + 2) * 128;
            const char* Bn = Bsrc + (size_t)(c + 2) * 128;
#pragma unroll
            for (int r = 0; r < 4; r++) {
                cp16(ab + dsto[r], An + (size_t)r * 32 * ldk);
                cp16(bb + dsto[r], Bn + (size_t)r * 32 * ldk);
            }
            CP_COMMIT();
            if (++pidx == 3) pidx = 0;
        }

        const uint32_t Ab = sb + bidx * 16384u;
        const uint32_t Bs = sb + 49152u + bidx * 16384u;
#pragma unroll
        for (int ks = 0; ks < 4; ks++) {
            uint32_t a[2][4], bf[4][4];
#pragma unroll
            for (int fm = 0; fm < 2; fm++) {
                const uint32_t ad = Ab + rowoffA[fm] + ((((uint32_t)(ks * 2 + qA)) ^ xrA[fm]) << 4);
                LDSM4(a[fm][0], a[fm][1], a[fm][2], a[fm][3], ad);
            }
#pragma unroll
            for (int fn = 0; fn < 4; fn++) {
                const uint32_t bd = Bs + rowoffB[fn] + ((((uint32_t)(ks * 2 + qB)) ^ xrB[fn]) << 4);
                LDSM4(bf[fn][0], bf[fn][1], bf[fn][2], bf[fn][3], bd);
            }
#pragma unroll
            for (int fm = 0; fm < 2; fm++)
#pragma unroll
                for (int fn = 0; fn < 4; fn++) {
                    MMA16816(acc[fm][2 * fn],     a[fm][0], a[fm][1], a[fm][2], a[fm][3],
                             bf[fn][0], bf[fn][1]);
                    MMA16816(acc[fm][2 * fn + 1], a[fm][0], a[fm][1], a[fm][2], a[fm][3],
                             bf[fn][2], bf[fn][3]);
                }
        }
        if (++bidx == 3) bidx = 0;
    }

    const int er = lane >> 2, ec = (lane & 3) << 1;
    float ssa[2][2] = {{0.f, 0.f}, {0.f, 0.f}};
#pragma unroll
    for (int fm = 0; fm < 2; fm++) {
#pragma unroll
        for (int fn = 0; fn < 8; fn++) {
            const int gm = mB + wm + fm * 16 + er;
            const int gn = n0 + wn + fn * 8 + ec;
            const float2 bv = *(const float2*)(bias + gn);
            float2 o0, o1;
            o0.x = acc[fm][fn][0] + bv.x; o0.y = acc[fm][fn][1] + bv.y;
            o1.x = acc[fm][fn][2] + bv.x; o1.y = acc[fm][fn][3] + bv.y;
            if (chalf) {
                __half* Ch = (__half*)Cout;
                *(__half2*)(Ch + (size_t)gm * ldc + gn) = __floats2half2_rn(o0.x, o0.y);
                *(__half2*)(Ch + (size_t)(gm + 8) * ldc + gn) = __floats2half2_rn(o1.x, o1.y);
            } else {
                float* Cf = (float*)Cout;
                *(float2*)(Cf + (size_t)gm * ldc + gn) = o0;
                *(float2*)(Cf + (size_t)(gm + 8) * ldc + gn) = o1;
            }
            if (smode) {
                const float2 iv = *(const float2*)(ig + gn);
                const float p0 = o0.x * iv.x, p1 = o0.y * iv.y;
                const float p2 = o1.x * iv.x, p3 = o1.y * iv.y;
                const bool m0 = (smode == 2) || ((gn % 48) < 32);
                const bool m1 = (smode == 2) || (((gn + 1) % 48) < 32);
                ssa[fm][0] += (m0 ? p0 * p0 : 0.f) + (m1 ? p1 * p1 : 0.f);
                ssa[fm][1] += (m0 ? p2 * p2 : 0.f) + (m1 ? p3 * p3 : 0.f);
            }
        }
    }
    if (smode) {
#pragma unroll
        for (int fm = 0; fm < 2; fm++)
#pragma unroll
            for (int h = 0; h < 2; h++) {
                float v = ssa[fm][h];
                v += __shfl_xor_sync(0xffffffffu, v, 1);
                v += __shfl_xor_sync(0xffffffffu, v, 2);
                if ((lane & 3) == 0)
                    atomicAdd(ss + mB + wm + fm * 16 + er + h * 8, v);
            }
    }
}

// ---------------------------- windowed attention ----------------------------
// Q,K,P,V all fp16. V stored TOK-MAJOR (112B rows, conflict-free trans-LDSM).
// Ph ALIASES Q2 (dead after QK MMA).
#define Q2_OFF  0u            // 64 x 208  13312
#define K2_OFF  13312u        // 13312
#define PH_OFF  0u            // 64 x 144 (9216) — aliases Q2
#define VTH_OFF 26624u        // 64 tok-rows x 112B = 7168
#define PS_OFF  33792u        // 225 f32
#define TS_OFF  34692u
#define RV_OFF  34948u
#define RC_OFF  35204u
#define MR_OFF  35460u        // 2 x 64 f32
#define SR_OFF  35972u        // 2 x 64 f32
#define ASMB    36484
__global__ __launch_bounds__(256, 4) void attn_k(const float* __restrict__ pos_emb)
{
    extern __shared__ __align__(128) char smx[];
    float* Ps = (float*)(smx + PS_OFF);
    int*   ts = (int*)(smx + TS_OFF);
    float* rv = (float*)(smx + RV_OFF);
    float* rc = (float*)(smx + RC_OFF);
    float* mred = (float*)(smx + MR_OFF);
    float* sred = (float*)(smx + SR_OFF);

    int blk = blockIdx.x;
    const int wx = blk % NW_; blk /= NW_;
    const int wy = blk % NW_; blk /= NW_;
    const int head = blk % NH_;
    const int b = blk / NH_;
    const int tid = threadIdx.x;

    if (tid < 64) {
        const int ry = tid >> 3, rx = tid & 7;
        const int y = (wy * 8 + ry + 4) % Hh;
        const int x = (wx * 8 + rx + 4) % Wd;
        const int t = b * (Hh * Wd) + y * Wd + x;
        ts[tid] = t;
        rv[tid] = rsqrtf(g_ssv[t] * (1.f / 768.f) + 1e-6f);
        rc[tid] = rsqrtf(g_ssc[t] * (1.f / 768.f) + 1e-6f);
    }
    for (int i = tid; i < 225; i += 256) Ps[i] = pos_emb[i];
    __syncthreads();

    const int hb = head * 48;

    // ---- Q/K gather: fp16 source, uint4 = 8 halves per load ----
    for (int i = tid; i < 64 * 12; i += 256) {
        const int tok = i / 12, u = i - tok * 12;
        const int t = ts[tok];
        uint4 qr, kr;
        float f;
        int ch;
        if (u < 6) {
            ch = u * 8;
            const __half* pvr = g_pv + (size_t)t * 1152;
            qr = *(const uint4*)(pvr + hb + ch);
            kr = *(const uint4*)(pvr + 384 + hb + ch);
            f = (u < 4) ? rv[tok] : 1.f;
        } else {
            const int c2 = (u - 6) * 8;
            ch = 48 + c2;
            const __half* pcr = g_pc + (size_t)t * 768;
            qr = *(const uint4*)(pcr + hb + c2);
            kr = *(const uint4*)(pcr + 384 + hb + c2);
            f = rc[tok];
        }
        uint4 qo, ko;
        qo.x = scaleh2(qr.x, f); qo.y = scaleh2(qr.y, f);
        qo.z = scaleh2(qr.z, f); qo.w = scaleh2(qr.w, f);
        ko.x = scaleh2(kr.x, f); ko.y = scaleh2(kr.y, f);
        ko.z = scaleh2(kr.z, f); ko.w = scaleh2(kr.w, f);
        *(uint4*)(smx + Q2_OFF + tok * 208 + ch * 2) = qo;
        *(uint4*)(smx + K2_OFF + tok * 208 + ch * 2) = ko;
    }
    // ---- V gather: tok-major (112B rows), single uint4 store ----
    for (int i = tid; i < 64 * 6; i += 256) {
        const int tok = i / 6, u = i - tok * 6;
        const int t = ts[tok];
        uint4 raw = *(const uint4*)(g_pv + (size_t)t * 1152 + 768 + hb + u * 8);
        const float f = (u < 4) ? rv[tok] : 1.f;
        uint4 o;
        o.x = scaleh2(raw.x, f); o.y = scaleh2(raw.y, f);
        o.z = scaleh2(raw.z, f); o.w = scaleh2(raw.w, f);
        *(uint4*)(smx + VTH_OFF + tok * 112 + u * 16) = o;
    }
    __syncthreads();

    // ---- QK^T via HMMA: 6 k16 steps ----
    const int lane = tid & 31, w = tid >> 5;
    const int wq = w & 3, wk = w >> 2;
    const int q = lane >> 3, tr = lane & 7;
    const uint32_t sQ = s2u(smx + Q2_OFF), sK = s2u(smx + K2_OFF);
    const uint32_t aBase = sQ + (uint32_t)(16 * wq + tr + ((q & 1) << 3)) * 208 + ((q >> 1) << 4);
    uint32_t bBase[2];
    bBase[0] = sK + (uint32_t)(32 * wk + tr + ((q >> 1) << 3)) * 208 + ((q & 1) << 4);
    bBase[1] = bBase[0] + 16 * 208;

    float acc[4][4] = {};
#pragma unroll
    for (int s = 0; s < 6; s++) {
        uint32_t a0, a1, a2, a3;
        LDSM4(a0, a1, a2, a3, aBase + s * 32);
#pragma unroll
        for (int fn = 0; fn < 2; fn++) {
            uint32_t b0, b1, b2, b3;
            LDSM4(b0, b1, b2, b3, bBase[fn] + s * 32);
            MMA16816(acc[2 * fn],     a0, a1, a2, a3, b0, b1);
            MMA16816(acc[2 * fn + 1], a0, a1, a2, a3, b2, b3);
        }
    }

    // ---- register epilogue: scale + bias + mask; ONE-ROUND softmax ----
    const float scale = 0.14433756729740643f;   // 1/sqrt(48)
    const bool lastR = (wy == NW_ - 1), lastC = (wx == NW_ - 1);
    const int i0 = 16 * wq + (lane >> 2);
    const int jbase = 32 * wk + ((lane & 3) << 1);
    float rmax[2] = {-INFINITY, -INFINITY};
#pragma unroll
    for (int f = 0; f < 4; f++) {
#pragma unroll
        for (int r = 0; r < 4; r++) {
            const int i = i0 + ((r >> 1) << 3);
            const int j = jbase + 8 * f + (r & 1);
            float v = acc[f][r] * scale
                    + Ps[((j >> 3) - (i >> 3) + 7) * 15 + ((j & 7) - (i & 7) + 7)];
            if (lastR && (((i >= 32) ? 1 : 0) ^ ((j >= 32) ? 1 : 0)))           v = -INFINITY;
            if (lastC && ((((i & 7) >= 4) ? 1 : 0) ^ (((j & 7) >= 4) ? 1 : 0))) v = -INFINITY;
            acc[f][r] = v;
            rmax[r >> 1] = fmaxf(rmax[r >> 1], v);
        }
    }
    float ml[2], rsum[2] = {0.f, 0.f};
#pragma unroll
    for (int h = 0; h < 2; h++) {
        rmax[h] = fmaxf(rmax[h], __shfl_xor_sync(0xffffffffu, rmax[h], 1));
        rmax[h] = fmaxf(rmax[h], __shfl_xor_sync(0xffffffffu, rmax[h], 2));
        ml[h] = fmaxf(rmax[h], -1e30f);          // clamp: fully-masked half -> 0 contributions
    }
#pragma unroll
    for (int f = 0; f < 4; f++) {
#pragma unroll
        for (int r = 0; r < 4; r++) {
            const float e = __expf(acc[f][r] - ml[r >> 1]);
            acc[f][r] = e;
            rsum[r >> 1] += e;
        }
    }
#pragma unroll
    for (int h = 0; h < 2; h++) {
        rsum[h] += __shfl_xor_sync(0xffffffffu, rsum[h], 1);
        rsum[h] += __shfl_xor_sync(0xffffffffu, rsum[h], 2);
    }
    if ((lane & 3) == 0) {
        mred[wk * 64 + i0]     = ml[0];
        mred[wk * 64 + i0 + 8] = ml[1];
        sred[wk * 64 + i0]     = rsum[0];
        sred[wk * 64 + i0 + 8] = rsum[1];
    }
    __syncthreads();   // also: all QK ldmatrix reads of Q2 done -> Ph alias safe
    float fac[2];
#pragma unroll
    for (int h = 0; h < 2; h++) {
        const int row = i0 + h * 8;
        const float m0 = mred[row], m1 = mred[64 + row];
        const float g = fmaxf(m0, m1);
        const float s = sred[row] * __expf(m0 - g) + sred[64 + row] * __expf(m1 - g);
        fac[h] = __expf(ml[h] - g) / s;
    }

    // ---- write P (fp16) straight from registers ----
#pragma unroll
    for (int h = 0; h < 2; h++) {
        const int i = i0 + h * 8;
        char* PhB = smx + PH_OFF + i * 144;
#pragma unroll
        for (int f = 0; f < 4; f++) {
            const float p0 = acc[f][h * 2] * fac[h];
            const float p1 = acc[f][h * 2 + 1] * fac[h];
            *(uint32_t*)(PhB + (jbase + 8 * f) * 2) =
                packh(__float2half_rn(p0), __float2half_rn(p1));
        }
    }
    __syncthreads();

    // ---- AV via HMMA: P (row-major A) x V (tok-major, trans-LDSM B) ----
    const int wq2 = w & 3, wn2 = w >> 2;
    const uint32_t sPh = s2u(smx + PH_OFF);
    const uint32_t sVh = s2u(smx + VTH_OFF);
    const uint32_t aOff = (uint32_t)(16 * wq2 + tr + ((q & 1) << 3)) * 144 + ((q >> 1) << 4);
    const uint32_t vb4 = sVh + (uint32_t)(lane & 15) * 112
                             + (uint32_t)(24 * wn2 + ((lane >> 4) << 3)) * 2;
    const uint32_t vb2 = sVh + (uint32_t)(lane & 15) * 112
                             + (uint32_t)(24 * wn2 + 16) * 2;

    float acc3[3][4] = {};
#pragma unroll
    for (int ks = 0; ks < 4; ks++) {
        uint32_t a0, a1, a2, a3, b0, b1, b2, b3, b4, b5;
        LDSM4(a0, a1, a2, a3, sPh + aOff + ks * 32);
        LDSM4T(b0, b1, b2, b3, vb4 + ks * 1792);   // 16 tok-rows * 112B
        LDSM2T(b4, b5, vb2 + ks * 1792);
        MMA16816(acc3[0], a0, a1, a2, a3, b0, b1);
        MMA16816(acc3[1], a0, a1, a2, a3, b2, b3);
        MMA16816(acc3[2], a0, a1, a2, a3, b4, b5);
    }

    // ---- output: fp16 -> g_Yb ----
    const int er2 = lane >> 2, ec2 = (lane & 3) << 1;
#pragma unroll
    for (int h = 0; h < 2; h++) {
        const int i = 16 * wq2 + er2 + h * 8;
        const int Y = wy * 8 + (i >> 3), X = wx * 8 + (i & 7);
        const size_t t = ((size_t)b * Hh + Y) * Wd + X;
        __half* op = g_Yb + t * 384 + hb;
#pragma unroll
        for (int f = 0; f < 3; f++) {
            const int e = 24 * wn2 + 8 * f + ec2;
            *(__half2*)(op + e) = __halves2half2(__float2half_rn(acc3[f][h * 2]),
                                                 __float2half_rn(acc3[f][h * 2 + 1]));
        }
    }
}

// ------------------------------- launcher -----------------------------------
extern "C" void kernel_launch(void* const* d_in, const int* in_sizes, int n_in,
                              void* d_out, int out_size)
{
    const float* values = (const float*)d_in[0];
    const float* coords = (const float*)d_in[1];
    const float* W_vqk  = (const float*)d_in[2];
    const float* b_vqk  = (const float*)d_in[3];
    const float* gm_vqk = (const float*)d_in[4];
    const float* W_vv   = (const float*)d_in[5];
    const float* b_vv   = (const float*)d_in[6];
    const float* W_cqk  = (const float*)d_in[7];
    const float* b_cqk  = (const float*)d_in[8];
    const float* gm_cqk = (const float*)d_in[9];
    const float* lam    = (const float*)d_in[10];
    const float* pos    = (const float*)d_in[11];
    const float* W_ov   = (const float*)d_in[12];
    const float* b_ov   = (const float*)d_in[13];
    float* out = (float*)d_out;

    __half *Av, *Ac, *Yb, *Bv, *Bc, *Bo, *pv, *pc;
    float *biasv, *biasc, *ssv, *ssc, *igv, *igc;
    cudaGetSymbolAddress((void**)&Av, g_Av);
    cudaGetSymbolAddress((void**)&Ac, g_Ac);
    cudaGetSymbolAddress((void**)&Yb, g_Yb);
    cudaGetSymbolAddress((void**)&Bv, g_Bv);
    cudaGetSymbolAddress((void**)&Bc, g_Bc);
    cudaGetSymbolAddress((void**)&Bo, g_Bo);
    cudaGetSymbolAddress((void**)&pv, g_pv);
    cudaGetSymbolAddress((void**)&pc, g_pc);
    cudaGetSymbolAddress((void**)&biasv, g_biasv);
    cudaGetSymbolAddress((void**)&biasc, g_biasc);
    cudaGetSymbolAddress((void**)&ssv, g_ssv);
    cudaGetSymbolAddress((void**)&ssc, g_ssc);
    cudaGetSymbolAddress((void**)&igv, g_igv);
    cudaGetSymbolAddress((void**)&igc, g_igc);

    // 1) fused pack (γ/λ folding) + ss-zero + bias/invγ permute
    pack_all<<<(int)((T6 + 255) / 256), 256>>>(values, coords, W_vqk, W_vv, W_cqk, W_ov,
                                               b_vqk, b_vv, gm_vqk, b_cqk, gm_cqk, lam);

    const int gsm = 98304;
    cudaFuncSetAttribute(gemm_mma, cudaFuncAttributeMaxDynamicSharedMemorySize, gsm);

    // 2) coords projection (K=128, fp16 out), 3) values projection (K=384, fp16 out)
    gemm_mma<<<dim3(768 / 128,  NTOK / 128), 256, gsm>>>(Ac, Bc, biasc, pc, 128,  768, ssc, igc, 2, 1);
    gemm_mma<<<dim3(1152 / 128, NTOK / 128), 256, gsm>>>(Av, Bv, biasv, pv, 384, 1152, ssv, igv, 1, 1);

    // 4) attention
    cudaFuncSetAttribute(attn_k, cudaFuncAttributeMaxDynamicSharedMemorySize, ASMB);
    attn_k<<<Bb * NH_ * NW_ * NW_, 256, ASMB>>>(pos);

    // 5) output projection (K=384, fp32 out to harness buffer)
    gemm_mma<<<dim3(384 / 128, NTOK / 128), 256, gsm>>>(Yb, Bo, b_ov, out, 384, 384, nullptr, nullptr, 0, 0);
}

// round 16
// speedup vs baseline: 3.3687x; 1.1350x over previous
#include <cuda_runtime.h>
#include <cuda_fp16.h>
#include <math.h>
#include <stdint.h>

#define Bb   2
#define Hh   192
#define Wd   192
#define NH_  8
#define HD_  48
#define NW_  24
#define NTOK (Bb*Hh*Wd)   // 73728

// ---------------- scratch (device globals; no runtime alloc) ----------------
__device__ __half g_Av[(size_t)NTOK * 384];    // values fp16
__device__ __half g_Ac[(size_t)NTOK * 128];    // coords fp16
__device__ __half g_Yb[(size_t)NTOK * 384];    // attn out fp16
__device__ __half g_Bv[1152 * 384];            // W' permuted+γ-folded vqk|vv
__device__ __half g_Bc[768 * 128];             // W' permuted+γλ-folded cqk
__device__ __half g_Bo[384 * 384];             // W' ov
__device__ float g_biasv[1152];                // γ-folded permuted bias
__device__ float g_biasc[768];
__device__ float g_igv[1152];                  // 1/γ (pre-norm recovery)
__device__ float g_igc[768];                   // 1/(γ[λ])
__device__ __half g_pv[(size_t)NTOK * 1152];   // proj out fp16: [Q|K|V] head-major, +bias
__device__ __half g_pc[(size_t)NTOK * 768];    // proj out fp16: [Qc|Kc]
__device__ float g_ssv[NTOK];
__device__ float g_ssc[NTOK];

// ------------------------------ PTX helpers ---------------------------------
__device__ __forceinline__ uint32_t s2u(const void* p) {
    uint32_t a;
    asm("{ .reg .u64 t; cvta.to.shared.u64 t, %1; cvt.u32.u64 %0, t; }" : "=r"(a) : "l"(p));
    return a;
}
__device__ __forceinline__ void cp16(uint32_t dst, const void* src) {
    asm volatile("cp.async.cg.shared.global [%0], [%1], 16;" :: "r"(dst), "l"(src));
}
#define CP_COMMIT() asm volatile("cp.async.commit_group;" ::: "memory")
#define CP_WAIT1()  asm volatile("cp.async.wait_group 1;" ::: "memory")
#define CP_WAIT0()  asm volatile("cp.async.wait_group 0;" ::: "memory")

#define LDSM4(R0,R1,R2,R3,ADDR) \
    asm volatile("ldmatrix.sync.aligned.m8n8.x4.shared.b16 {%0,%1,%2,%3}, [%4];" \
                 : "=r"(R0), "=r"(R1), "=r"(R2), "=r"(R3) : "r"(ADDR))
#define LDSM4T(R0,R1,R2,R3,ADDR) \
    asm volatile("ldmatrix.sync.aligned.m8n8.x4.trans.shared.b16 {%0,%1,%2,%3}, [%4];" \
                 : "=r"(R0), "=r"(R1), "=r"(R2), "=r"(R3) : "r"(ADDR))
#define LDSM2T(R0,R1,ADDR) \
    asm volatile("ldmatrix.sync.aligned.m8n8.x2.trans.shared.b16 {%0,%1}, [%2];" \
                 : "=r"(R0), "=r"(R1) : "r"(ADDR))

#define MMA16816(D,A0,A1,A2,A3,B0,B1) \
    asm volatile("mma.sync.aligned.m16n8k16.row.col.f32.f16.f16.f32 " \
                 "{%0,%1,%2,%3},{%4,%5,%6,%7},{%8,%9},{%0,%1,%2,%3};" \
                 : "+f"(D[0]), "+f"(D[1]), "+f"(D[2]), "+f"(D[3]) \
                 : "r"(A0), "r"(A1), "r"(A2), "r"(A3), "r"(B0), "r"(B1))

__device__ __forceinline__ uint32_t packh(__half a, __half b) {
    return (uint32_t)__half_as_ushort(a) | ((uint32_t)__half_as_ushort(b) << 16);
}
__device__ __forceinline__ uint32_t scaleh2(uint32_t h2, float f) {
    __half2 h = *(__half2*)&h2;
    float2 v = __half22float2(h);
    __half2 o = __floats2half2_rn(v.x * f, v.y * f);
    return *(uint32_t*)&o;
}
__device__ __forceinline__ uint4 cvt8(const float4 a, const float4 b) {
    uint4 o;
    __half2 h;
    h = __floats2half2_rn(a.x, a.y); o.x = *(uint32_t*)&h;
    h = __floats2half2_rn(a.z, a.w); o.y = *(uint32_t*)&h;
    h = __floats2half2_rn(b.x, b.y); o.z = *(uint32_t*)&h;
    h = __floats2half2_rn(b.z, b.w); o.w = *(uint32_t*)&h;
    return o;
}

// ---------------- fused pack + metaperm + ss-zero (1 launch) -----------------
// A-sections vectorized: 8 elements per thread.
#define P0 ((size_t)NTOK * 48)          // A_v: NTOK*384/8
#define P1 (P0 + (size_t)NTOK * 16)     // A_c: NTOK*128/8
#define P2 (P1 + 1152 * 384)
#define P3 (P2 + 768 * 128)
#define P4 (P3 + 384 * 384)
#define P5 (P4 + NTOK)
#define P6 (P5 + 1920)
__global__ void pack_all(const float* __restrict__ values, const float* __restrict__ coords,
                         const float* __restrict__ Wqk, const float* __restrict__ Wvv,
                         const float* __restrict__ Wcqk, const float* __restrict__ Wov,
                         const float* __restrict__ bqk, const float* __restrict__ bvv,
                         const float* __restrict__ gvqk,
                         const float* __restrict__ bcqk, const float* __restrict__ gcqk,
                         const float* __restrict__ lamp)
{
    size_t i = (size_t)blockIdx.x * 256 + threadIdx.x;
    if (i < P0) {                       // A_v fp16, vec8
        const float4 a = ((const float4*)values)[i * 2];
        const float4 b = ((const float4*)values)[i * 2 + 1];
        ((uint4*)g_Av)[i] = cvt8(a, b);
    } else if (i < P1) {                // A_c fp16, vec8
        const size_t j = i - P0;
        const float4 a = ((const float4*)coords)[j * 2];
        const float4 b = ((const float4*)coords)[j * 2 + 1];
        ((uint4*)g_Ac)[j] = cvt8(a, b);
    } else if (i < P2) {                // B_v permuted [Q|K|V] head-major, γ-folded
        int j = (int)(i - P1);
        int n = j / 384, k = j - (j / 384) * 384;
        const int blk = n / 384;
        const int hm = (n % 384) / 48, e = n % 48;
        const int c = 3 * (e * 8 + hm) + blk;
        float w = (c < 768) ? Wqk[(size_t)k * 768 + c] : Wvv[(size_t)k * 384 + (c - 768)];
        const float gf = (c < 768) ? gvqk[c] : 1.0f;
        g_Bv[(size_t)n * 384 + k] = __float2half_rn(w * gf);
    } else if (i < P3) {                // B_c permuted [Qc|Kc], γλ-folded
        int j = (int)(i - P2);
        int n = j / 128, k = j - (j / 128) * 128;
        const int blk = n / 384;
        const int hm = (n % 384) / 48, e = n % 48;
        const int c = 2 * (e * 8 + hm) + blk;
        const float gf = gcqk[c] * (blk == 0 ? lamp[0] : 1.0f);
        g_Bc[(size_t)n * 128 + k] = __float2half_rn(Wcqk[(size_t)k * 768 + c] * gf);
    } else if (i < P4) {                // B_o
        int j = (int)(i - P3);
        int n = j / 384, k = j - (j / 384) * 384;
        g_Bo[(size_t)n * 384 + k] = __float2half_rn(Wov[(size_t)k * 384 + n]);
    } else if (i < P5) {                // ss zero
        const int t = (int)(i - P4);
        g_ssv[t] = 0.f; g_ssc[t] = 0.f;
    } else if (i < P6) {                // bias + 1/γ permute
        int n = (int)(i - P5);
        if (n < 1152) {
            const int blk = n / 384, hm = (n % 384) / 48, e = n % 48;
            const int c = 3 * (e * 8 + hm) + blk;
            const float gf = (c < 768) ? gvqk[c] : 1.0f;
            g_biasv[n] = ((c < 768) ? bqk[c] : bvv[c - 768]) * gf;
            g_igv[n]   = (gf != 0.f) ? 1.f / gf : 0.f;
        } else {
            const int n2 = n - 1152;
            const int blk = n2 / 384, hm = (n2 % 384) / 48, e = n2 % 48;
            const int c = 2 * (e * 8 + hm) + blk;
            const float gf = gcqk[c] * (blk == 0 ? lamp[0] : 1.0f);
            g_biasc[n2] = bcqk[c] * gf;
            g_igc[n2]   = (gf != 0.f) ? 1.f / gf : 0.f;
        }
    }
}

// --------- HMMA GEMM core (macro-shared body via function w/ params) ---------
// 3-stage cp.async pipeline, ONE __syncthreads per K-chunk.
__device__ __forceinline__ void gemm_body(
    const __half* A, const __half* B, const float* bias, void* Cout,
    int Kp, int ldc, float* ss, const float* ig, int smode, int chalf,
    int mB, int n0, char* smem)
{
    const uint32_t sb = s2u(smem);
    const int tid = threadIdx.x, lane = tid & 31, wid = tid >> 5;
    const int wm = (wid & 3) << 5;
    const int wn = (wid >> 2) << 6;

    const int lrow = tid >> 3, lu = tid & 7;
    const size_t ldk = (size_t)Kp * 2;
    const char* Asrc = (const char*)A + (size_t)(mB + lrow) * ldk + lu * 16;
    const char* Bsrc = (const char*)B + (size_t)(n0 + lrow) * ldk + lu * 16;
    uint32_t dsto[4];
#pragma unroll
    for (int r = 0; r < 4; r++) {
        const int row = lrow + r * 32;
        dsto[r] = row * 128 + ((lu ^ (row & 7)) << 4);
    }

    const int q = lane >> 3, tr = lane & 7;
    const int qA = q >> 1, qB = q & 1;
    uint32_t rowoffA[2], xrA[2];
#pragma unroll
    for (int fm = 0; fm < 2; fm++) {
        const int row = wm + fm * 16 + tr + ((q & 1) << 3);
        rowoffA[fm] = row * 128; xrA[fm] = row & 7;
    }
    uint32_t rowoffB[4], xrB[4];
#pragma unroll
    for (int fn = 0; fn < 4; fn++) {
        const int row = wn + fn * 16 + tr + ((q >> 1) << 3);
        rowoffB[fn] = row * 128; xrB[fn] = row & 7;
    }

    float acc[2][8][4] = {};

    const int NC = Kp >> 6;
#pragma unroll
    for (int pc = 0; pc < 2; pc++) {
        if (pc < NC) {
            const uint32_t ab = sb + pc * 16384u;
            const uint32_t bb = sb + 49152u + pc * 16384u;
            const char* An = Asrc + (size_t)pc * 128;
            const char* Bn = Bsrc + (size_t)pc * 128;
#pragma unroll
            for (int r = 0; r < 4; r++) {
                cp16(ab + dsto[r], An + (size_t)r * 32 * ldk);
                cp16(bb + dsto[r], Bn + (size_t)r * 32 * ldk);
            }
            CP_COMMIT();
        }
    }

    int bidx = 0, pidx = 2;
    for (int c = 0; c < NC; c++) {
        if (c + 1 < NC) { CP_WAIT1(); } else { CP_WAIT0(); }
        __syncthreads();
        if (c + 2 < NC) {
            const uint32_t ab = sb + pidx * 16384u;
            const uint32_t bb = sb + 49152u + pidx * 16384u;
            const char* An = Asrc + (size_t)(c + 2) * 128;
            const char* Bn = Bsrc + (size_t)(c + 2) * 128;
#pragma unroll
            for (int r = 0; r < 4; r++) {
                cp16(ab + dsto[r], An + (size_t)r * 32 * ldk);
                cp16(bb + dsto[r], Bn + (size_t)r * 32 * ldk);
            }
            CP_COMMIT();
            if (++pidx == 3) pidx = 0;
        }

        const uint32_t Ab = sb + bidx * 16384u;
        const uint32_t Bs = sb + 49152u + bidx * 16384u;
#pragma unroll
        for (int ks = 0; ks < 4; ks++) {
            uint32_t a[2][4], bf[4][4];
#pragma unroll
            for (int fm = 0; fm < 2; fm++) {
                const uint32_t ad = Ab + rowoffA[fm] + ((((uint32_t)(ks * 2 + qA)) ^ xrA[fm]) << 4);
                LDSM4(a[fm][0], a[fm][1], a[fm][2], a[fm][3], ad);
            }
#pragma unroll
            for (int fn = 0; fn < 4; fn++) {
                const uint32_t bd = Bs + rowoffB[fn] + ((((uint32_t)(ks * 2 + qB)) ^ xrB[fn]) << 4);
                LDSM4(bf[fn][0], bf[fn][1], bf[fn][2], bf[fn][3], bd);
            }
#pragma unroll
            for (int fm = 0; fm < 2; fm++)
#pragma unroll
                for (int fn = 0; fn < 4; fn++) {
                    MMA16816(acc[fm][2 * fn],     a[fm][0], a[fm][1], a[fm][2], a[fm][3],
                             bf[fn][0], bf[fn][1]);
                    MMA16816(acc[fm][2 * fn + 1], a[fm][0], a[fm][1], a[fm][2], a[fm][3],
                             bf[fn][2], bf[fn][3]);
                }
        }
        if (++bidx == 3) bidx = 0;
    }

    const int er = lane >> 2, ec = (lane & 3) << 1;
    float ssa[2][2] = {{0.f, 0.f}, {0.f, 0.f}};
#pragma unroll
    for (int fm = 0; fm < 2; fm++) {
#pragma unroll
        for (int fn = 0; fn < 8; fn++) {
            const int gm = mB + wm + fm * 16 + er;
            const int gn = n0 + wn + fn * 8 + ec;
            const float2 bv = *(const float2*)(bias + gn);
            float2 o0, o1;
            o0.x = acc[fm][fn][0] + bv.x; o0.y = acc[fm][fn][1] + bv.y;
            o1.x = acc[fm][fn][2] + bv.x; o1.y = acc[fm][fn][3] + bv.y;
            if (chalf) {
                __half* Ch = (__half*)Cout;
                *(__half2*)(Ch + (size_t)gm * ldc + gn) = __floats2half2_rn(o0.x, o0.y);
                *(__half2*)(Ch + (size_t)(gm + 8) * ldc + gn) = __floats2half2_rn(o1.x, o1.y);
            } else {
                float* Cf = (float*)Cout;
                *(float2*)(Cf + (size_t)gm * ldc + gn) = o0;
                *(float2*)(Cf + (size_t)(gm + 8) * ldc + gn) = o1;
            }
            if (smode) {
                const float2 iv = *(const float2*)(ig + gn);
                const float p0 = o0.x * iv.x, p1 = o0.y * iv.y;
                const float p2 = o1.x * iv.x, p3 = o1.y * iv.y;
                const bool m0 = (smode == 2) || ((gn % 48) < 32);
                const bool m1 = (smode == 2) || (((gn + 1) % 48) < 32);
                ssa[fm][0] += (m0 ? p0 * p0 : 0.f) + (m1 ? p1 * p1 : 0.f);
                ssa[fm][1] += (m0 ? p2 * p2 : 0.f) + (m1 ? p3 * p3 : 0.f);
            }
        }
    }
    if (smode) {
#pragma unroll
        for (int fm = 0; fm < 2; fm++)
#pragma unroll
            for (int h = 0; h < 2; h++) {
                float v = ssa[fm][h];
                v += __shfl_xor_sync(0xffffffffu, v, 1);
                v += __shfl_xor_sync(0xffffffffu, v, 2);
                if ((lane & 3) == 0)
                    atomicAdd(ss + mB + wm + fm * 16 + er + h * 8, v);
            }
    }
}

// fused coords+values projection: blockIdx.x<6 -> coords, else values
__global__ __launch_bounds__(256, 2) void gemm_cv()
{
    extern __shared__ __align__(1024) char smem[];
    const int bx = blockIdx.x;
    const int mB = blockIdx.y * 128;
    if (bx < 6) {
        gemm_body(g_Ac, g_Bc, g_biasc, g_pc, 128, 768, g_ssc, g_igc, 2, 1,
                  mB, bx * 128, smem);
    } else {
        gemm_body(g_Av, g_Bv, g_biasv, g_pv, 384, 1152, g_ssv, g_igv, 1, 1,
                  mB, (bx - 6) * 128, smem);
    }
}
// output projection (fp32 out to harness buffer)
__global__ __launch_bounds__(256, 2) void gemm_o(float* __restrict__ out,
                                                 const float* __restrict__ b_ov)
{
    extern __shared__ __align__(1024) char smem[];
    gemm_body(g_Yb, g_Bo, b_ov, out, 384, 384, nullptr, nullptr, 0, 0,
              blockIdx.y * 128, blockIdx.x * 128, smem);
}

// ---------------------------- windowed attention ----------------------------
// Q,K,P,V all fp16. V stored TOK-MAJOR (112B rows, conflict-free trans-LDSM).
// Ph ALIASES Q2 (dead after QK MMA).
#define Q2_OFF  0u            // 64 x 208  13312
#define K2_OFF  13312u        // 13312
#define PH_OFF  0u            // 64 x 144 (9216) — aliases Q2
#define VTH_OFF 26624u        // 64 tok-rows x 112B = 7168
#define PS_OFF  33792u        // 225 f32
#define TS_OFF  34692u
#define RV_OFF  34948u
#define RC_OFF  35204u
#define MR_OFF  35460u        // 2 x 64 f32
#define SR_OFF  35972u        // 2 x 64 f32
#define ASMB    36484
__global__ __launch_bounds__(256, 4) void attn_k(const float* __restrict__ pos_emb)
{
    extern __shared__ __align__(128) char smx[];
    float* Ps = (float*)(smx + PS_OFF);
    int*   ts = (int*)(smx + TS_OFF);
    float* rv = (float*)(smx + RV_OFF);
    float* rc = (float*)(smx + RC_OFF);
    float* mred = (float*)(smx + MR_OFF);
    float* sred = (float*)(smx + SR_OFF);

    int blk = blockIdx.x;
    const int wx = blk % NW_; blk /= NW_;
    const int wy = blk % NW_; blk /= NW_;
    const int head = blk % NH_;
    const int b = blk / NH_;
    const int tid = threadIdx.x;

    if (tid < 64) {
        const int ry = tid >> 3, rx = tid & 7;
        const int y = (wy * 8 + ry + 4) % Hh;
        const int x = (wx * 8 + rx + 4) % Wd;
        const int t = b * (Hh * Wd) + y * Wd + x;
        ts[tid] = t;
        rv[tid] = rsqrtf(g_ssv[t] * (1.f / 768.f) + 1e-6f);
        rc[tid] = rsqrtf(g_ssc[t] * (1.f / 768.f) + 1e-6f);
    }
    for (int i = tid; i < 225; i += 256) Ps[i] = pos_emb[i];
    __syncthreads();

    const int hb = head * 48;

    // ---- Q/K gather: fp16 source, uint4 = 8 halves per load ----
    for (int i = tid; i < 64 * 12; i += 256) {
        const int tok = i / 12, u = i - tok * 12;
        const int t = ts[tok];
        uint4 qr, kr;
        float f;
        int ch;
        if (u < 6) {
            ch = u * 8;
            const __half* pvr = g_pv + (size_t)t * 1152;
            qr = *(const uint4*)(pvr + hb + ch);
            kr = *(const uint4*)(pvr + 384 + hb + ch);
            f = (u < 4) ? rv[tok] : 1.f;
        } else {
            const int c2 = (u - 6) * 8;
            ch = 48 + c2;
            const __half* pcr = g_pc + (size_t)t * 768;
            qr = *(const uint4*)(pcr + hb + c2);
            kr = *(const uint4*)(pcr + 384 + hb + c2);
            f = rc[tok];
        }
        uint4 qo, ko;
        qo.x = scaleh2(qr.x, f); qo.y = scaleh2(qr.y, f);
        qo.z = scaleh2(qr.z, f); qo.w = scaleh2(qr.w, f);
        ko.x = scaleh2(kr.x, f); ko.y = scaleh2(kr.y, f);
        ko.z = scaleh2(kr.z, f); ko.w = scaleh2(kr.w, f);
        *(uint4*)(smx + Q2_OFF + tok * 208 + ch * 2) = qo;
        *(uint4*)(smx + K2_OFF + tok * 208 + ch * 2) = ko;
    }
    // ---- V gather: tok-major (112B rows), single uint4 store ----
    for (int i = tid; i < 64 * 6; i += 256) {
        const int tok = i / 6, u = i - tok * 6;
        const int t = ts[tok];
        uint4 raw = *(const uint4*)(g_pv + (size_t)t * 1152 + 768 + hb + u * 8);
        const float f = (u < 4) ? rv[tok] : 1.f;
        uint4 o;
        o.x = scaleh2(raw.x, f); o.y = scaleh2(raw.y, f);
        o.z = scaleh2(raw.z, f); o.w = scaleh2(raw.w, f);
        *(uint4*)(smx + VTH_OFF + tok * 112 + u * 16) = o;
    }
    __syncthreads();

    // ---- QK^T via HMMA: 6 k16 steps ----
    const int lane = tid & 31, w = tid >> 5;
    const int wq = w & 3, wk = w >> 2;
    const int q = lane >> 3, tr = lane & 7;
    const uint32_t sQ = s2u(smx + Q2_OFF), sK = s2u(smx + K2_OFF);
    const uint32_t aBase = sQ + (uint32_t)(16 * wq + tr + ((q & 1) << 3)) * 208 + ((q >> 1) << 4);
    uint32_t bBase[2];
    bBase[0] = sK + (uint32_t)(32 * wk + tr + ((q >> 1) << 3)) * 208 + ((q & 1) << 4);
    bBase[1] = bBase[0] + 16 * 208;

    float acc[4][4] = {};
#pragma unroll
    for (int s = 0; s < 6; s++) {
        uint32_t a0, a1, a2, a3;
        LDSM4(a0, a1, a2, a3, aBase + s * 32);
#pragma unroll
        for (int fn = 0; fn < 2; fn++) {
            uint32_t b0, b1, b2, b3;
            LDSM4(b0, b1, b2, b3, bBase[fn] + s * 32);
            MMA16816(acc[2 * fn],     a0, a1, a2, a3, b0, b1);
            MMA16816(acc[2 * fn + 1], a0, a1, a2, a3, b2, b3);
        }
    }

    // ---- register epilogue: scale + bias + mask; ONE-ROUND softmax ----
    const float scale = 0.14433756729740643f;   // 1/sqrt(48)
    const bool lastR = (wy == NW_ - 1), lastC = (wx == NW_ - 1);
    const int i0 = 16 * wq + (lane >> 2);
    const int jbase = 32 * wk + ((lane & 3) << 1);
    float rmax[2] = {-INFINITY, -INFINITY};
#pragma unroll
    for (int f = 0; f < 4; f++) {
#pragma unroll
        for (int r = 0; r < 4; r++) {
            const int i = i0 + ((r >> 1) << 3);
            const int j = jbase + 8 * f + (r & 1);
            float v = acc[f][r] * scale
                    + Ps[((j >> 3) - (i >> 3) + 7) * 15 + ((j & 7) - (i & 7) + 7)];
            if (lastR && (((i >= 32) ? 1 : 0) ^ ((j >= 32) ? 1 : 0)))           v = -INFINITY;
            if (lastC && ((((i & 7) >= 4) ? 1 : 0) ^ (((j & 7) >= 4) ? 1 : 0))) v = -INFINITY;
            acc[f][r] = v;
            rmax[r >> 1] = fmaxf(rmax[r >> 1], v);
        }
    }
    float ml[2], rsum[2] = {0.f, 0.f};
#pragma unroll
    for (int h = 0; h < 2; h++) {
        rmax[h] = fmaxf(rmax[h], __shfl_xor_sync(0xffffffffu, rmax[h], 1));
        rmax[h] = fmaxf(rmax[h], __shfl_xor_sync(0xffffffffu, rmax[h], 2));
        ml[h] = fmaxf(rmax[h], -1e30f);
    }
#pragma unroll
    for (int f = 0; f < 4; f++) {
#pragma unroll
        for (int r = 0; r < 4; r++) {
            const float e = __expf(acc[f][r] - ml[r >> 1]);
            acc[f][r] = e;
            rsum[r >> 1] += e;
        }
    }
#pragma unroll
    for (int h = 0; h < 2; h++) {
        rsum[h] += __shfl_xor_sync(0xffffffffu, rsum[h], 1);
        rsum[h] += __shfl_xor_sync(0xffffffffu, rsum[h], 2);
    }
    if ((lane & 3) == 0) {
        mred[wk * 64 + i0]     = ml[0];
        mred[wk * 64 + i0 + 8] = ml[1];
        sred[wk * 64 + i0]     = rsum[0];
        sred[wk * 64 + i0 + 8] = rsum[1];
    }
    __syncthreads();   // also: all QK ldmatrix reads of Q2 done -> Ph alias safe
    float fac[2];
#pragma unroll
    for (int h = 0; h < 2; h++) {
        const int row = i0 + h * 8;
        const float m0 = mred[row], m1 = mred[64 + row];
        const float g = fmaxf(m0, m1);
        const float s = sred[row] * __expf(m0 - g) + sred[64 + row] * __expf(m1 - g);
        fac[h] = __expf(ml[h] - g) / s;
    }

    // ---- write P (fp16) straight from registers ----
#pragma unroll
    for (int h = 0; h < 2; h++) {
        const int i = i0 + h * 8;
        char* PhB = smx + PH_OFF + i * 144;
#pragma unroll
        for (int f = 0; f < 4; f++) {
            const float p0 = acc[f][h * 2] * fac[h];
            const float p1 = acc[f][h * 2 + 1] * fac[h];
            *(uint32_t*)(PhB + (jbase + 8 * f) * 2) =
                packh(__float2half_rn(p0), __float2half_rn(p1));
        }
    }
    __syncthreads();

    // ---- AV via HMMA: P (row-major A) x V (tok-major, trans-LDSM B) ----
    const int wq2 = w & 3, wn2 = w >> 2;
    const uint32_t sPh = s2u(smx + PH_OFF);
    const uint32_t sVh = s2u(smx + VTH_OFF);
    const uint32_t aOff = (uint32_t)(16 * wq2 + tr + ((q & 1) << 3)) * 144 + ((q >> 1) << 4);
    const uint32_t vb4 = sVh + (uint32_t)(lane & 15) * 112
                             + (uint32_t)(24 * wn2 + ((lane >> 4) << 3)) * 2;
    const uint32_t vb2 = sVh + (uint32_t)(lane & 15) * 112
                             + (uint32_t)(24 * wn2 + 16) * 2;

    float acc3[3][4] = {};
#pragma unroll
    for (int ks = 0; ks < 4; ks++) {
        uint32_t a0, a1, a2, a3, b0, b1, b2, b3, b4, b5;
        LDSM4(a0, a1, a2, a3, sPh + aOff + ks * 32);
        LDSM4T(b0, b1, b2, b3, vb4 + ks * 1792);
        LDSM2T(b4, b5, vb2 + ks * 1792);
        MMA16816(acc3[0], a0, a1, a2, a3, b0, b1);
        MMA16816(acc3[1], a0, a1, a2, a3, b2, b3);
        MMA16816(acc3[2], a0, a1, a2, a3, b4, b5);
    }

    // ---- output: fp16 -> g_Yb ----
    const int er2 = lane >> 2, ec2 = (lane & 3) << 1;
#pragma unroll
    for (int h = 0; h < 2; h++) {
        const int i = 16 * wq2 + er2 + h * 8;
        const int Y = wy * 8 + (i >> 3), X = wx * 8 + (i & 7);
        const size_t t = ((size_t)b * Hh + Y) * Wd + X;
        __half* op = g_Yb + t * 384 + hb;
#pragma unroll
        for (int f = 0; f < 3; f++) {
            const int e = 24 * wn2 + 8 * f + ec2;
            *(__half2*)(op + e) = __halves2half2(__float2half_rn(acc3[f][h * 2]),
                                                 __float2half_rn(acc3[f][h * 2 + 1]));
        }
    }
}

// ------------------------------- launcher -----------------------------------
extern "C" void kernel_launch(void* const* d_in, const int* in_sizes, int n_in,
                              void* d_out, int out_size)
{
    const float* values = (const float*)d_in[0];
    const float* coords = (const float*)d_in[1];
    const float* W_vqk  = (const float*)d_in[2];
    const float* b_vqk  = (const float*)d_in[3];
    const float* gm_vqk = (const float*)d_in[4];
    const float* W_vv   = (const float*)d_in[5];
    const float* b_vv   = (const float*)d_in[6];
    const float* W_cqk  = (const float*)d_in[7];
    const float* b_cqk  = (const float*)d_in[8];
    const float* gm_cqk = (const float*)d_in[9];
    const float* lam    = (const float*)d_in[10];
    const float* pos    = (const float*)d_in[11];
    const float* W_ov   = (const float*)d_in[12];
    const float* b_ov   = (const float*)d_in[13];
    float* out = (float*)d_out;

    // 1) fused pack (vectorized A) + ss-zero + bias/invγ permute
    pack_all<<<(int)((P6 + 255) / 256), 256>>>(values, coords, W_vqk, W_vv, W_cqk, W_ov,
                                               b_vqk, b_vv, gm_vqk, b_cqk, gm_cqk, lam);

    const int gsm = 98304;
    cudaFuncSetAttribute(gemm_cv, cudaFuncAttributeMaxDynamicSharedMemorySize, gsm);
    cudaFuncSetAttribute(gemm_o,  cudaFuncAttributeMaxDynamicSharedMemorySize, gsm);

    // 2) fused coords+values projections (single launch)
    gemm_cv<<<dim3(15, NTOK / 128), 256, gsm>>>();

    // 3) attention
    cudaFuncSetAttribute(attn_k, cudaFuncAttributeMaxDynamicSharedMemorySize, ASMB);
    attn_k<<<Bb * NH_ * NW_ * NW_, 256, ASMB>>>(pos);

    // 4) output projection
    gemm_o<<<dim3(384 / 128, NTOK / 128), 256, gsm>>>(out, b_ov);
}

// round 17
// speedup vs baseline: 3.3753x; 1.0020x over previous
#include <cuda_runtime.h>
#include <cuda_fp16.h>
#include <math.h>
#include <stdint.h>

#define Bb   2
#define Hh   192
#define Wd   192
#define NH_  8
#define HD_  48
#define NW_  24
#define NTOK (Bb*Hh*Wd)   // 73728

// ---------------- scratch (device globals; no runtime alloc) ----------------
__device__ __half g_Av[(size_t)NTOK * 384];    // values fp16
__device__ __half g_Ac[(size_t)NTOK * 128];    // coords fp16
__device__ __half g_Yb[(size_t)NTOK * 384];    // attn out fp16
__device__ __half g_Bv[1152 * 384];            // W' permuted+γ-folded vqk|vv
__device__ __half g_Bc[768 * 128];             // W' permuted+γλ-folded cqk
__device__ __half g_Bo[384 * 384];             // W' ov
__device__ float g_biasv[1152];                // γ-folded permuted bias
__device__ float g_biasc[768];
__device__ float g_igv[1152];                  // 1/γ (pre-norm recovery)
__device__ float g_igc[768];                   // 1/(γ[λ])
__device__ __half g_pv[(size_t)NTOK * 1152];   // proj out fp16: [Q|K|V] head-major, +bias
__device__ __half g_pc[(size_t)NTOK * 768];    // proj out fp16: [Qc|Kc]
__device__ float g_ssv[NTOK];
__device__ float g_ssc[NTOK];

// ------------------------------ PTX helpers ---------------------------------
__device__ __forceinline__ uint32_t s2u(const void* p) {
    uint32_t a;
    asm("{ .reg .u64 t; cvta.to.shared.u64 t, %1; cvt.u32.u64 %0, t; }" : "=r"(a) : "l"(p));
    return a;
}
__device__ __forceinline__ void cp16(uint32_t dst, const void* src) {
    asm volatile("cp.async.cg.shared.global [%0], [%1], 16;" :: "r"(dst), "l"(src));
}
#define CP_COMMIT() asm volatile("cp.async.commit_group;" ::: "memory")
#define CP_WAIT1()  asm volatile("cp.async.wait_group 1;" ::: "memory")
#define CP_WAIT0()  asm volatile("cp.async.wait_group 0;" ::: "memory")

#define LDSM4(R0,R1,R2,R3,ADDR) \
    asm volatile("ldmatrix.sync.aligned.m8n8.x4.shared.b16 {%0,%1,%2,%3}, [%4];" \
                 : "=r"(R0), "=r"(R1), "=r"(R2), "=r"(R3) : "r"(ADDR))
#define LDSM4T(R0,R1,R2,R3,ADDR) \
    asm volatile("ldmatrix.sync.aligned.m8n8.x4.trans.shared.b16 {%0,%1,%2,%3}, [%4];" \
                 : "=r"(R0), "=r"(R1), "=r"(R2), "=r"(R3) : "r"(ADDR))
#define LDSM2T(R0,R1,ADDR) \
    asm volatile("ldmatrix.sync.aligned.m8n8.x2.trans.shared.b16 {%0,%1}, [%2];" \
                 : "=r"(R0), "=r"(R1) : "r"(ADDR))

#define MMA16816(D,A0,A1,A2,A3,B0,B1) \
    asm volatile("mma.sync.aligned.m16n8k16.row.col.f32.f16.f16.f32 " \
                 "{%0,%1,%2,%3},{%4,%5,%6,%7},{%8,%9},{%0,%1,%2,%3};" \
                 : "+f"(D[0]), "+f"(D[1]), "+f"(D[2]), "+f"(D[3]) \
                 : "r"(A0), "r"(A1), "r"(A2), "r"(A3), "r"(B0), "r"(B1))

__device__ __forceinline__ uint32_t packh(__half a, __half b) {
    return (uint32_t)__half_as_ushort(a) | ((uint32_t)__half_as_ushort(b) << 16);
}
__device__ __forceinline__ uint32_t scaleh2(uint32_t h2, float f) {
    __half2 h = *(__half2*)&h2;
    float2 v = __half22float2(h);
    __half2 o = __floats2half2_rn(v.x * f, v.y * f);
    return *(uint32_t*)&o;
}
__device__ __forceinline__ uint4 cvt8(const float4 a, const float4 b) {
    uint4 o;
    __half2 h;
    h = __floats2half2_rn(a.x, a.y); o.x = *(uint32_t*)&h;
    h = __floats2half2_rn(a.z, a.w); o.y = *(uint32_t*)&h;
    h = __floats2half2_rn(b.x, b.y); o.z = *(uint32_t*)&h;
    h = __floats2half2_rn(b.z, b.w); o.w = *(uint32_t*)&h;
    return o;
}

// ---------------- fused pack + metaperm + ss-zero (1 launch) -----------------
#define P0 ((size_t)NTOK * 48)          // A_v: NTOK*384/8
#define P1 (P0 + (size_t)NTOK * 16)     // A_c: NTOK*128/8
#define P2 (P1 + 1152 * 384)
#define P3 (P2 + 768 * 128)
#define P4 (P3 + 384 * 384)
#define P5 (P4 + NTOK)
#define P6 (P5 + 1920)
__global__ void pack_all(const float* __restrict__ values, const float* __restrict__ coords,
                         const float* __restrict__ Wqk, const float* __restrict__ Wvv,
                         const float* __restrict__ Wcqk, const float* __restrict__ Wov,
                         const float* __restrict__ bqk, const float* __restrict__ bvv,
                         const float* __restrict__ gvqk,
                         const float* __restrict__ bcqk, const float* __restrict__ gcqk,
                         const float* __restrict__ lamp)
{
    size_t i = (size_t)blockIdx.x * 256 + threadIdx.x;
    if (i < P0) {
        const float4 a = ((const float4*)values)[i * 2];
        const float4 b = ((const float4*)values)[i * 2 + 1];
        ((uint4*)g_Av)[i] = cvt8(a, b);
    } else if (i < P1) {
        const size_t j = i - P0;
        const float4 a = ((const float4*)coords)[j * 2];
        const float4 b = ((const float4*)coords)[j * 2 + 1];
        ((uint4*)g_Ac)[j] = cvt8(a, b);
    } else if (i < P2) {
        int j = (int)(i - P1);
        int n = j / 384, k = j - (j / 384) * 384;
        const int blk = n / 384;
        const int hm = (n % 384) / 48, e = n % 48;
        const int c = 3 * (e * 8 + hm) + blk;
        float w = (c < 768) ? Wqk[(size_t)k * 768 + c] : Wvv[(size_t)k * 384 + (c - 768)];
        const float gf = (c < 768) ? gvqk[c] : 1.0f;
        g_Bv[(size_t)n * 384 + k] = __float2half_rn(w * gf);
    } else if (i < P3) {
        int j = (int)(i - P2);
        int n = j / 128, k = j - (j / 128) * 128;
        const int blk = n / 384;
        const int hm = (n % 384) / 48, e = n % 48;
        const int c = 2 * (e * 8 + hm) + blk;
        const float gf = gcqk[c] * (blk == 0 ? lamp[0] : 1.0f);
        g_Bc[(size_t)n * 128 + k] = __float2half_rn(Wcqk[(size_t)k * 768 + c] * gf);
    } else if (i < P4) {
        int j = (int)(i - P3);
        int n = j / 384, k = j - (j / 384) * 384;
        g_Bo[(size_t)n * 384 + k] = __float2half_rn(Wov[(size_t)k * 384 + n]);
    } else if (i < P5) {
        const int t = (int)(i - P4);
        g_ssv[t] = 0.f; g_ssc[t] = 0.f;
    } else if (i < P6) {
        int n = (int)(i - P5);
        if (n < 1152) {
            const int blk = n / 384, hm = (n % 384) / 48, e = n % 48;
            const int c = 3 * (e * 8 + hm) + blk;
            const float gf = (c < 768) ? gvqk[c] : 1.0f;
            g_biasv[n] = ((c < 768) ? bqk[c] : bvv[c - 768]) * gf;
            g_igv[n]   = (gf != 0.f) ? 1.f / gf : 0.f;
        } else {
            const int n2 = n - 1152;
            const int blk = n2 / 384, hm = (n2 % 384) / 48, e = n2 % 48;
            const int c = 2 * (e * 8 + hm) + blk;
            const float gf = gcqk[c] * (blk == 0 ? lamp[0] : 1.0f);
            g_biasc[n2] = bcqk[c] * gf;
            g_igc[n2]   = (gf != 0.f) ? 1.f / gf : 0.f;
        }
    }
}

// --------- HMMA GEMM core: fragment-double-buffered ks loop ------------------
__device__ __forceinline__ void gemm_body(
    const __half* A, const __half* B, const float* bias, void* Cout,
    int Kp, int ldc, float* ss, const float* ig, int smode, int chalf,
    int mB, int n0, char* smem)
{
    const uint32_t sb = s2u(smem);
    const int tid = threadIdx.x, lane = tid & 31, wid = tid >> 5;
    const int wm = (wid & 3) << 5;
    const int wn = (wid >> 2) << 6;

    const int lrow = tid >> 3, lu = tid & 7;
    const size_t ldk = (size_t)Kp * 2;
    const char* Asrc = (const char*)A + (size_t)(mB + lrow) * ldk + lu * 16;
    const char* Bsrc = (const char*)B + (size_t)(n0 + lrow) * ldk + lu * 16;
    uint32_t dsto[4];
#pragma unroll
    for (int r = 0; r < 4; r++) {
        const int row = lrow + r * 32;
        dsto[r] = row * 128 + ((lu ^ (row & 7)) << 4);
    }

    const int q = lane >> 3, tr = lane & 7;
    const int qA = q >> 1, qB = q & 1;
    uint32_t rowoffA[2], xrA[2];
#pragma unroll
    for (int fm = 0; fm < 2; fm++) {
        const int row = wm + fm * 16 + tr + ((q & 1) << 3);
        rowoffA[fm] = row * 128; xrA[fm] = row & 7;
    }
    uint32_t rowoffB[4], xrB[4];
#pragma unroll
    for (int fn = 0; fn < 4; fn++) {
        const int row = wn + fn * 16 + tr + ((q >> 1) << 3);
        rowoffB[fn] = row * 128; xrB[fn] = row & 7;
    }

    float acc[2][8][4] = {};

    const int NC = Kp >> 6;
#pragma unroll
    for (int pc = 0; pc < 2; pc++) {
        if (pc < NC) {
            const uint32_t ab = sb + pc * 16384u;
            const uint32_t bb = sb + 49152u + pc * 16384u;
            const char* An = Asrc + (size_t)pc * 128;
            const char* Bn = Bsrc + (size_t)pc * 128;
#pragma unroll
            for (int r = 0; r < 4; r++) {
                cp16(ab + dsto[r], An + (size_t)r * 32 * ldk);
                cp16(bb + dsto[r], Bn + (size_t)r * 32 * ldk);
            }
            CP_COMMIT();
        }
    }

    uint32_t a[2][2][4], bf[2][4][4];
    int bidx = 0, pidx = 2;
    for (int c = 0; c < NC; c++) {
        if (c + 1 < NC) { CP_WAIT1(); } else { CP_WAIT0(); }
        __syncthreads();
        if (c + 2 < NC) {
            const uint32_t ab = sb + pidx * 16384u;
            const uint32_t bb = sb + 49152u + pidx * 16384u;
            const char* An = Asrc + (size_t)(c + 2) * 128;
            const char* Bn = Bsrc + (size_t)(c + 2) * 128;
#pragma unroll
            for (int r = 0; r < 4; r++) {
                cp16(ab + dsto[r], An + (size_t)r * 32 * ldk);
                cp16(bb + dsto[r], Bn + (size_t)r * 32 * ldk);
            }
            CP_COMMIT();
            if (++pidx == 3) pidx = 0;
        }

        const uint32_t Ab = sb + bidx * 16384u;
        const uint32_t Bs = sb + 49152u + bidx * 16384u;

        // prologue: fragments for ks=0
#pragma unroll
        for (int fm = 0; fm < 2; fm++) {
            const uint32_t ad = Ab + rowoffA[fm] + ((((uint32_t)qA) ^ xrA[fm]) << 4);
            LDSM4(a[0][fm][0], a[0][fm][1], a[0][fm][2], a[0][fm][3], ad);
        }
#pragma unroll
        for (int fn = 0; fn < 4; fn++) {
            const uint32_t bd = Bs + rowoffB[fn] + ((((uint32_t)qB) ^ xrB[fn]) << 4);
            LDSM4(bf[0][fn][0], bf[0][fn][1], bf[0][fn][2], bf[0][fn][3], bd);
        }
#pragma unroll
        for (int ks = 0; ks < 4; ks++) {
            const int cur = ks & 1, nxt = cur ^ 1;
            if (ks < 3) {       // prefetch fragments for ks+1 into alternate regs
#pragma unroll
                for (int fm = 0; fm < 2; fm++) {
                    const uint32_t ad = Ab + rowoffA[fm]
                        + ((((uint32_t)((ks + 1) * 2 + qA)) ^ xrA[fm]) << 4);
                    LDSM4(a[nxt][fm][0], a[nxt][fm][1], a[nxt][fm][2], a[nxt][fm][3], ad);
                }
#pragma unroll
                for (int fn = 0; fn < 4; fn++) {
                    const uint32_t bd = Bs + rowoffB[fn]
                        + ((((uint32_t)((ks + 1) * 2 + qB)) ^ xrB[fn]) << 4);
                    LDSM4(bf[nxt][fn][0], bf[nxt][fn][1], bf[nxt][fn][2], bf[nxt][fn][3], bd);
                }
            }
#pragma unroll
            for (int fm = 0; fm < 2; fm++)
#pragma unroll
                for (int fn = 0; fn < 4; fn++) {
                    MMA16816(acc[fm][2 * fn],     a[cur][fm][0], a[cur][fm][1],
                             a[cur][fm][2], a[cur][fm][3], bf[cur][fn][0], bf[cur][fn][1]);
                    MMA16816(acc[fm][2 * fn + 1], a[cur][fm][0], a[cur][fm][1],
                             a[cur][fm][2], a[cur][fm][3], bf[cur][fn][2], bf[cur][fn][3]);
                }
        }
        if (++bidx == 3) bidx = 0;
    }

    const int er = lane >> 2, ec = (lane & 3) << 1;
    float ssa[2][2] = {{0.f, 0.f}, {0.f, 0.f}};
#pragma unroll
    for (int fm = 0; fm < 2; fm++) {
#pragma unroll
        for (int fn = 0; fn < 8; fn++) {
            const int gm = mB + wm + fm * 16 + er;
            const int gn = n0 + wn + fn * 8 + ec;
            const float2 bv = *(const float2*)(bias + gn);
            float2 o0, o1;
            o0.x = acc[fm][fn][0] + bv.x; o0.y = acc[fm][fn][1] + bv.y;
            o1.x = acc[fm][fn][2] + bv.x; o1.y = acc[fm][fn][3] + bv.y;
            if (chalf) {
                __half* Ch = (__half*)Cout;
                *(__half2*)(Ch + (size_t)gm * ldc + gn) = __floats2half2_rn(o0.x, o0.y);
                *(__half2*)(Ch + (size_t)(gm + 8) * ldc + gn) = __floats2half2_rn(o1.x, o1.y);
            } else {
                float* Cf = (float*)Cout;
                *(float2*)(Cf + (size_t)gm * ldc + gn) = o0;
                *(float2*)(Cf + (size_t)(gm + 8) * ldc + gn) = o1;
            }
            if (smode) {
                const float2 iv = *(const float2*)(ig + gn);
                const float p0 = o0.x * iv.x, p1 = o0.y * iv.y;
                const float p2 = o1.x * iv.x, p3 = o1.y * iv.y;
                const bool m0 = (smode == 2) || ((gn % 48) < 32);
                const bool m1 = (smode == 2) || (((gn + 1) % 48) < 32);
                ssa[fm][0] += (m0 ? p0 * p0 : 0.f) + (m1 ? p1 * p1 : 0.f);
                ssa[fm][1] += (m0 ? p2 * p2 : 0.f) + (m1 ? p3 * p3 : 0.f);
            }
        }
    }
    if (smode) {
#pragma unroll
        for (int fm = 0; fm < 2; fm++)
#pragma unroll
            for (int h = 0; h < 2; h++) {
                float v = ssa[fm][h];
                v += __shfl_xor_sync(0xffffffffu, v, 1);
                v += __shfl_xor_sync(0xffffffffu, v, 2);
                if ((lane & 3) == 0)
                    atomicAdd(ss + mB + wm + fm * 16 + er + h * 8, v);
            }
    }
}

// fused coords+values projection: blockIdx.x<6 -> coords, else values
__global__ __launch_bounds__(256, 2) void gemm_cv()
{
    extern __shared__ __align__(1024) char smem[];
    const int bx = blockIdx.x;
    const int mB = blockIdx.y * 128;
    if (bx < 6) {
        gemm_body(g_Ac, g_Bc, g_biasc, g_pc, 128, 768, g_ssc, g_igc, 2, 1,
                  mB, bx * 128, smem);
    } else {
        gemm_body(g_Av, g_Bv, g_biasv, g_pv, 384, 1152, g_ssv, g_igv, 1, 1,
                  mB, (bx - 6) * 128, smem);
    }
}
// output projection (fp32 out to harness buffer)
__global__ __launch_bounds__(256, 2) void gemm_o(float* __restrict__ out,
                                                 const float* __restrict__ b_ov)
{
    extern __shared__ __align__(1024) char smem[];
    gemm_body(g_Yb, g_Bo, b_ov, out, 384, 384, nullptr, nullptr, 0, 0,
              blockIdx.y * 128, blockIdx.x * 128, smem);
}

// ---------------------------- windowed attention ----------------------------
#define Q2_OFF  0u            // 64 x 208  13312
#define K2_OFF  13312u        // 13312
#define PH_OFF  0u            // 64 x 144 (9216) — aliases Q2
#define VTH_OFF 26624u        // 64 tok-rows x 112B = 7168
#define PS_OFF  33792u        // 225 f32
#define TS_OFF  34692u
#define RV_OFF  34948u
#define RC_OFF  35204u
#define MR_OFF  35460u        // 2 x 64 f32
#define SR_OFF  35972u        // 2 x 64 f32
#define ASMB    36484
__global__ __launch_bounds__(256, 4) void attn_k(const float* __restrict__ pos_emb)
{
    extern __shared__ __align__(128) char smx[];
    float* Ps = (float*)(smx + PS_OFF);
    int*   ts = (int*)(smx + TS_OFF);
    float* rv = (float*)(smx + RV_OFF);
    float* rc = (float*)(smx + RC_OFF);
    float* mred = (float*)(smx + MR_OFF);
    float* sred = (float*)(smx + SR_OFF);

    int blk = blockIdx.x;
    const int wx = blk % NW_; blk /= NW_;
    const int wy = blk % NW_; blk /= NW_;
    const int head = blk % NH_;
    const int b = blk / NH_;
    const int tid = threadIdx.x;

    if (tid < 64) {
        const int ry = tid >> 3, rx = tid & 7;
        const int y = (wy * 8 + ry + 4) % Hh;
        const int x = (wx * 8 + rx + 4) % Wd;
        const int t = b * (Hh * Wd) + y * Wd + x;
        ts[tid] = t;
        rv[tid] = rsqrtf(g_ssv[t] * (1.f / 768.f) + 1e-6f);
        rc[tid] = rsqrtf(g_ssc[t] * (1.f / 768.f) + 1e-6f);
    }
    for (int i = tid; i < 225; i += 256) Ps[i] = pos_emb[i];
    __syncthreads();

    const int hb = head * 48;

    // ---- Q/K gather ----
    for (int i = tid; i < 64 * 12; i += 256) {
        const int tok = i / 12, u = i - tok * 12;
        const int t = ts[tok];
        uint4 qr, kr;
        float f;
        int ch;
        if (u < 6) {
            ch = u * 8;
            const __half* pvr = g_pv + (size_t)t * 1152;
            qr = *(const uint4*)(pvr + hb + ch);
            kr = *(const uint4*)(pvr + 384 + hb + ch);
            f = (u < 4) ? rv[tok] : 1.f;
        } else {
            const int c2 = (u - 6) * 8;
            ch = 48 + c2;
            const __half* pcr = g_pc + (size_t)t * 768;
            qr = *(const uint4*)(pcr + hb + c2);
            kr = *(const uint4*)(pcr + 384 + hb + c2);
            f = rc[tok];
        }
        uint4 qo, ko;
        qo.x = scaleh2(qr.x, f); qo.y = scaleh2(qr.y, f);
        qo.z = scaleh2(qr.z, f); qo.w = scaleh2(qr.w, f);
        ko.x = scaleh2(kr.x, f); ko.y = scaleh2(kr.y, f);
        ko.z = scaleh2(kr.z, f); ko.w = scaleh2(kr.w, f);
        *(uint4*)(smx + Q2_OFF + tok * 208 + ch * 2) = qo;
        *(uint4*)(smx + K2_OFF + tok * 208 + ch * 2) = ko;
    }
    // ---- V gather: tok-major ----
    for (int i = tid; i < 64 * 6; i += 256) {
        const int tok = i / 6, u = i - tok * 6;
        const int t = ts[tok];
        uint4 raw = *(const uint4*)(g_pv + (size_t)t * 1152 + 768 + hb + u * 8);
        const float f = (u < 4) ? rv[tok] : 1.f;
        uint4 o;
        o.x = scaleh2(raw.x, f); o.y = scaleh2(raw.y, f);
        o.z = scaleh2(raw.z, f); o.w = scaleh2(raw.w, f);
        *(uint4*)(smx + VTH_OFF + tok * 112 + u * 16) = o;
    }
    __syncthreads();

    // ---- QK^T via HMMA: 6 k16 steps ----
    const int lane = tid & 31, w = tid >> 5;
    const int wq = w & 3, wk = w >> 2;
    const int q = lane >> 3, tr = lane & 7;
    const uint32_t sQ = s2u(smx + Q2_OFF), sK = s2u(smx + K2_OFF);
    const uint32_t aBase = sQ + (uint32_t)(16 * wq + tr + ((q & 1) << 3)) * 208 + ((q >> 1) << 4);
    uint32_t bBase[2];
    bBase[0] = sK + (uint32_t)(32 * wk + tr + ((q >> 1) << 3)) * 208 + ((q & 1) << 4);
    bBase[1] = bBase[0] + 16 * 208;

    float acc[4][4] = {};
#pragma unroll
    for (int s = 0; s < 6; s++) {
        uint32_t a0, a1, a2, a3;
        LDSM4(a0, a1, a2, a3, aBase + s * 32);
#pragma unroll
        for (int fn = 0; fn < 2; fn++) {
            uint32_t b0, b1, b2, b3;
            LDSM4(b0, b1, b2, b3, bBase[fn] + s * 32);
            MMA16816(acc[2 * fn],     a0, a1, a2, a3, b0, b1);
            MMA16816(acc[2 * fn + 1], a0, a1, a2, a3, b2, b3);
        }
    }

    // ---- register epilogue: scale + bias + mask; ONE-ROUND softmax ----
    const float scale = 0.14433756729740643f;   // 1/sqrt(48)
    const bool lastR = (wy == NW_ - 1), lastC = (wx == NW_ - 1);
    const int i0 = 16 * wq + (lane >> 2);
    const int jbase = 32 * wk + ((lane & 3) << 1);
    float rmax[2] = {-INFINITY, -INFINITY};
#pragma unroll
    for (int f = 0; f < 4; f++) {
#pragma unroll
        for (int r = 0; r < 4; r++) {
            const int i = i0 + ((r >> 1) << 3);
            const int j = jbase + 8 * f + (r & 1);
            float v = acc[f][r] * scale
                    + Ps[((j >> 3) - (i >> 3) + 7) * 15 + ((j & 7) - (i & 7) + 7)];
            if (lastR && (((i >= 32) ? 1 : 0) ^ ((j >= 32) ? 1 : 0)))           v = -INFINITY;
            if (lastC && ((((i & 7) >= 4) ? 1 : 0) ^ (((j & 7) >= 4) ? 1 : 0))) v = -INFINITY;
            acc[f][r] = v;
            rmax[r >> 1] = fmaxf(rmax[r >> 1], v);
        }
    }
    float ml[2], rsum[2] = {0.f, 0.f};
#pragma unroll
    for (int h = 0; h < 2; h++) {
        rmax[h] = fmaxf(rmax[h], __shfl_xor_sync(0xffffffffu, rmax[h], 1));
        rmax[h] = fmaxf(rmax[h], __shfl_xor_sync(0xffffffffu, rmax[h], 2));
        ml[h] = fmaxf(rmax[h], -1e30f);
    }
#pragma unroll
    for (int f = 0; f < 4; f++) {
#pragma unroll
        for (int r = 0; r < 4; r++) {
            const float e = __expf(acc[f][r] - ml[r >> 1]);
            acc[f][r] = e;
            rsum[r >> 1] += e;
        }
    }
#pragma unroll
    for (int h = 0; h < 2; h++) {
        rsum[h] += __shfl_xor_sync(0xffffffffu, rsum[h], 1);
        rsum[h] += __shfl_xor_sync(0xffffffffu, rsum[h], 2);
    }
    if ((lane & 3) == 0) {
        mred[wk * 64 + i0]     = ml[0];
        mred[wk * 64 + i0 + 8] = ml[1];
        sred[wk * 64 + i0]     = rsum[0];
        sred[wk * 64 + i0 + 8] = rsum[1];
    }
    __syncthreads();   // all QK ldmatrix reads of Q2 done -> Ph alias safe
    float fac[2];
#pragma unroll
    for (int h = 0; h < 2; h++) {
        const int row = i0 + h * 8;
        const float m0 = mred[row], m1 = mred[64 + row];
        const float g = fmaxf(m0, m1);
        const float s = sred[row] * __expf(m0 - g) + sred[64 + row] * __expf(m1 - g);
        fac[h] = __expf(ml[h] - g) / s;
    }

    // ---- write P (fp16) straight from registers ----
#pragma unroll
    for (int h = 0; h < 2; h++) {
        const int i = i0 + h * 8;
        char* PhB = smx + PH_OFF + i * 144;
#pragma unroll
        for (int f = 0; f < 4; f++) {
            const float p0 = acc[f][h * 2] * fac[h];
            const float p1 = acc[f][h * 2 + 1] * fac[h];
            *(uint32_t*)(PhB + (jbase + 8 * f) * 2) =
                packh(__float2half_rn(p0), __float2half_rn(p1));
        }
    }
    __syncthreads();

    // ---- AV via HMMA: P (row-major A) x V (tok-major, trans-LDSM B) ----
    const int wq2 = w & 3, wn2 = w >> 2;
    const uint32_t sPh = s2u(smx + PH_OFF);
    const uint32_t sVh = s2u(smx + VTH_OFF);
    const uint32_t aOff = (uint32_t)(16 * wq2 + tr + ((q & 1) << 3)) * 144 + ((q >> 1) << 4);
    const uint32_t vb4 = sVh + (uint32_t)(lane & 15) * 112
                             + (uint32_t)(24 * wn2 + ((lane >> 4) << 3)) * 2;
    const uint32_t vb2 = sVh + (uint32_t)(lane & 15) * 112
                             + (uint32_t)(24 * wn2 + 16) * 2;

    float acc3[3][4] = {};
#pragma unroll
    for (int ks = 0; ks < 4; ks++) {
        uint32_t a0, a1, a2, a3, b0, b1, b2, b3, b4, b5;
        LDSM4(a0, a1, a2, a3, sPh + aOff + ks * 32);
        LDSM4T(b0, b1, b2, b3, vb4 + ks * 1792);
        LDSM2T(b4, b5, vb2 + ks * 1792);
        MMA16816(acc3[0], a0, a1, a2, a3, b0, b1);
        MMA16816(acc3[1], a0, a1, a2, a3, b2, b3);
        MMA16816(acc3[2], a0, a1, a2, a3, b4, b5);
    }

    // ---- output: fp16 -> g_Yb ----
    const int er2 = lane >> 2, ec2 = (lane & 3) << 1;
#pragma unroll
    for (int h = 0; h < 2; h++) {
        const int i = 16 * wq2 + er2 + h * 8;
        const int Y = wy * 8 + (i >> 3), X = wx * 8 + (i & 7);
        const size_t t = ((size_t)b * Hh + Y) * Wd + X;
        __half* op = g_Yb + t * 384 + hb;
#pragma unroll
        for (int f = 0; f < 3; f++) {
            const int e = 24 * wn2 + 8 * f + ec2;
            *(__half2*)(op + e) = __halves2half2(__float2half_rn(acc3[f][h * 2]),
                                                 __float2half_rn(acc3[f][h * 2 + 1]));
        }
    }
}

// ------------------------------- launcher -----------------------------------
extern "C" void kernel_launch(void* const* d_in, const int* in_sizes, int n_in,
                              void* d_out, int out_size)
{
    const float* values = (const float*)d_in[0];
    const float* coords = (const float*)d_in[1];
    const float* W_vqk  = (const float*)d_in[2];
    const float* b_vqk  = (const float*)d_in[3];
    const float* gm_vqk = (const float*)d_in[4];
    const float* W_vv   = (const float*)d_in[5];
    const float* b_vv   = (const float*)d_in[6];
    const float* W_cqk  = (const float*)d_in[7];
    const float* b_cqk  = (const float*)d_in[8];
    const float* gm_cqk = (const float*)d_in[9];
    const float* lam    = (const float*)d_in[10];
    const float* pos    = (const float*)d_in[11];
    const float* W_ov   = (const float*)d_in[12];
    const float* b_ov   = (const float*)d_in[13];
    float* out = (float*)d_out;

    // 1) fused pack (vectorized A) + ss-zero + bias/invγ permute
    pack_all<<<(int)((P6 + 255) / 256), 256>>>(values, coords, W_vqk, W_vv, W_cqk, W_ov,
                                               b_vqk, b_vv, gm_vqk, b_cqk, gm_cqk, lam);

    const int gsm = 98304;
    cudaFuncSetAttribute(gemm_cv, cudaFuncAttributeMaxDynamicSharedMemorySize, gsm);
    cudaFuncSetAttribute(gemm_o,  cudaFuncAttributeMaxDynamicSharedMemorySize, gsm);

    // 2) fused coords+values projections (single launch)
    gemm_cv<<<dim3(15, NTOK / 128), 256, gsm>>>();

    // 3) attention
    cudaFuncSetAttribute(attn_k, cudaFuncAttributeMaxDynamicSharedMemorySize, ASMB);
    attn_k<<<Bb * NH_ * NW_ * NW_, 256, ASMB>>>(pos);

    // 4) output projection
    gemm_o<<<dim3(384 / 128, NTOK / 128), 256, gsm>>>(out, b_ov);
}